// round 5
// baseline (speedup 1.0000x reference)
#include <cuda_runtime.h>
#include <math.h>

// Problem constants (fixed by the dataset)
#define B_   32
#define F_   40
#define NB_  36
#define R_   512
#define H_   512
#define D_   1536          // R + 2H
#define NBF  1280          // B*F
#define PM   1024          // p buffer cols: [p1(512) | p2(512)]

// ---------------- scratch (static __device__, no allocation) ----------------
__device__ float g_hb [B_ * H_];      // hidden@Ws_h.T + bs_h + bs_f
__device__ float g_hp2[B_ * H_];      // hidden@Wr_h.T + br_h + br_f
__device__ float g_feat[(long)NBF * D_];   // [obj_att | i3d]
__device__ float g_p  [(long)NBF * PM];    // [p1 | p2]
__device__ float g_e2 [B_ * F_ * F_];

// ============================================================================
// K0: hidden projections (tiny). One block per batch row.
// ============================================================================
__global__ __launch_bounds__(256) void k0_hproj(
    const float* __restrict__ hidden, const float* __restrict__ Wsh,
    const float* __restrict__ bsh,    const float* __restrict__ bsf,
    const float* __restrict__ Wrh,    const float* __restrict__ brh,
    const float* __restrict__ brf)
{
    __shared__ float hs[H_];
    int b = blockIdx.x, tid = threadIdx.x;
    for (int h = tid; h < H_; h += 256) hs[h] = hidden[b * H_ + h];
    __syncthreads();
    for (int h = tid; h < H_; h += 256) {
        const float4* w1 = reinterpret_cast<const float4*>(Wsh + (long)h * H_);
        const float4* w2 = reinterpret_cast<const float4*>(Wrh + (long)h * H_);
        float a1 = 0.f, a2 = 0.f;
        #pragma unroll 4
        for (int k4 = 0; k4 < H_ / 4; k4++) {
            float4 v1 = w1[k4], v2 = w2[k4];
            float h0 = hs[k4*4+0], h1 = hs[k4*4+1], h2 = hs[k4*4+2], h3 = hs[k4*4+3];
            a1 = fmaf(h0, v1.x, a1); a1 = fmaf(h1, v1.y, a1);
            a1 = fmaf(h2, v1.z, a1); a1 = fmaf(h3, v1.w, a1);
            a2 = fmaf(h0, v2.x, a2); a2 = fmaf(h1, v2.y, a2);
            a2 = fmaf(h2, v2.z, a2); a2 = fmaf(h3, v2.w, a2);
        }
        g_hb [b * H_ + h] = a1 + bsh[h] + bsf[h];
        g_hp2[b * H_ + h] = a2 + brh[h] + brf[h];
    }
}

// ============================================================================
// K2: fused stage-1. One block per (b,f): 36x512x512 GEMM with tanh*was
// reduction epilogue, in-block softmax over NB=36, attention-weighted sum,
// and concat with i3d into g_feat. Thread tile 9(l) x 8(h); 72 FMA per
// 17 smem floats per k-step -> FMA-pipe bound.
// ============================================================================
#define KC 16
__global__ __launch_bounds__(256, 2) void k2_stage1(
    const float* __restrict__ obj, const float* __restrict__ i3d,
    const float* __restrict__ Wsf, const float* __restrict__ was)
{
    __shared__ float As[NB_][KC];      // broadcast reads -> no pad needed
    __shared__ float Ws[H_][KC + 1];   // odd stride 17 -> conflict-free
    __shared__ float e_s[NB_];
    __shared__ float alpha[NB_];

    int bf = blockIdx.x;
    int b  = bf / F_;
    const float* fbase = obj + (long)bf * NB_ * R_;
    int tid   = threadIdx.x;
    int lgrp  = tid >> 6;     // 0..3   (warp-uniform)
    int hlane = tid & 63;     // 0..63  (lane-linear)

    float acc[9][8];
    #pragma unroll
    for (int i = 0; i < 9; i++)
        #pragma unroll
        for (int j = 0; j < 8; j++) acc[i][j] = 0.f;

    if (tid < NB_) e_s[tid] = 0.f;

    for (int k0 = 0; k0 < R_; k0 += KC) {
        // A tile: 36x16 floats = 144 float4
        if (tid < (NB_ * KC) / 4) {
            int l = tid >> 2, kk4 = tid & 3;
            float4 v = *reinterpret_cast<const float4*>(fbase + l * R_ + k0 + kk4 * 4);
            *reinterpret_cast<float4*>(&As[l][kk4 * 4]) = v;
        }
        // W tile: 512x16 floats = 2048 float4 (8 per thread)
        #pragma unroll
        for (int it = 0; it < 8; it++) {
            int idx = tid + it * 256;
            int h = idx >> 2, kk4 = idx & 3;
            float4 v = *reinterpret_cast<const float4*>(Wsf + (long)h * R_ + k0 + kk4 * 4);
            Ws[h][kk4 * 4 + 0] = v.x; Ws[h][kk4 * 4 + 1] = v.y;
            Ws[h][kk4 * 4 + 2] = v.z; Ws[h][kk4 * 4 + 3] = v.w;
        }
        __syncthreads();
        #pragma unroll 4
        for (int kk = 0; kk < KC; kk++) {
            float a[9], w[8];
            #pragma unroll
            for (int i = 0; i < 9; i++) a[i] = As[lgrp * 9 + i][kk];
            #pragma unroll
            for (int j = 0; j < 8; j++) w[j] = Ws[hlane + j * 64][kk];
            #pragma unroll
            for (int i = 0; i < 9; i++)
                #pragma unroll
                for (int j = 0; j < 8; j++)
                    acc[i][j] = fmaf(a[i], w[j], acc[i][j]);
        }
        __syncthreads();
    }

    // Epilogue: e[l] = sum_h was[h]*tanh(acc + hb[b][h])
    float hbv[8], wv[8];
    #pragma unroll
    for (int j = 0; j < 8; j++) {
        int h = hlane + j * 64;
        hbv[j] = g_hb[b * H_ + h];
        wv[j]  = was[h];
    }
    #pragma unroll
    for (int i = 0; i < 9; i++) {
        float part = 0.f;
        #pragma unroll
        for (int j = 0; j < 8; j++)
            part += wv[j] * tanhf(acc[i][j] + hbv[j]);
        atomicAdd(&e_s[lgrp * 9 + i], part);
    }
    __syncthreads();

    // softmax over 36 (serial in thread 0; trivial cost)
    if (tid == 0) {
        float m = -1e30f;
        for (int l = 0; l < NB_; l++) m = fmaxf(m, e_s[l]);
        float s = 0.f;
        float tmp[NB_];
        for (int l = 0; l < NB_; l++) { tmp[l] = expf(e_s[l] - m); s += tmp[l]; }
        float inv = 1.f / s;
        for (int l = 0; l < NB_; l++) alpha[l] = tmp[l] * inv;
    }
    __syncthreads();

    // att + concat with i3d into g_feat
    float* fout = g_feat + (long)bf * D_;
    for (int d = tid; d < R_; d += 256) {
        float s = 0.f;
        #pragma unroll 4
        for (int l = 0; l < NB_; l++) s = fmaf(alpha[l], fbase[l * R_ + d], s);
        fout[d] = s;
    }
    for (int d = tid; d < 2 * H_; d += 256)
        fout[R_ + d] = i3d[(long)bf * (2 * H_) + d];
}

// ============================================================================
// K4: p = feat(1280x1536) @ W2.T(1024x1536), W2 = [Wr_f[:, :D] ; Wr_f[:, D:]].
// Block tile 32(n) x 128(m), thread tile 4x4, Kc=32.
// ============================================================================
__global__ __launch_bounds__(256) void k4_pgemm(const float* __restrict__ Wrf)
{
    __shared__ float As[32][32];     // broadcast reads
    __shared__ float Ws[128][33];    // odd stride
    int n0 = blockIdx.x * 32;
    int m0 = blockIdx.y * 128;
    int tid = threadIdx.x;
    int ngrp = tid >> 5, mlane = tid & 31;
    float acc[4][4];
    #pragma unroll
    for (int i = 0; i < 4; i++)
        #pragma unroll
        for (int j = 0; j < 4; j++) acc[i][j] = 0.f;

    for (int k0 = 0; k0 < D_; k0 += 32) {
        { // A: 32x32 = 256 float4, one per thread
            int n = tid >> 3, kk4 = tid & 7;
            float4 v = *reinterpret_cast<const float4*>(g_feat + (long)(n0 + n) * D_ + k0 + kk4 * 4);
            *reinterpret_cast<float4*>(&As[n][kk4 * 4]) = v;
        }
        #pragma unroll
        for (int it = 0; it < 4; it++) { // W: 128x32 = 1024 float4
            int idx = tid + it * 256;
            int m = idx >> 3, kk4 = idx & 7;
            int gm = m0 + m;
            const float* src = Wrf + (long)(gm & 511) * (2 * D_) + (gm >> 9) * D_ + k0 + kk4 * 4;
            float4 v = *reinterpret_cast<const float4*>(src);
            Ws[m][kk4 * 4 + 0] = v.x; Ws[m][kk4 * 4 + 1] = v.y;
            Ws[m][kk4 * 4 + 2] = v.z; Ws[m][kk4 * 4 + 3] = v.w;
        }
        __syncthreads();
        #pragma unroll 8
        for (int kk = 0; kk < 32; kk++) {
            float a[4], w[4];
            #pragma unroll
            for (int i = 0; i < 4; i++) a[i] = As[ngrp + i * 8][kk];
            #pragma unroll
            for (int j = 0; j < 4; j++) w[j] = Ws[mlane + j * 32][kk];
            #pragma unroll
            for (int i = 0; i < 4; i++)
                #pragma unroll
                for (int j = 0; j < 4; j++)
                    acc[i][j] = fmaf(a[i], w[j], acc[i][j]);
        }
        __syncthreads();
    }
    #pragma unroll
    for (int i = 0; i < 4; i++)
        #pragma unroll
        for (int j = 0; j < 4; j++)
            g_p[(long)(n0 + ngrp + i * 8) * PM + m0 + mlane + j * 32] = acc[i][j];
}

// ============================================================================
// K5: e2[b,i,j] = war . tanh(p2[b,i] + p1[b,j] + hp2[b]). Block per (b,i),
// warp per j-group, shuffle reduction.
// ============================================================================
__global__ __launch_bounds__(256) void k5_e2(const float* __restrict__ war)
{
    __shared__ float base[H_];
    __shared__ float warr[H_];
    int bi = blockIdx.x;
    int b = bi / F_, i = bi % F_;
    int tid = threadIdx.x, warp = tid >> 5, lane = tid & 31;
    for (int h = tid; h < H_; h += 256) {
        base[h] = g_p[(long)bi * PM + H_ + h] + g_hp2[b * H_ + h];  // p2 + hproj
        warr[h] = war[h];
    }
    __syncthreads();
    for (int jj = 0; jj < 5; jj++) {
        int j = warp + jj * 8;
        const float* p1 = g_p + (long)(b * F_ + j) * PM;   // p1 part (m<512)
        float part = 0.f;
        #pragma unroll 4
        for (int kk = 0; kk < 16; kk++) {
            int h = lane + kk * 32;
            part += warr[h] * tanhf(base[h] + p1[h]);
        }
        #pragma unroll
        for (int off = 16; off; off >>= 1)
            part += __shfl_xor_sync(0xffffffffu, part, off);
        if (lane == 0) g_e2[(long)b * (F_ * F_) + i * F_ + j] = part;
    }
}

// ============================================================================
// K6: per-batch softmax over 1600, row/col marginals, final weighted sums.
// ============================================================================
__global__ __launch_bounds__(256) void k6_final(float* __restrict__ out)
{
    __shared__ float ex[F_ * F_];
    __shared__ float red[256];
    __shared__ float rowsum[F_], colsum[F_];
    int b = blockIdx.x, tid = threadIdx.x;
    const float* e = g_e2 + b * (F_ * F_);

    float m = -1e30f;
    for (int t = tid; t < F_ * F_; t += 256) m = fmaxf(m, e[t]);
    red[tid] = m; __syncthreads();
    for (int s = 128; s > 0; s >>= 1) {
        if (tid < s) red[tid] = fmaxf(red[tid], red[tid + s]);
        __syncthreads();
    }
    m = red[0]; __syncthreads();

    float sum = 0.f;
    for (int t = tid; t < F_ * F_; t += 256) { float v = expf(e[t] - m); ex[t] = v; sum += v; }
    red[tid] = sum; __syncthreads();
    for (int s = 128; s > 0; s >>= 1) {
        if (tid < s) red[tid] += red[tid + s];
        __syncthreads();
    }
    float inv = 1.f / red[0];

    if (tid < F_) { rowsum[tid] = 0.f; colsum[tid] = 0.f; }
    __syncthreads();
    for (int t = tid; t < F_ * F_; t += 256) {
        float a = ex[t] * inv;
        atomicAdd(&rowsum[t / F_], a);   // sum over j  -> weights feat[i]
        atomicAdd(&colsum[t % F_], a);   // sum over i  -> weights feat[j]
    }
    __syncthreads();

    for (int d = tid; d < D_; d += 256) {
        float r1 = 0.f, r2 = 0.f;
        #pragma unroll 8
        for (int q = 0; q < F_; q++) {
            float fv = g_feat[(long)(b * F_ + q) * D_ + d];
            r1 = fmaf(colsum[q], fv, r1);   // rel1 = sum_j colsum[j]*feat[j]
            r2 = fmaf(rowsum[q], fv, r2);   // rel2 = sum_i rowsum[i]*feat[i]
        }
        out[b * (2 * D_) + d]      = r1;
        out[b * (2 * D_) + D_ + d] = r2;
    }
}

// ============================================================================
extern "C" void kernel_launch(void* const* d_in, const int* in_sizes, int n_in,
                              void* d_out, int out_size)
{
    const float* i3d    = (const float*)d_in[0];   // (32,40,1024)
    const float* obj    = (const float*)d_in[1];   // (32,40,36,512)
    const float* hidden = (const float*)d_in[2];   // (32,512)
    const float* Wsf    = (const float*)d_in[3];   // (512,512)
    const float* bsf    = (const float*)d_in[4];
    const float* Wsh    = (const float*)d_in[5];   // (512,512)
    const float* bsh    = (const float*)d_in[6];
    const float* was    = (const float*)d_in[7];   // (512,)
    const float* Wrf    = (const float*)d_in[8];   // (512,3072)
    const float* brf    = (const float*)d_in[9];
    const float* Wrh    = (const float*)d_in[10];  // (512,512)
    const float* brh    = (const float*)d_in[11];
    const float* war    = (const float*)d_in[12];  // (512,)
    float* out = (float*)d_out;                    // (32,3072)

    k0_hproj <<<B_,  256>>>(hidden, Wsh, bsh, bsf, Wrh, brh, brf);
    k2_stage1<<<NBF, 256>>>(obj, i3d, Wsf, was);
    k4_pgemm <<<dim3(NBF / 32, PM / 128), 256>>>(Wrf);
    k5_e2    <<<NBF, 256>>>(war);
    k6_final <<<B_,  256>>>(out);
}

// round 7
// speedup vs baseline: 2.3956x; 2.3956x over previous
#include <cuda_runtime.h>
#include <cuda_bf16.h>
#include <math.h>
#include <stdint.h>

#define B_   32
#define F_   40
#define NB_  36
#define R_   512
#define H_   512
#define D_   1536
#define NBF  1280
#define PM   1024
#define M1   46080
#define BFB  1440      // F_*NB_ rows per batch in stage-1

// ---------------- device scratch (static, no allocation) ----------------
__device__ __align__(16) float g_hb [B_*H_];
__device__ __align__(16) float g_hp2[B_*H_];
__device__ __align__(16) float g_e1 [M1];
__device__ __align__(16) float g_feat[(long)NBF*D_];
__device__ __align__(16) float g_p  [(long)NBF*PM];
__device__ __align__(16) float g_e2 [B_*F_*F_];
__device__ __align__(16) __nv_bfloat16 g_Ahi[(long)M1*R_];
__device__ __align__(16) __nv_bfloat16 g_Alo[(long)M1*R_];
__device__ __align__(16) __nv_bfloat16 g_B1hi[H_*R_];
__device__ __align__(16) __nv_bfloat16 g_B1lo[H_*R_];
__device__ __align__(16) __nv_bfloat16 g_Fhi[(long)NBF*D_];
__device__ __align__(16) __nv_bfloat16 g_Flo[(long)NBF*D_];
__device__ __align__(16) __nv_bfloat16 g_B2hi[(long)PM*D_];
__device__ __align__(16) __nv_bfloat16 g_B2lo[(long)PM*D_];

// ---------------- portable (non-'a') PTX helpers ----------------
__device__ __forceinline__ uint32_t smem_u32(const void* p){
    uint32_t a;
    asm("{ .reg .u64 t; cvta.to.shared.u64 t, %1; cvt.u32.u64 %0, t; }" : "=r"(a) : "l"(p));
    return a;
}
#define CP_ASYNC16(dst, src) \
    asm volatile("cp.async.cg.shared.global [%0], [%1], 16;" :: "r"(dst), "l"(src) : "memory")
#define CP_COMMIT() asm volatile("cp.async.commit_group;" ::: "memory")
#define CP_WAIT(n)  asm volatile("cp.async.wait_group %0;" :: "n"(n) : "memory")

__device__ __forceinline__ void ldsm4(uint32_t* r, uint32_t addr){
    asm volatile("ldmatrix.sync.aligned.m8n8.x4.shared.b16 {%0,%1,%2,%3}, [%4];"
        : "=r"(r[0]), "=r"(r[1]), "=r"(r[2]), "=r"(r[3]) : "r"(addr));
}
__device__ __forceinline__ void mma16816(float* c, const uint32_t* a, const uint32_t* b){
    asm volatile("mma.sync.aligned.m16n8k16.row.col.f32.bf16.bf16.f32 "
        "{%0,%1,%2,%3}, {%4,%5,%6,%7}, {%8,%9}, {%0,%1,%2,%3};"
        : "+f"(c[0]), "+f"(c[1]), "+f"(c[2]), "+f"(c[3])
        : "r"(a[0]), "r"(a[1]), "r"(a[2]), "r"(a[3]), "r"(b[0]), "r"(b[1]));
}

// ============================================================================
// K0: hidden projections (tiny)
// ============================================================================
__global__ __launch_bounds__(256) void k0_hproj(
    const float* __restrict__ hidden, const float* __restrict__ Wsh,
    const float* __restrict__ bsh,    const float* __restrict__ bsf,
    const float* __restrict__ Wrh,    const float* __restrict__ brh,
    const float* __restrict__ brf)
{
    __shared__ float hs[H_];
    int b = blockIdx.x, tid = threadIdx.x;
    for (int h = tid; h < H_; h += 256) hs[h] = hidden[b * H_ + h];
    __syncthreads();
    for (int h = tid; h < H_; h += 256) {
        const float4* w1 = reinterpret_cast<const float4*>(Wsh + (long)h * H_);
        const float4* w2 = reinterpret_cast<const float4*>(Wrh + (long)h * H_);
        float a1 = 0.f, a2 = 0.f;
        #pragma unroll 4
        for (int k4 = 0; k4 < H_ / 4; k4++) {
            float4 v1 = w1[k4], v2 = w2[k4];
            float h0 = hs[k4*4+0], h1 = hs[k4*4+1], h2 = hs[k4*4+2], h3 = hs[k4*4+3];
            a1 = fmaf(h0, v1.x, a1); a1 = fmaf(h1, v1.y, a1);
            a1 = fmaf(h2, v1.z, a1); a1 = fmaf(h3, v1.w, a1);
            a2 = fmaf(h0, v2.x, a2); a2 = fmaf(h1, v2.y, a2);
            a2 = fmaf(h2, v2.z, a2); a2 = fmaf(h3, v2.w, a2);
        }
        g_hb [b * H_ + h] = a1 + bsh[h] + bsf[h];
        g_hp2[b * H_ + h] = a2 + brh[h] + brf[h];
    }
}

// ============================================================================
// K1: bf16 hi/lo splits
// ============================================================================
__device__ __forceinline__ uint32_t pack_hi2(float a, float b, float& ra, float& rb){
    __nv_bfloat162 p = __floats2bfloat162_rn(a, b);
    ra = __low2float(p); rb = __high2float(p);
    return *reinterpret_cast<uint32_t*>(&p);
}
__device__ __forceinline__ uint32_t pack_lo2(float a, float b){
    __nv_bfloat162 p = __floats2bfloat162_rn(a, b);
    return *reinterpret_cast<uint32_t*>(&p);
}
__device__ __forceinline__ void split4_store(float4 v, __nv_bfloat16* hi, __nv_bfloat16* lo, size_t qi){
    float rx, ry, rz, rw;
    uint32_t h01 = pack_hi2(v.x, v.y, rx, ry);
    uint32_t h23 = pack_hi2(v.z, v.w, rz, rw);
    uint32_t l01 = pack_lo2(v.x - rx, v.y - ry);
    uint32_t l23 = pack_lo2(v.z - rz, v.w - rw);
    reinterpret_cast<uint2*>(hi)[qi] = make_uint2(h01, h23);
    reinterpret_cast<uint2*>(lo)[qi] = make_uint2(l01, l23);
}

__global__ __launch_bounds__(256) void k1_splitA(const float* __restrict__ src){
    size_t i = (size_t)blockIdx.x * 256 + threadIdx.x;
    float4 v = reinterpret_cast<const float4*>(src)[i];
    split4_store(v, g_Ahi, g_Alo, i);
}

__global__ __launch_bounds__(256) void k1_splitB(const float* __restrict__ Wsf,
                                                 const float* __restrict__ Wrf){
    size_t q = (size_t)blockIdx.x * 256 + threadIdx.x;
    if (q < 65536) {                                     // B1: Wsf 512x512
        float4 v = reinterpret_cast<const float4*>(Wsf)[q];
        split4_store(v, g_B1hi, g_B1lo, q);
    } else {                                             // B2: rearranged Wrf -> 1024x1536
        size_t j = q - 65536;
        int m = (int)(j / 384), c4 = (int)(j % 384);
        const float* row = Wrf + (long)(m & 511) * (2 * D_) + (m >> 9) * D_;
        float4 v = reinterpret_cast<const float4*>(row)[c4];
        size_t qi = (size_t)m * (D_ / 4) + c4;
        split4_store(v, g_B2hi, g_B2lo, qi);
    }
}

__global__ __launch_bounds__(256) void kz_e1(){
    int i = blockIdx.x * 256 + threadIdx.x;
    if (i < M1) g_e1[i] = 0.f;
}

// ============================================================================
// KMMA: double-buffered cp.async + ldmatrix + mma.sync bf16 GEMM.
// CTA tile 128(M) x 128(N), 8 warps of 32x64, K-chunks of 64 (SW128 swizzle).
// 3 passes (hi*hi, lo*hi, hi*lo) accumulate in fp32 fragments.
// MODE 1: stage-1, epilogue partial e = sum_n was[n]*tanh(C+hb[n]) -> atomicAdd g_e1.
// MODE 2: stage-2, plain stores into g_p.
// ============================================================================
#define SMEM_BUF   65536          // 2 x (A 16KB + B 16KB)
#define SMEM_EPI   1536           // was_s(512) + hb_s(1024)
#define SMEM_TOT   (SMEM_BUF + SMEM_EPI)

template<int KD, int NC, int MODE>
__global__ __launch_bounds__(256) void kmma(const float* __restrict__ wasp)
{
    extern __shared__ char smem[];
    const uint32_t sb = smem_u32(smem);
    const int tid  = threadIdx.x, lane = tid & 31, wid = tid >> 5;
    const int wm   = wid & 3, wn = wid >> 2;
    const int row0 = blockIdx.x * 128;
    const int n0c  = blockIdx.y * 128;
    constexpr int CPP = KD / 64;          // chunks per pass

    const __nv_bfloat16 *Ahi, *Alo, *Bhi, *Blo;
    if (MODE == 1) { Ahi = g_Ahi; Alo = g_Alo; Bhi = g_B1hi; Blo = g_B1lo; }
    else           { Ahi = g_Fhi; Alo = g_Flo; Bhi = g_B2hi; Blo = g_B2lo; }

    float* was_s = (float*)(smem + SMEM_BUF);
    float* hb_s  = (float*)(smem + SMEM_BUF + 512);
    int b0 = 0;
    if (MODE == 1) {
        b0 = row0 / BFB;
        int b1 = (row0 + 127) / BFB;
        for (int i = tid; i < 128; i += 256) {
            was_s[i]       = wasp[n0c + i];
            hb_s[i]        = g_hb[b0 * H_ + n0c + i];
            hb_s[128 + i]  = g_hb[b1 * H_ + n0c + i];
        }
    }

    // cp.async geometry: thread -> (row group, 16B chunk)
    const int ldr = tid >> 3;            // base row (+32 per iter)
    const int ldq = tid & 7;             // 16B chunk within 128B row

    // ldmatrix per-lane geometry (see fragment mapping in theory)
    const int sub = lane >> 3, lr = lane & 7;
    const int a_row = wm * 32 + ((sub & 1) << 3) + lr;    // + i*16
    const int a_cb  = (sub >> 1) << 4;                    // + kb
    const int b_row = wn * 64 + ((sub >> 1) << 3) + lr;   // + j2*16
    const int b_cb  = (sub & 1) << 4;
    const uint32_t amask = (uint32_t)((a_row & 7) << 4);
    const uint32_t bmask = (uint32_t)((b_row & 7) << 4);

    float acc[2][8][4];
    #pragma unroll
    for (int i = 0; i < 2; i++)
        #pragma unroll
        for (int j = 0; j < 8; j++)
            #pragma unroll
            for (int v = 0; v < 4; v++) acc[i][j][v] = 0.f;

    auto load_chunk = [&](int c) {
        const int s = c & 1;
        const int pass = c / CPP;
        const long kin = (long)(c % CPP) * 64;
        const __nv_bfloat16* As = (pass == 1) ? Alo : Ahi;
        const __nv_bfloat16* Bs = (pass == 2) ? Blo : Bhi;
        uint32_t abase = sb + s * 32768;
        uint32_t bbase = abase + 16384;
        #pragma unroll
        for (int it = 0; it < 4; it++) {
            int r = ldr + it * 32;
            uint32_t off = (uint32_t)(r * 128 + ldq * 16) ^ ((uint32_t)(r & 7) << 4);
            CP_ASYNC16(abase + off, As + (long)(row0 + r) * KD + kin + ldq * 8);
            CP_ASYNC16(bbase + off, Bs + (long)(n0c + r) * KD + kin + ldq * 8);
        }
        CP_COMMIT();
    };

    auto compute_chunk = [&](int c) {
        const int s = c & 1;
        uint32_t abase = sb + s * 32768;
        uint32_t bbase = abase + 16384;
        #pragma unroll
        for (int ks = 0; ks < 4; ks++) {
            const uint32_t kb = (uint32_t)(ks * 32);
            uint32_t af[2][4], bfr[4][4];
            #pragma unroll
            for (int i = 0; i < 2; i++)
                ldsm4(af[i], abase + (uint32_t)((a_row + i * 16) * 128)
                                   + (((uint32_t)a_cb + kb) ^ amask));
            #pragma unroll
            for (int j2 = 0; j2 < 4; j2++)
                ldsm4(bfr[j2], bbase + (uint32_t)((b_row + j2 * 16) * 128)
                                     + (((uint32_t)b_cb + kb) ^ bmask));
            #pragma unroll
            for (int i = 0; i < 2; i++)
                #pragma unroll
                for (int j = 0; j < 8; j++)
                    mma16816(acc[i][j], af[i], &bfr[j >> 1][(j & 1) * 2]);
        }
    };

    load_chunk(0);
    for (int c = 0; c < NC; c++) {
        if (c + 1 < NC) { load_chunk(c + 1); CP_WAIT(1); }
        else            { CP_WAIT(0); }
        __syncthreads();
        compute_chunk(c);
        __syncthreads();
    }

    const int g = lane >> 2, t = lane & 3;
    if (MODE == 1) {
        #pragma unroll
        for (int i = 0; i < 2; i++) {
            int rl = wm * 32 + i * 16 + g;
            int rh = rl + 8;
            const float* hbl = hb_s + (((row0 + rl) / BFB) == b0 ? 0 : 128);
            const float* hbh = hb_s + (((row0 + rh) / BFB) == b0 ? 0 : 128);
            float pl = 0.f, ph = 0.f;
            #pragma unroll
            for (int j = 0; j < 8; j++) {
                int nl = wn * 64 + j * 8 + 2 * t;
                float w0 = was_s[nl], w1 = was_s[nl + 1];
                pl += w0 * tanhf(acc[i][j][0] + hbl[nl])
                    + w1 * tanhf(acc[i][j][1] + hbl[nl + 1]);
                ph += w0 * tanhf(acc[i][j][2] + hbh[nl])
                    + w1 * tanhf(acc[i][j][3] + hbh[nl + 1]);
            }
            pl += __shfl_xor_sync(0xffffffffu, pl, 1);
            pl += __shfl_xor_sync(0xffffffffu, pl, 2);
            ph += __shfl_xor_sync(0xffffffffu, ph, 1);
            ph += __shfl_xor_sync(0xffffffffu, ph, 2);
            if (t == 0) {
                atomicAdd(&g_e1[row0 + rl], pl);
                atomicAdd(&g_e1[row0 + rh], ph);
            }
        }
    } else {
        #pragma unroll
        for (int i = 0; i < 2; i++) {
            int rl = row0 + wm * 32 + i * 16 + g;
            #pragma unroll
            for (int j = 0; j < 8; j++) {
                int nc = n0c + wn * 64 + j * 8 + 2 * t;
                *reinterpret_cast<float2*>(&g_p[(long)rl * PM + nc])
                    = make_float2(acc[i][j][0], acc[i][j][1]);
                *reinterpret_cast<float2*>(&g_p[(long)(rl + 8) * PM + nc])
                    = make_float2(acc[i][j][2], acc[i][j][3]);
            }
        }
    }
}

// ============================================================================
// K3: softmax over NB + attention + concat + bf16 split of feat
// ============================================================================
__global__ __launch_bounds__(256) void k3_soft(const float* __restrict__ obj,
                                               const float* __restrict__ i3d)
{
    __shared__ float e_s[NB_], alpha[NB_];
    int bf = blockIdx.x, tid = threadIdx.x;
    const float* fbase = obj + (long)bf * NB_ * R_;
    if (tid < NB_) e_s[tid] = g_e1[bf * NB_ + tid];
    __syncthreads();
    if (tid == 0) {
        float m = -1e30f;
        for (int l = 0; l < NB_; l++) m = fmaxf(m, e_s[l]);
        float s = 0.f, tmp[NB_];
        for (int l = 0; l < NB_; l++) { tmp[l] = expf(e_s[l] - m); s += tmp[l]; }
        float inv = 1.f / s;
        for (int l = 0; l < NB_; l++) alpha[l] = tmp[l] * inv;
    }
    __syncthreads();
    float* fout = g_feat + (long)bf * D_;
    __nv_bfloat16* fh = g_Fhi + (long)bf * D_;
    __nv_bfloat16* fl = g_Flo + (long)bf * D_;
    for (int d = tid; d < R_; d += 256) {
        float s = 0.f;
        #pragma unroll 4
        for (int l = 0; l < NB_; l++) s = fmaf(alpha[l], fbase[l * R_ + d], s);
        fout[d] = s;
        __nv_bfloat16 h = __float2bfloat16(s);
        fh[d] = h; fl[d] = __float2bfloat16(s - __bfloat162float(h));
    }
    for (int d = tid; d < 2 * H_; d += 256) {
        float v = i3d[(long)bf * (2 * H_) + d];
        fout[R_ + d] = v;
        __nv_bfloat16 h = __float2bfloat16(v);
        fh[R_ + d] = h; fl[R_ + d] = __float2bfloat16(v - __bfloat162float(h));
    }
}

// ============================================================================
// K5: e2[b,i,j] = war . tanh(p2[b,i] + p1[b,j] + hp2[b])
// ============================================================================
__global__ __launch_bounds__(256) void k5_e2(const float* __restrict__ war)
{
    __shared__ float base[H_];
    __shared__ float warr[H_];
    int bi = blockIdx.x;
    int b = bi / F_;
    int tid = threadIdx.x, warp = tid >> 5, lane = tid & 31;
    for (int h = tid; h < H_; h += 256) {
        base[h] = g_p[(long)bi * PM + H_ + h] + g_hp2[b * H_ + h];
        warr[h] = war[h];
    }
    __syncthreads();
    for (int jj = 0; jj < 5; jj++) {
        int j = warp + jj * 8;
        const float* p1 = g_p + (long)(b * F_ + j) * PM;
        float part = 0.f;
        #pragma unroll 4
        for (int kk = 0; kk < 16; kk++) {
            int h = lane + kk * 32;
            part += warr[h] * tanhf(base[h] + p1[h]);
        }
        #pragma unroll
        for (int off = 16; off; off >>= 1)
            part += __shfl_xor_sync(0xffffffffu, part, off);
        if (lane == 0) g_e2[(long)b * (F_ * F_) + (bi % F_) * F_ + j] = part;
    }
}

// ============================================================================
// K6: per-batch softmax over F*F, marginals, final weighted sums
// ============================================================================
__global__ __launch_bounds__(256) void k6_final(float* __restrict__ out)
{
    __shared__ float ex[F_ * F_];
    __shared__ float red[256];
    __shared__ float rowsum[F_], colsum[F_];
    int b = blockIdx.x, tid = threadIdx.x;
    const float* e = g_e2 + b * (F_ * F_);

    float m = -1e30f;
    for (int t = tid; t < F_ * F_; t += 256) m = fmaxf(m, e[t]);
    red[tid] = m; __syncthreads();
    for (int s = 128; s > 0; s >>= 1) {
        if (tid < s) red[tid] = fmaxf(red[tid], red[tid + s]);
        __syncthreads();
    }
    m = red[0]; __syncthreads();

    float sum = 0.f;
    for (int t = tid; t < F_ * F_; t += 256) { float v = expf(e[t] - m); ex[t] = v; sum += v; }
    red[tid] = sum; __syncthreads();
    for (int s = 128; s > 0; s >>= 1) {
        if (tid < s) red[tid] += red[tid + s];
        __syncthreads();
    }
    float inv = 1.f / red[0];

    if (tid < F_) { rowsum[tid] = 0.f; colsum[tid] = 0.f; }
    __syncthreads();
    for (int t = tid; t < F_ * F_; t += 256) {
        float a = ex[t] * inv;
        atomicAdd(&rowsum[t / F_], a);
        atomicAdd(&colsum[t % F_], a);
    }
    __syncthreads();

    for (int d = tid; d < D_; d += 256) {
        float r1 = 0.f, r2 = 0.f;
        #pragma unroll 8
        for (int q = 0; q < F_; q++) {
            float fv = g_feat[(long)(b * F_ + q) * D_ + d];
            r1 = fmaf(colsum[q], fv, r1);
            r2 = fmaf(rowsum[q], fv, r2);
        }
        out[b * (2 * D_) + d]      = r1;
        out[b * (2 * D_) + D_ + d] = r2;
    }
}

// ============================================================================
extern "C" void kernel_launch(void* const* d_in, const int* in_sizes, int n_in,
                              void* d_out, int out_size)
{
    const float* i3d    = (const float*)d_in[0];
    const float* obj    = (const float*)d_in[1];
    const float* hidden = (const float*)d_in[2];
    const float* Wsf    = (const float*)d_in[3];
    const float* Wsh    = (const float*)d_in[5];
    const float* bsf    = (const float*)d_in[4];
    const float* bsh    = (const float*)d_in[6];
    const float* was    = (const float*)d_in[7];
    const float* Wrf    = (const float*)d_in[8];
    const float* brf    = (const float*)d_in[9];
    const float* Wrh    = (const float*)d_in[10];
    const float* brh    = (const float*)d_in[11];
    const float* war    = (const float*)d_in[12];
    float* out = (float*)d_out;

    cudaFuncSetAttribute(kmma<512, 24, 1>,  cudaFuncAttributeMaxDynamicSharedMemorySize, SMEM_TOT);
    cudaFuncSetAttribute(kmma<1536, 72, 2>, cudaFuncAttributeMaxDynamicSharedMemorySize, SMEM_TOT);

    k0_hproj  <<<B_, 256>>>(hidden, Wsh, bsh, bsf, Wrh, brh, brf);
    k1_splitA <<<23040, 256>>>(obj);
    k1_splitB <<<1792,  256>>>(Wsf, Wrf);
    kz_e1     <<<180, 256>>>();
    kmma<512, 24, 1>  <<<dim3(M1 / 128, 4),  256, SMEM_TOT>>>(was);     // stage-1 mma.sync + tanh reduce
    k3_soft   <<<NBF, 256>>>(obj, i3d);
    kmma<1536, 72, 2> <<<dim3(NBF / 128, 8), 256, SMEM_TOT>>>(nullptr); // stage-2 mma.sync
    k5_e2     <<<NBF, 256>>>(war);
    k6_final  <<<B_, 256>>>(out);
}

// round 8
// speedup vs baseline: 2.5192x; 1.0516x over previous
#include <cuda_runtime.h>
#include <cuda_fp16.h>
#include <math.h>
#include <stdint.h>

#define B_   32
#define F_   40
#define NB_  36
#define R_   512
#define H_   512
#define D_   1536
#define NBF  1280
#define PM   1024
#define M1   46080
#define BFB  1440      // F_*NB_ rows per batch in stage-1

// ---------------- device scratch (static, no allocation) ----------------
__device__ __align__(16) float g_hb [B_*H_];
__device__ __align__(16) float g_hp2[B_*H_];
__device__ __align__(16) float g_e1 [M1];
__device__ __align__(16) float g_feat[(long)NBF*D_];
__device__ __align__(16) float g_p  [(long)NBF*PM];
__device__ __align__(16) float g_e2 [B_*F_*F_];
__device__ __align__(16) __half g_Ahi[(long)M1*R_];
__device__ __align__(16) __half g_Alo[(long)M1*R_];
__device__ __align__(16) __half g_B1h[H_*R_];
__device__ __align__(16) __half g_Fhi[(long)NBF*D_];
__device__ __align__(16) __half g_Flo[(long)NBF*D_];
__device__ __align__(16) __half g_B2h[(long)PM*D_];

// ---------------- portable (non-'a') PTX helpers ----------------
__device__ __forceinline__ uint32_t smem_u32(const void* p){
    uint32_t a;
    asm("{ .reg .u64 t; cvta.to.shared.u64 t, %1; cvt.u32.u64 %0, t; }" : "=r"(a) : "l"(p));
    return a;
}
#define CP_ASYNC16(dst, src) \
    asm volatile("cp.async.cg.shared.global [%0], [%1], 16;" :: "r"(dst), "l"(src) : "memory")
#define CP_COMMIT() asm volatile("cp.async.commit_group;" ::: "memory")
#define CP_WAIT(n)  asm volatile("cp.async.wait_group %0;" :: "n"(n) : "memory")

__device__ __forceinline__ void ldsm4(uint32_t* r, uint32_t addr){
    asm volatile("ldmatrix.sync.aligned.m8n8.x4.shared.b16 {%0,%1,%2,%3}, [%4];"
        : "=r"(r[0]), "=r"(r[1]), "=r"(r[2]), "=r"(r[3]) : "r"(addr));
}
__device__ __forceinline__ void mma16816(float* c, const uint32_t* a, const uint32_t* b){
    asm volatile("mma.sync.aligned.m16n8k16.row.col.f32.f16.f16.f32 "
        "{%0,%1,%2,%3}, {%4,%5,%6,%7}, {%8,%9}, {%0,%1,%2,%3};"
        : "+f"(c[0]), "+f"(c[1]), "+f"(c[2]), "+f"(c[3])
        : "r"(a[0]), "r"(a[1]), "r"(a[2]), "r"(a[3]), "r"(b[0]), "r"(b[1]));
}

// ============================================================================
// K0: hidden projections. grid (32, 16); block handles 32 h-values,
// 8 threads per h split over k, shuffle reduce.
// ============================================================================
__global__ __launch_bounds__(256) void k0_hproj(
    const float* __restrict__ hidden, const float* __restrict__ Wsh,
    const float* __restrict__ bsh,    const float* __restrict__ bsf,
    const float* __restrict__ Wrh,    const float* __restrict__ brh,
    const float* __restrict__ brf)
{
    __shared__ float hs[H_];
    int b = blockIdx.x, tid = threadIdx.x;
    int h = blockIdx.y * 32 + (tid >> 3);
    int ks = tid & 7;
    for (int i = tid; i < H_; i += 256) hs[i] = hidden[b * H_ + i];
    __syncthreads();
    const float4* w1 = reinterpret_cast<const float4*>(Wsh + (long)h * H_) + ks * 16;
    const float4* w2 = reinterpret_cast<const float4*>(Wrh + (long)h * H_) + ks * 16;
    const float*  hk = hs + ks * 64;
    float a1 = 0.f, a2 = 0.f;
    #pragma unroll
    for (int k4 = 0; k4 < 16; k4++) {
        float4 v1 = w1[k4], v2 = w2[k4];
        float h0 = hk[k4*4+0], h1 = hk[k4*4+1], h2 = hk[k4*4+2], h3 = hk[k4*4+3];
        a1 = fmaf(h0, v1.x, a1); a1 = fmaf(h1, v1.y, a1);
        a1 = fmaf(h2, v1.z, a1); a1 = fmaf(h3, v1.w, a1);
        a2 = fmaf(h0, v2.x, a2); a2 = fmaf(h1, v2.y, a2);
        a2 = fmaf(h2, v2.z, a2); a2 = fmaf(h3, v2.w, a2);
    }
    #pragma unroll
    for (int off = 4; off; off >>= 1) {
        a1 += __shfl_xor_sync(0xffffffffu, a1, off);
        a2 += __shfl_xor_sync(0xffffffffu, a2, off);
    }
    if (ks == 0) {
        g_hb [b * H_ + h] = a1 + bsh[h] + bsf[h];
        g_hp2[b * H_ + h] = a2 + brh[h] + brf[h];
    }
}

// ============================================================================
// K1: fp16 hi/lo splits
// ============================================================================
__device__ __forceinline__ void split4_store(float4 v, __half* hi, __half* lo, size_t qi){
    __half2 h01 = __floats2half2_rn(v.x, v.y);
    __half2 h23 = __floats2half2_rn(v.z, v.w);
    float rx = __low2float(h01), ry = __high2float(h01);
    float rz = __low2float(h23), rw = __high2float(h23);
    __half2 l01 = __floats2half2_rn(v.x - rx, v.y - ry);
    __half2 l23 = __floats2half2_rn(v.z - rz, v.w - rw);
    reinterpret_cast<uint2*>(hi)[qi] = make_uint2(*(uint32_t*)&h01, *(uint32_t*)&h23);
    reinterpret_cast<uint2*>(lo)[qi] = make_uint2(*(uint32_t*)&l01, *(uint32_t*)&l23);
}
__device__ __forceinline__ void hi4_store(float4 v, __half* hi, size_t qi){
    __half2 h01 = __floats2half2_rn(v.x, v.y);
    __half2 h23 = __floats2half2_rn(v.z, v.w);
    reinterpret_cast<uint2*>(hi)[qi] = make_uint2(*(uint32_t*)&h01, *(uint32_t*)&h23);
}

__global__ __launch_bounds__(256) void k1_splitA(const float* __restrict__ src){
    size_t i = (size_t)blockIdx.x * 256 + threadIdx.x;
    float4 v = reinterpret_cast<const float4*>(src)[i];
    split4_store(v, g_Ahi, g_Alo, i);
}

// also zeroes g_e1 (so kmma1 can atomicAdd)
__global__ __launch_bounds__(256) void k1_splitB(const float* __restrict__ Wsf,
                                                 const float* __restrict__ Wrf){
    size_t q = (size_t)blockIdx.x * 256 + threadIdx.x;
    if (q < M1) g_e1[q] = 0.f;
    if (q < 65536) {                                     // B1: Wsf 512x512
        float4 v = reinterpret_cast<const float4*>(Wsf)[q];
        hi4_store(v, g_B1h, q);
    } else {                                             // B2: rearranged Wrf -> 1024x1536
        size_t j = q - 65536;
        int m = (int)(j / 384), c4 = (int)(j % 384);
        const float* row = Wrf + (long)(m & 511) * (2 * D_) + (m >> 9) * D_;
        float4 v = reinterpret_cast<const float4*>(row)[c4];
        hi4_store(v, g_B2h, (size_t)m * (D_ / 4) + c4);
    }
}

// ============================================================================
// KMMA: double-buffered cp.async + ldmatrix + mma.sync fp16 GEMM, 2 passes
// (Ahi*Bh + Alo*Bh; B rounded once to fp16). CTA tile 128x128, 8 warps 32x64,
// K-chunks of 64, SW128 swizzle. MODE 1: tanh-reduce epilogue -> atomicAdd g_e1.
// MODE 2: plain stores into g_p.
// ============================================================================
#define SMEM_BUF   65536
#define SMEM_EPI   1536
#define SMEM_TOT   (SMEM_BUF + SMEM_EPI)

template<int KD, int NC, int MODE>
__global__ __launch_bounds__(256, 2) void kmma(const float* __restrict__ wasp)
{
    extern __shared__ char smem[];
    const uint32_t sb = smem_u32(smem);
    const int tid  = threadIdx.x, lane = tid & 31, wid = tid >> 5;
    const int wm   = wid & 3, wn = wid >> 2;
    const int row0 = blockIdx.x * 128;
    const int n0c  = blockIdx.y * 128;
    constexpr int CPP = KD / 64;          // chunks per pass

    const __half *Ahi, *Alo, *Bh;
    if (MODE == 1) { Ahi = g_Ahi; Alo = g_Alo; Bh = g_B1h; }
    else           { Ahi = g_Fhi; Alo = g_Flo; Bh = g_B2h; }

    float* was_s = (float*)(smem + SMEM_BUF);
    float* hb_s  = (float*)(smem + SMEM_BUF + 512);
    int b0 = 0;
    if (MODE == 1) {
        b0 = row0 / BFB;
        int b1 = (row0 + 127) / BFB;
        for (int i = tid; i < 128; i += 256) {
            was_s[i]       = wasp[n0c + i];
            hb_s[i]        = g_hb[b0 * H_ + n0c + i];
            hb_s[128 + i]  = g_hb[b1 * H_ + n0c + i];
        }
    }

    const int ldr = tid >> 3;            // base row (+32 per iter)
    const int ldq = tid & 7;             // 16B chunk within 128B row

    const int sub = lane >> 3, lr = lane & 7;
    const int a_row = wm * 32 + ((sub & 1) << 3) + lr;
    const int a_cb  = (sub >> 1) << 4;
    const int b_row = wn * 64 + ((sub >> 1) << 3) + lr;
    const int b_cb  = (sub & 1) << 4;
    const uint32_t amask = (uint32_t)((a_row & 7) << 4);
    const uint32_t bmask = (uint32_t)((b_row & 7) << 4);

    float acc[2][8][4];
    #pragma unroll
    for (int i = 0; i < 2; i++)
        #pragma unroll
        for (int j = 0; j < 8; j++)
            #pragma unroll
            for (int v = 0; v < 4; v++) acc[i][j][v] = 0.f;

    auto load_chunk = [&](int c) {
        const int s = c & 1;
        const int pass = c / CPP;
        const long kin = (long)(c % CPP) * 64;
        const __half* As = (pass == 1) ? Alo : Ahi;
        uint32_t abase = sb + s * 32768;
        uint32_t bbase = abase + 16384;
        #pragma unroll
        for (int it = 0; it < 4; it++) {
            int r = ldr + it * 32;
            uint32_t off = (uint32_t)(r * 128 + ldq * 16) ^ ((uint32_t)(r & 7) << 4);
            CP_ASYNC16(abase + off, As + (long)(row0 + r) * KD + kin + ldq * 8);
            CP_ASYNC16(bbase + off, Bh + (long)(n0c + r) * KD + kin + ldq * 8);
        }
        CP_COMMIT();
    };

    auto compute_chunk = [&](int c) {
        const int s = c & 1;
        uint32_t abase = sb + s * 32768;
        uint32_t bbase = abase + 16384;
        #pragma unroll
        for (int ks = 0; ks < 4; ks++) {
            const uint32_t kb = (uint32_t)(ks * 32);
            uint32_t af[2][4], bfr[4][4];
            #pragma unroll
            for (int i = 0; i < 2; i++)
                ldsm4(af[i], abase + (uint32_t)((a_row + i * 16) * 128)
                                   + (((uint32_t)a_cb + kb) ^ amask));
            #pragma unroll
            for (int j2 = 0; j2 < 4; j2++)
                ldsm4(bfr[j2], bbase + (uint32_t)((b_row + j2 * 16) * 128)
                                     + (((uint32_t)b_cb + kb) ^ bmask));
            #pragma unroll
            for (int i = 0; i < 2; i++)
                #pragma unroll
                for (int j = 0; j < 8; j++)
                    mma16816(acc[i][j], af[i], &bfr[j >> 1][(j & 1) * 2]);
        }
    };

    load_chunk(0);
    for (int c = 0; c < NC; c++) {
        if (c + 1 < NC) { load_chunk(c + 1); CP_WAIT(1); }
        else            { CP_WAIT(0); }
        __syncthreads();
        compute_chunk(c);
        __syncthreads();
    }

    const int g = lane >> 2, t = lane & 3;
    if (MODE == 1) {
        #pragma unroll
        for (int i = 0; i < 2; i++) {
            int rl = wm * 32 + i * 16 + g;
            int rh = rl + 8;
            const float* hbl = hb_s + (((row0 + rl) / BFB) == b0 ? 0 : 128);
            const float* hbh = hb_s + (((row0 + rh) / BFB) == b0 ? 0 : 128);
            float pl = 0.f, ph = 0.f;
            #pragma unroll
            for (int j = 0; j < 8; j++) {
                int nl = wn * 64 + j * 8 + 2 * t;
                float w0 = was_s[nl], w1 = was_s[nl + 1];
                pl += w0 * tanhf(acc[i][j][0] + hbl[nl])
                    + w1 * tanhf(acc[i][j][1] + hbl[nl + 1]);
                ph += w0 * tanhf(acc[i][j][2] + hbh[nl])
                    + w1 * tanhf(acc[i][j][3] + hbh[nl + 1]);
            }
            pl += __shfl_xor_sync(0xffffffffu, pl, 1);
            pl += __shfl_xor_sync(0xffffffffu, pl, 2);
            ph += __shfl_xor_sync(0xffffffffu, ph, 1);
            ph += __shfl_xor_sync(0xffffffffu, ph, 2);
            if (t == 0) {
                atomicAdd(&g_e1[row0 + rl], pl);
                atomicAdd(&g_e1[row0 + rh], ph);
            }
        }
    } else {
        #pragma unroll
        for (int i = 0; i < 2; i++) {
            int rl = row0 + wm * 32 + i * 16 + g;
            #pragma unroll
            for (int j = 0; j < 8; j++) {
                int nc = n0c + wn * 64 + j * 8 + 2 * t;
                *reinterpret_cast<float2*>(&g_p[(long)rl * PM + nc])
                    = make_float2(acc[i][j][0], acc[i][j][1]);
                *reinterpret_cast<float2*>(&g_p[(long)(rl + 8) * PM + nc])
                    = make_float2(acc[i][j][2], acc[i][j][3]);
            }
        }
    }
}

// ============================================================================
// K3: softmax over NB + attention + concat + fp16 split of feat
// ============================================================================
__global__ __launch_bounds__(256) void k3_soft(const float* __restrict__ obj,
                                               const float* __restrict__ i3d)
{
    __shared__ float e_s[NB_], alpha[NB_];
    int bf = blockIdx.x, tid = threadIdx.x;
    const float* fbase = obj + (long)bf * NB_ * R_;
    if (tid < NB_) e_s[tid] = g_e1[bf * NB_ + tid];
    __syncthreads();
    if (tid == 0) {
        float m = -1e30f;
        for (int l = 0; l < NB_; l++) m = fmaxf(m, e_s[l]);
        float s = 0.f, tmp[NB_];
        for (int l = 0; l < NB_; l++) { tmp[l] = expf(e_s[l] - m); s += tmp[l]; }
        float inv = 1.f / s;
        for (int l = 0; l < NB_; l++) alpha[l] = tmp[l] * inv;
    }
    __syncthreads();
    float* fout = g_feat + (long)bf * D_;
    __half* fh = g_Fhi + (long)bf * D_;
    __half* fl = g_Flo + (long)bf * D_;
    for (int d = tid; d < R_; d += 256) {
        float s = 0.f;
        #pragma unroll 4
        for (int l = 0; l < NB_; l++) s = fmaf(alpha[l], fbase[l * R_ + d], s);
        fout[d] = s;
        __half h = __float2half_rn(s);
        fh[d] = h; fl[d] = __float2half_rn(s - __half2float(h));
    }
    for (int d = tid; d < 2 * H_; d += 256) {
        float v = i3d[(long)bf * (2 * H_) + d];
        fout[R_ + d] = v;
        __half h = __float2half_rn(v);
        fh[R_ + d] = h; fl[R_ + d] = __float2half_rn(v - __half2float(h));
    }
}

// ============================================================================
// K5: e2[b,i,j] = war . tanh(p2[b,i] + p1[b,j] + hp2[b])
// ============================================================================
__global__ __launch_bounds__(256) void k5_e2(const float* __restrict__ war)
{
    __shared__ float base[H_];
    __shared__ float warr[H_];
    int bi = blockIdx.x;
    int b = bi / F_;
    int tid = threadIdx.x, warp = tid >> 5, lane = tid & 31;
    for (int h = tid; h < H_; h += 256) {
        base[h] = g_p[(long)bi * PM + H_ + h] + g_hp2[b * H_ + h];
        warr[h] = war[h];
    }
    __syncthreads();
    for (int jj = 0; jj < 5; jj++) {
        int j = warp + jj * 8;
        const float* p1 = g_p + (long)(b * F_ + j) * PM;
        float part = 0.f;
        #pragma unroll 4
        for (int kk = 0; kk < 16; kk++) {
            int h = lane + kk * 32;
            part += warr[h] * tanhf(base[h] + p1[h]);
        }
        #pragma unroll
        for (int off = 16; off; off >>= 1)
            part += __shfl_xor_sync(0xffffffffu, part, off);
        if (lane == 0) g_e2[(long)b * (F_ * F_) + (bi % F_) * F_ + j] = part;
    }
}

// ============================================================================
// K6: per-batch softmax over F*F, marginals, final weighted sums. grid (32,3).
// ============================================================================
__global__ __launch_bounds__(256) void k6_final(float* __restrict__ out)
{
    __shared__ float ex[F_ * F_];
    __shared__ float red[256];
    __shared__ float rowsum[F_], colsum[F_];
    int b = blockIdx.x, tid = threadIdx.x;
    const float* e = g_e2 + b * (F_ * F_);

    float m = -1e30f;
    for (int t = tid; t < F_ * F_; t += 256) m = fmaxf(m, e[t]);
    red[tid] = m; __syncthreads();
    for (int s = 128; s > 0; s >>= 1) {
        if (tid < s) red[tid] = fmaxf(red[tid], red[tid + s]);
        __syncthreads();
    }
    m = red[0]; __syncthreads();

    float sum = 0.f;
    for (int t = tid; t < F_ * F_; t += 256) { float v = expf(e[t] - m); ex[t] = v; sum += v; }
    red[tid] = sum; __syncthreads();
    for (int s = 128; s > 0; s >>= 1) {
        if (tid < s) red[tid] += red[tid + s];
        __syncthreads();
    }
    float inv = 1.f / red[0];

    if (tid < F_) { rowsum[tid] = 0.f; colsum[tid] = 0.f; }
    __syncthreads();
    for (int t = tid; t < F_ * F_; t += 256) {
        float a = ex[t] * inv;
        atomicAdd(&rowsum[t / F_], a);
        atomicAdd(&colsum[t % F_], a);
    }
    __syncthreads();

    int c0 = blockIdx.y * 512;
    for (int d = c0 + tid; d < c0 + 512; d += 256) {
        float r1 = 0.f, r2 = 0.f;
        #pragma unroll 8
        for (int q = 0; q < F_; q++) {
            float fv = g_feat[(long)(b * F_ + q) * D_ + d];
            r1 = fmaf(colsum[q], fv, r1);
            r2 = fmaf(rowsum[q], fv, r2);
        }
        out[b * (2 * D_) + d]      = r1;
        out[b * (2 * D_) + D_ + d] = r2;
    }
}

// ============================================================================
extern "C" void kernel_launch(void* const* d_in, const int* in_sizes, int n_in,
                              void* d_out, int out_size)
{
    const float* i3d    = (const float*)d_in[0];
    const float* obj    = (const float*)d_in[1];
    const float* hidden = (const float*)d_in[2];
    const float* Wsf    = (const float*)d_in[3];
    const float* bsf    = (const float*)d_in[4];
    const float* Wsh    = (const float*)d_in[5];
    const float* bsh    = (const float*)d_in[6];
    const float* was    = (const float*)d_in[7];
    const float* Wrf    = (const float*)d_in[8];
    const float* brf    = (const float*)d_in[9];
    const float* Wrh    = (const float*)d_in[10];
    const float* brh    = (const float*)d_in[11];
    const float* war    = (const float*)d_in[12];
    float* out = (float*)d_out;

    cudaFuncSetAttribute(kmma<512, 16, 1>,  cudaFuncAttributeMaxDynamicSharedMemorySize, SMEM_TOT);
    cudaFuncSetAttribute(kmma<1536, 48, 2>, cudaFuncAttributeMaxDynamicSharedMemorySize, SMEM_TOT);

    k0_hproj  <<<dim3(B_, 16), 256>>>(hidden, Wsh, bsh, bsf, Wrh, brh, brf);
    k1_splitA <<<23040, 256>>>(obj);
    k1_splitB <<<1792,  256>>>(Wsf, Wrf);
    kmma<512, 16, 1>  <<<dim3(M1 / 128, 4),  256, SMEM_TOT>>>(was);     // 4th launch -> profiled
    k3_soft   <<<NBF, 256>>>(obj, i3d);
    kmma<1536, 48, 2> <<<dim3(NBF / 128, 8), 256, SMEM_TOT>>>(nullptr);
    k5_e2     <<<NBF, 256>>>(war);
    k6_final  <<<dim3(B_, 3), 256>>>(out);
}

// round 9
// speedup vs baseline: 4.9827x; 1.9779x over previous
#include <cuda_runtime.h>
#include <cuda_fp16.h>
#include <math.h>
#include <stdint.h>

#define B_   32
#define F_   40
#define NB_  36
#define R_   512
#define H_   512
#define D_   1536
#define NBF  1280
#define PM   1024
#define M1   46080
#define BFB  1440      // F_*NB_ rows per batch in stage-1

// ---------------- device scratch (static, no allocation) ----------------
__device__ __align__(16) float g_hb [B_*H_];
__device__ __align__(16) float g_hp2[B_*H_];
__device__ __align__(16) float g_e1 [M1];
__device__ __align__(16) float g_feat[(long)NBF*D_];
__device__ __align__(16) float g_p  [(long)NBF*PM];
__device__ __align__(16) float g_e2 [B_*F_*F_];
__device__ __align__(16) __half g_Ah [(long)M1*R_];
__device__ __align__(16) __half g_B1h[H_*R_];
__device__ __align__(16) __half g_Fh [(long)NBF*D_];
__device__ __align__(16) __half g_B2h[(long)PM*D_];

// ---------------- portable (non-'a') PTX helpers ----------------
__device__ __forceinline__ uint32_t smem_u32(const void* p){
    uint32_t a;
    asm("{ .reg .u64 t; cvta.to.shared.u64 t, %1; cvt.u32.u64 %0, t; }" : "=r"(a) : "l"(p));
    return a;
}
#define CP_ASYNC16(dst, src) \
    asm volatile("cp.async.cg.shared.global [%0], [%1], 16;" :: "r"(dst), "l"(src) : "memory")
#define CP_COMMIT() asm volatile("cp.async.commit_group;" ::: "memory")
#define CP_WAIT(n)  asm volatile("cp.async.wait_group %0;" :: "n"(n) : "memory")

__device__ __forceinline__ void ldsm4(uint32_t* r, uint32_t addr){
    asm volatile("ldmatrix.sync.aligned.m8n8.x4.shared.b16 {%0,%1,%2,%3}, [%4];"
        : "=r"(r[0]), "=r"(r[1]), "=r"(r[2]), "=r"(r[3]) : "r"(addr));
}
__device__ __forceinline__ void mma16816(float* c, const uint32_t* a, const uint32_t* b){
    asm volatile("mma.sync.aligned.m16n8k16.row.col.f32.f16.f16.f32 "
        "{%0,%1,%2,%3}, {%4,%5,%6,%7}, {%8,%9}, {%0,%1,%2,%3};"
        : "+f"(c[0]), "+f"(c[1]), "+f"(c[2]), "+f"(c[3])
        : "r"(a[0]), "r"(a[1]), "r"(a[2]), "r"(a[3]), "r"(b[0]), "r"(b[1]));
}

// ============================================================================
// K0: hidden projections. grid (32, 16); 8 threads per h split over k.
// ============================================================================
__global__ __launch_bounds__(256) void k0_hproj(
    const float* __restrict__ hidden, const float* __restrict__ Wsh,
    const float* __restrict__ bsh,    const float* __restrict__ bsf,
    const float* __restrict__ Wrh,    const float* __restrict__ brh,
    const float* __restrict__ brf)
{
    __shared__ float hs[H_];
    int b = blockIdx.x, tid = threadIdx.x;
    int h = blockIdx.y * 32 + (tid >> 3);
    int ks = tid & 7;
    for (int i = tid; i < H_; i += 256) hs[i] = hidden[b * H_ + i];
    __syncthreads();
    const float4* w1 = reinterpret_cast<const float4*>(Wsh + (long)h * H_) + ks * 16;
    const float4* w2 = reinterpret_cast<const float4*>(Wrh + (long)h * H_) + ks * 16;
    const float*  hk = hs + ks * 64;
    float a1 = 0.f, a2 = 0.f;
    #pragma unroll
    for (int k4 = 0; k4 < 16; k4++) {
        float4 v1 = w1[k4], v2 = w2[k4];
        float h0 = hk[k4*4+0], h1 = hk[k4*4+1], h2 = hk[k4*4+2], h3 = hk[k4*4+3];
        a1 = fmaf(h0, v1.x, a1); a1 = fmaf(h1, v1.y, a1);
        a1 = fmaf(h2, v1.z, a1); a1 = fmaf(h3, v1.w, a1);
        a2 = fmaf(h0, v2.x, a2); a2 = fmaf(h1, v2.y, a2);
        a2 = fmaf(h2, v2.z, a2); a2 = fmaf(h3, v2.w, a2);
    }
    #pragma unroll
    for (int off = 4; off; off >>= 1) {
        a1 += __shfl_xor_sync(0xffffffffu, a1, off);
        a2 += __shfl_xor_sync(0xffffffffu, a2, off);
    }
    if (ks == 0) {
        g_hb [b * H_ + h] = a1 + bsh[h] + bsf[h];
        g_hp2[b * H_ + h] = a2 + brh[h] + brf[h];
    }
}

// ============================================================================
// K1: fp16 conversions (single rounding; no lo-correction terms)
// ============================================================================
__device__ __forceinline__ void hi4_store(float4 v, __half* hi, size_t qi){
    __half2 h01 = __floats2half2_rn(v.x, v.y);
    __half2 h23 = __floats2half2_rn(v.z, v.w);
    reinterpret_cast<uint2*>(hi)[qi] = make_uint2(*(uint32_t*)&h01, *(uint32_t*)&h23);
}

__global__ __launch_bounds__(256) void k1_splitA(const float* __restrict__ src){
    size_t i = (size_t)blockIdx.x * 256 + threadIdx.x;
    float4 v = reinterpret_cast<const float4*>(src)[i];
    hi4_store(v, g_Ah, i);
}

// also zeroes g_e1 (so kmma1 can atomicAdd)
__global__ __launch_bounds__(256) void k1_splitB(const float* __restrict__ Wsf,
                                                 const float* __restrict__ Wrf){
    size_t q = (size_t)blockIdx.x * 256 + threadIdx.x;
    if (q < M1) g_e1[q] = 0.f;
    if (q < 65536) {                                     // B1: Wsf 512x512
        float4 v = reinterpret_cast<const float4*>(Wsf)[q];
        hi4_store(v, g_B1h, q);
    } else {                                             // B2: rearranged Wrf -> 1024x1536
        size_t j = q - 65536;
        int m = (int)(j / 384), c4 = (int)(j % 384);
        const float* row = Wrf + (long)(m & 511) * (2 * D_) + (m >> 9) * D_;
        float4 v = reinterpret_cast<const float4*>(row)[c4];
        hi4_store(v, g_B2h, (size_t)m * (D_ / 4) + c4);
    }
}

// ============================================================================
// KMMA: double-buffered cp.async + ldmatrix + mma.sync fp16 GEMM, single pass.
// CTA tile 128x128, 8 warps of 32x64, K-chunks of 64, SW128 swizzle.
// MODE 1: tanh-reduce epilogue -> atomicAdd g_e1. MODE 2: stores into g_p.
// ============================================================================
#define SMEM_BUF   65536
#define SMEM_EPI   1536
#define SMEM_TOT   (SMEM_BUF + SMEM_EPI)

template<int KD, int NC, int MODE>
__global__ __launch_bounds__(256, 2) void kmma(const float* __restrict__ wasp)
{
    extern __shared__ char smem[];
    const uint32_t sb = smem_u32(smem);
    const int tid  = threadIdx.x, lane = tid & 31, wid = tid >> 5;
    const int wm   = wid & 3, wn = wid >> 2;
    const int row0 = blockIdx.x * 128;
    const int n0c  = blockIdx.y * 128;

    const __half *Ah, *Bh;
    if (MODE == 1) { Ah = g_Ah; Bh = g_B1h; }
    else           { Ah = g_Fh; Bh = g_B2h; }

    float* was_s = (float*)(smem + SMEM_BUF);
    float* hb_s  = (float*)(smem + SMEM_BUF + 512);
    int b0 = 0;
    if (MODE == 1) {
        b0 = row0 / BFB;
        int b1 = (row0 + 127) / BFB;
        for (int i = tid; i < 128; i += 256) {
            was_s[i]       = wasp[n0c + i];
            hb_s[i]        = g_hb[b0 * H_ + n0c + i];
            hb_s[128 + i]  = g_hb[b1 * H_ + n0c + i];
        }
    }

    const int ldr = tid >> 3;            // base row (+32 per iter)
    const int ldq = tid & 7;             // 16B chunk within 128B row

    const int sub = lane >> 3, lr = lane & 7;
    const int a_row = wm * 32 + ((sub & 1) << 3) + lr;
    const int a_cb  = (sub >> 1) << 4;
    const int b_row = wn * 64 + ((sub >> 1) << 3) + lr;
    const int b_cb  = (sub & 1) << 4;
    const uint32_t amask = (uint32_t)((a_row & 7) << 4);
    const uint32_t bmask = (uint32_t)((b_row & 7) << 4);

    float acc[2][8][4];
    #pragma unroll
    for (int i = 0; i < 2; i++)
        #pragma unroll
        for (int j = 0; j < 8; j++)
            #pragma unroll
            for (int v = 0; v < 4; v++) acc[i][j][v] = 0.f;

    auto load_chunk = [&](int c) {
        const int s = c & 1;
        const long kin = (long)c * 64;
        uint32_t abase = sb + s * 32768;
        uint32_t bbase = abase + 16384;
        #pragma unroll
        for (int it = 0; it < 4; it++) {
            int r = ldr + it * 32;
            uint32_t off = (uint32_t)(r * 128 + ldq * 16) ^ ((uint32_t)(r & 7) << 4);
            CP_ASYNC16(abase + off, Ah + (long)(row0 + r) * KD + kin + ldq * 8);
            CP_ASYNC16(bbase + off, Bh + (long)(n0c + r) * KD + kin + ldq * 8);
        }
        CP_COMMIT();
    };

    auto compute_chunk = [&](int c) {
        const int s = c & 1;
        uint32_t abase = sb + s * 32768;
        uint32_t bbase = abase + 16384;
        #pragma unroll
        for (int ks = 0; ks < 4; ks++) {
            const uint32_t kb = (uint32_t)(ks * 32);
            uint32_t af[2][4], bfr[4][4];
            #pragma unroll
            for (int i = 0; i < 2; i++)
                ldsm4(af[i], abase + (uint32_t)((a_row + i * 16) * 128)
                                   + (((uint32_t)a_cb + kb) ^ amask));
            #pragma unroll
            for (int j2 = 0; j2 < 4; j2++)
                ldsm4(bfr[j2], bbase + (uint32_t)((b_row + j2 * 16) * 128)
                                     + (((uint32_t)b_cb + kb) ^ bmask));
            #pragma unroll
            for (int i = 0; i < 2; i++)
                #pragma unroll
                for (int j = 0; j < 8; j++)
                    mma16816(acc[i][j], af[i], &bfr[j >> 1][(j & 1) * 2]);
        }
    };

    load_chunk(0);
    for (int c = 0; c < NC; c++) {
        if (c + 1 < NC) { load_chunk(c + 1); CP_WAIT(1); }
        else            { CP_WAIT(0); }
        __syncthreads();
        compute_chunk(c);
        __syncthreads();
    }

    const int g = lane >> 2, t = lane & 3;
    if (MODE == 1) {
        #pragma unroll
        for (int i = 0; i < 2; i++) {
            int rl = wm * 32 + i * 16 + g;
            int rh = rl + 8;
            const float* hbl = hb_s + (((row0 + rl) / BFB) == b0 ? 0 : 128);
            const float* hbh = hb_s + (((row0 + rh) / BFB) == b0 ? 0 : 128);
            float pl = 0.f, ph = 0.f;
            #pragma unroll
            for (int j = 0; j < 8; j++) {
                int nl = wn * 64 + j * 8 + 2 * t;
                float w0 = was_s[nl], w1 = was_s[nl + 1];
                pl += w0 * tanhf(acc[i][j][0] + hbl[nl])
                    + w1 * tanhf(acc[i][j][1] + hbl[nl + 1]);
                ph += w0 * tanhf(acc[i][j][2] + hbh[nl])
                    + w1 * tanhf(acc[i][j][3] + hbh[nl + 1]);
            }
            pl += __shfl_xor_sync(0xffffffffu, pl, 1);
            pl += __shfl_xor_sync(0xffffffffu, pl, 2);
            ph += __shfl_xor_sync(0xffffffffu, ph, 1);
            ph += __shfl_xor_sync(0xffffffffu, ph, 2);
            if (t == 0) {
                atomicAdd(&g_e1[row0 + rl], pl);
                atomicAdd(&g_e1[row0 + rh], ph);
            }
        }
    } else {
        #pragma unroll
        for (int i = 0; i < 2; i++) {
            int rl = row0 + wm * 32 + i * 16 + g;
            #pragma unroll
            for (int j = 0; j < 8; j++) {
                int nc = n0c + wn * 64 + j * 8 + 2 * t;
                *reinterpret_cast<float2*>(&g_p[(long)rl * PM + nc])
                    = make_float2(acc[i][j][0], acc[i][j][1]);
                *reinterpret_cast<float2*>(&g_p[(long)(rl + 8) * PM + nc])
                    = make_float2(acc[i][j][2], acc[i][j][3]);
            }
        }
    }
}

// ============================================================================
// K3: softmax over NB + attention + concat + fp16 convert of feat
// ============================================================================
__global__ __launch_bounds__(256) void k3_soft(const float* __restrict__ obj,
                                               const float* __restrict__ i3d)
{
    __shared__ float e_s[NB_], alpha[NB_];
    int bf = blockIdx.x, tid = threadIdx.x;
    const float* fbase = obj + (long)bf * NB_ * R_;
    if (tid < NB_) e_s[tid] = g_e1[bf * NB_ + tid];
    __syncthreads();
    if (tid == 0) {
        float m = -1e30f;
        for (int l = 0; l < NB_; l++) m = fmaxf(m, e_s[l]);
        float s = 0.f, tmp[NB_];
        for (int l = 0; l < NB_; l++) { tmp[l] = expf(e_s[l] - m); s += tmp[l]; }
        float inv = 1.f / s;
        for (int l = 0; l < NB_; l++) alpha[l] = tmp[l] * inv;
    }
    __syncthreads();
    float* fout = g_feat + (long)bf * D_;
    __half* fh = g_Fh + (long)bf * D_;
    for (int d = tid; d < R_; d += 256) {
        float s = 0.f;
        #pragma unroll 4
        for (int l = 0; l < NB_; l++) s = fmaf(alpha[l], fbase[l * R_ + d], s);
        fout[d] = s;
        fh[d] = __float2half_rn(s);
    }
    for (int d = tid; d < 2 * H_; d += 256) {
        float v = i3d[(long)bf * (2 * H_) + d];
        fout[R_ + d] = v;
        fh[R_ + d] = __float2half_rn(v);
    }
}

// ============================================================================
// K5: e2[b,i,j] = war . tanh(p2[b,i] + p1[b,j] + hp2[b])
// ============================================================================
__global__ __launch_bounds__(256) void k5_e2(const float* __restrict__ war)
{
    __shared__ float base[H_];
    __shared__ float warr[H_];
    int bi = blockIdx.x;
    int b = bi / F_;
    int tid = threadIdx.x, warp = tid >> 5, lane = tid & 31;
    for (int h = tid; h < H_; h += 256) {
        base[h] = g_p[(long)bi * PM + H_ + h] + g_hp2[b * H_ + h];
        warr[h] = war[h];
    }
    __syncthreads();
    for (int jj = 0; jj < 5; jj++) {
        int j = warp + jj * 8;
        const float* p1 = g_p + (long)(b * F_ + j) * PM;
        float part = 0.f;
        #pragma unroll 4
        for (int kk = 0; kk < 16; kk++) {
            int h = lane + kk * 32;
            part += warr[h] * tanhf(base[h] + p1[h]);
        }
        #pragma unroll
        for (int off = 16; off; off >>= 1)
            part += __shfl_xor_sync(0xffffffffu, part, off);
        if (lane == 0) g_e2[(long)b * (F_ * F_) + (bi % F_) * F_ + j] = part;
    }
}

// ============================================================================
// K6: per-batch softmax over F*F, marginals, final weighted sums. grid (32,3).
// ============================================================================
__global__ __launch_bounds__(256) void k6_final(float* __restrict__ out)
{
    __shared__ float ex[F_ * F_];
    __shared__ float red[256];
    __shared__ float rowsum[F_], colsum[F_];
    int b = blockIdx.x, tid = threadIdx.x;
    const float* e = g_e2 + b * (F_ * F_);

    float m = -1e30f;
    for (int t = tid; t < F_ * F_; t += 256) m = fmaxf(m, e[t]);
    red[tid] = m; __syncthreads();
    for (int s = 128; s > 0; s >>= 1) {
        if (tid < s) red[tid] = fmaxf(red[tid], red[tid + s]);
        __syncthreads();
    }
    m = red[0]; __syncthreads();

    float sum = 0.f;
    for (int t = tid; t < F_ * F_; t += 256) { float v = expf(e[t] - m); ex[t] = v; sum += v; }
    red[tid] = sum; __syncthreads();
    for (int s = 128; s > 0; s >>= 1) {
        if (tid < s) red[tid] += red[tid + s];
        __syncthreads();
    }
    float inv = 1.f / red[0];

    if (tid < F_) { rowsum[tid] = 0.f; colsum[tid] = 0.f; }
    __syncthreads();
    for (int t = tid; t < F_ * F_; t += 256) {
        float a = ex[t] * inv;
        atomicAdd(&rowsum[t / F_], a);
        atomicAdd(&colsum[t % F_], a);
    }
    __syncthreads();

    int c0 = blockIdx.y * 512;
    for (int d = c0 + tid; d < c0 + 512; d += 256) {
        float r1 = 0.f, r2 = 0.f;
        #pragma unroll 8
        for (int q = 0; q < F_; q++) {
            float fv = g_feat[(long)(b * F_ + q) * D_ + d];
            r1 = fmaf(colsum[q], fv, r1);
            r2 = fmaf(rowsum[q], fv, r2);
        }
        out[b * (2 * D_) + d]      = r1;
        out[b * (2 * D_) + D_ + d] = r2;
    }
}

// ============================================================================
extern "C" void kernel_launch(void* const* d_in, const int* in_sizes, int n_in,
                              void* d_out, int out_size)
{
    const float* i3d    = (const float*)d_in[0];
    const float* obj    = (const float*)d_in[1];
    const float* hidden = (const float*)d_in[2];
    const float* Wsf    = (const float*)d_in[3];
    const float* bsf    = (const float*)d_in[4];
    const float* Wsh    = (const float*)d_in[5];
    const float* bsh    = (const float*)d_in[6];
    const float* was    = (const float*)d_in[7];
    const float* Wrf    = (const float*)d_in[8];
    const float* brf    = (const float*)d_in[9];
    const float* Wrh    = (const float*)d_in[10];
    const float* brh    = (const float*)d_in[11];
    const float* war    = (const float*)d_in[12];
    float* out = (float*)d_out;

    cudaFuncSetAttribute(kmma<512, 8, 1>,   cudaFuncAttributeMaxDynamicSharedMemorySize, SMEM_TOT);
    cudaFuncSetAttribute(kmma<1536, 24, 2>, cudaFuncAttributeMaxDynamicSharedMemorySize, SMEM_TOT);

    k0_hproj  <<<dim3(B_, 16), 256>>>(hidden, Wsh, bsh, bsf, Wrh, brh, brf);
    k1_splitA <<<23040, 256>>>(obj);
    k1_splitB <<<1792,  256>>>(Wsf, Wrf);
    kmma<512, 8, 1>   <<<dim3(M1 / 128, 4),  256, SMEM_TOT>>>(was);     // 4th launch -> profiled
    k3_soft   <<<NBF, 256>>>(obj, i3d);
    kmma<1536, 24, 2> <<<dim3(NBF / 128, 8), 256, SMEM_TOT>>>(nullptr);
    k5_e2     <<<NBF, 256>>>(war);
    k6_final  <<<dim3(B_, 3), 256>>>(out);
}

// round 10
// speedup vs baseline: 5.3413x; 1.0720x over previous
#include <cuda_runtime.h>
#include <cuda_fp16.h>
#include <math.h>
#include <stdint.h>

#define B_   32
#define F_   40
#define NB_  36
#define R_   512
#define H_   512
#define D_   1536
#define NBF  1280
#define PM   1024
#define M1   46080
#define BFB  1440      // F_*NB_ rows per batch in stage-1

// ---------------- device scratch (static, no allocation) ----------------
__device__ __align__(16) float g_hb [B_*H_];
__device__ __align__(16) float g_hp2[B_*H_];
__device__ __align__(16) float g_e1 [M1];
__device__ __align__(16) float g_feat[(long)NBF*D_];
__device__ __align__(16) float g_p  [(long)NBF*PM];
__device__ __align__(16) float g_e2 [B_*F_*F_];
__device__ __align__(16) __half g_Ah [(long)M1*R_];
__device__ __align__(16) __half g_B1h[H_*R_];
__device__ __align__(16) __half g_Fh [(long)NBF*D_];
__device__ __align__(16) __half g_B2h[(long)PM*D_];

// ---------------- portable (non-'a') PTX helpers ----------------
__device__ __forceinline__ uint32_t smem_u32(const void* p){
    uint32_t a;
    asm("{ .reg .u64 t; cvta.to.shared.u64 t, %1; cvt.u32.u64 %0, t; }" : "=r"(a) : "l"(p));
    return a;
}
__device__ __forceinline__ float tanha(float x){
    float y;
    asm("tanh.approx.f32 %0, %1;" : "=f"(y) : "f"(x));
    return y;
}
#define CP_ASYNC16(dst, src) \
    asm volatile("cp.async.cg.shared.global [%0], [%1], 16;" :: "r"(dst), "l"(src) : "memory")
#define CP_COMMIT() asm volatile("cp.async.commit_group;" ::: "memory")
#define CP_WAIT(n)  asm volatile("cp.async.wait_group %0;" :: "n"(n) : "memory")

__device__ __forceinline__ void ldsm4(uint32_t* r, uint32_t addr){
    asm volatile("ldmatrix.sync.aligned.m8n8.x4.shared.b16 {%0,%1,%2,%3}, [%4];"
        : "=r"(r[0]), "=r"(r[1]), "=r"(r[2]), "=r"(r[3]) : "r"(addr));
}
__device__ __forceinline__ void mma16816(float* c, const uint32_t* a, const uint32_t* b){
    asm volatile("mma.sync.aligned.m16n8k16.row.col.f32.f16.f16.f32 "
        "{%0,%1,%2,%3}, {%4,%5,%6,%7}, {%8,%9}, {%0,%1,%2,%3};"
        : "+f"(c[0]), "+f"(c[1]), "+f"(c[2]), "+f"(c[3])
        : "r"(a[0]), "r"(a[1]), "r"(a[2]), "r"(a[3]), "r"(b[0]), "r"(b[1]));
}

// ============================================================================
// K0: hidden projections. grid (32, 16); 8 threads per h split over k.
// ============================================================================
__global__ __launch_bounds__(256) void k0_hproj(
    const float* __restrict__ hidden, const float* __restrict__ Wsh,
    const float* __restrict__ bsh,    const float* __restrict__ bsf,
    const float* __restrict__ Wrh,    const float* __restrict__ brh,
    const float* __restrict__ brf)
{
    __shared__ float hs[H_];
    int b = blockIdx.x, tid = threadIdx.x;
    int h = blockIdx.y * 32 + (tid >> 3);
    int ks = tid & 7;
    for (int i = tid; i < H_; i += 256) hs[i] = hidden[b * H_ + i];
    __syncthreads();
    const float4* w1 = reinterpret_cast<const float4*>(Wsh + (long)h * H_) + ks * 16;
    const float4* w2 = reinterpret_cast<const float4*>(Wrh + (long)h * H_) + ks * 16;
    const float*  hk = hs + ks * 64;
    float a1 = 0.f, a2 = 0.f;
    #pragma unroll
    for (int k4 = 0; k4 < 16; k4++) {
        float4 v1 = w1[k4], v2 = w2[k4];
        float h0 = hk[k4*4+0], h1 = hk[k4*4+1], h2 = hk[k4*4+2], h3 = hk[k4*4+3];
        a1 = fmaf(h0, v1.x, a1); a1 = fmaf(h1, v1.y, a1);
        a1 = fmaf(h2, v1.z, a1); a1 = fmaf(h3, v1.w, a1);
        a2 = fmaf(h0, v2.x, a2); a2 = fmaf(h1, v2.y, a2);
        a2 = fmaf(h2, v2.z, a2); a2 = fmaf(h3, v2.w, a2);
    }
    #pragma unroll
    for (int off = 4; off; off >>= 1) {
        a1 += __shfl_xor_sync(0xffffffffu, a1, off);
        a2 += __shfl_xor_sync(0xffffffffu, a2, off);
    }
    if (ks == 0) {
        g_hb [b * H_ + h] = a1 + bsh[h] + bsf[h];
        g_hp2[b * H_ + h] = a2 + brh[h] + brf[h];
    }
}

// ============================================================================
// K1: fp16 conversions (single rounding)
// ============================================================================
__device__ __forceinline__ void hi4_store(float4 v, __half* hi, size_t qi){
    __half2 h01 = __floats2half2_rn(v.x, v.y);
    __half2 h23 = __floats2half2_rn(v.z, v.w);
    reinterpret_cast<uint2*>(hi)[qi] = make_uint2(*(uint32_t*)&h01, *(uint32_t*)&h23);
}

__global__ __launch_bounds__(256) void k1_splitA(const float* __restrict__ src){
    size_t i = (size_t)blockIdx.x * 256 + threadIdx.x;
    float4 v = reinterpret_cast<const float4*>(src)[i];
    hi4_store(v, g_Ah, i);
}

// also zeroes g_e1 (so kmma1 can atomicAdd)
__global__ __launch_bounds__(256) void k1_splitB(const float* __restrict__ Wsf,
                                                 const float* __restrict__ Wrf){
    size_t q = (size_t)blockIdx.x * 256 + threadIdx.x;
    if (q < M1) g_e1[q] = 0.f;
    if (q < 65536) {                                     // B1: Wsf 512x512
        float4 v = reinterpret_cast<const float4*>(Wsf)[q];
        hi4_store(v, g_B1h, q);
    } else {                                             // B2: rearranged Wrf -> 1024x1536
        size_t j = q - 65536;
        int m = (int)(j / 384), c4 = (int)(j % 384);
        const float* row = Wrf + (long)(m & 511) * (2 * D_) + (m >> 9) * D_;
        float4 v = reinterpret_cast<const float4*>(row)[c4];
        hi4_store(v, g_B2h, (size_t)m * (D_ / 4) + c4);
    }
}

// ============================================================================
// KMMA: 3-stage cp.async + ldmatrix + mma.sync fp16 GEMM, single pass,
// ONE __syncthreads per K-chunk. CTA tile 128x128, 8 warps 32x64, Kc=64,
// SW128 swizzle. MODE 1: tanh.approx-reduce epilogue -> atomicAdd g_e1.
// MODE 2: stores into g_p.
// ============================================================================
#define STAGE_B    32768          // A 16KB + B 16KB per stage
#define SMEM_BUF   (3 * STAGE_B)  // 96KB
#define SMEM_EPI   1536
#define SMEM_TOT   (SMEM_BUF + SMEM_EPI)

template<int KD, int NC, int MODE>
__global__ __launch_bounds__(256, 2) void kmma(const float* __restrict__ wasp)
{
    extern __shared__ char smem[];
    const uint32_t sb = smem_u32(smem);
    const int tid  = threadIdx.x, lane = tid & 31, wid = tid >> 5;
    const int wm   = wid & 3, wn = wid >> 2;
    const int row0 = blockIdx.x * 128;
    const int n0c  = blockIdx.y * 128;

    const __half *Ah, *Bh;
    if (MODE == 1) { Ah = g_Ah; Bh = g_B1h; }
    else           { Ah = g_Fh; Bh = g_B2h; }

    float* was_s = (float*)(smem + SMEM_BUF);
    float* hb_s  = (float*)(smem + SMEM_BUF + 512);
    int b0 = 0;
    if (MODE == 1) {
        b0 = row0 / BFB;
        int b1 = (row0 + 127) / BFB;
        for (int i = tid; i < 128; i += 256) {
            was_s[i]       = wasp[n0c + i];
            hb_s[i]        = g_hb[b0 * H_ + n0c + i];
            hb_s[128 + i]  = g_hb[b1 * H_ + n0c + i];
        }
    }

    const int ldr = tid >> 3;            // base row (+32 per iter)
    const int ldq = tid & 7;             // 16B chunk within 128B row

    const int sub = lane >> 3, lr = lane & 7;
    const int a_row = wm * 32 + ((sub & 1) << 3) + lr;
    const int a_cb  = (sub >> 1) << 4;
    const int b_row = wn * 64 + ((sub >> 1) << 3) + lr;
    const int b_cb  = (sub & 1) << 4;
    const uint32_t amask = (uint32_t)((a_row & 7) << 4);
    const uint32_t bmask = (uint32_t)((b_row & 7) << 4);

    float acc[2][8][4];
    #pragma unroll
    for (int i = 0; i < 2; i++)
        #pragma unroll
        for (int j = 0; j < 8; j++)
            #pragma unroll
            for (int v = 0; v < 4; v++) acc[i][j][v] = 0.f;

    auto load_chunk = [&](int c) {
        const long kin = (long)c * 64;
        uint32_t abase = sb + (uint32_t)(c % 3) * STAGE_B;
        uint32_t bbase = abase + 16384;
        #pragma unroll
        for (int it = 0; it < 4; it++) {
            int r = ldr + it * 32;
            uint32_t off = (uint32_t)(r * 128 + ldq * 16) ^ ((uint32_t)(r & 7) << 4);
            CP_ASYNC16(abase + off, Ah + (long)(row0 + r) * KD + kin + ldq * 8);
            CP_ASYNC16(bbase + off, Bh + (long)(n0c + r) * KD + kin + ldq * 8);
        }
        CP_COMMIT();
    };

    auto compute_chunk = [&](int c) {
        uint32_t abase = sb + (uint32_t)(c % 3) * STAGE_B;
        uint32_t bbase = abase + 16384;
        #pragma unroll
        for (int ks = 0; ks < 4; ks++) {
            const uint32_t kb = (uint32_t)(ks * 32);
            uint32_t af[2][4], bfr[4][4];
            #pragma unroll
            for (int i = 0; i < 2; i++)
                ldsm4(af[i], abase + (uint32_t)((a_row + i * 16) * 128)
                                   + (((uint32_t)a_cb + kb) ^ amask));
            #pragma unroll
            for (int j2 = 0; j2 < 4; j2++)
                ldsm4(bfr[j2], bbase + (uint32_t)((b_row + j2 * 16) * 128)
                                     + (((uint32_t)b_cb + kb) ^ bmask));
            #pragma unroll
            for (int i = 0; i < 2; i++)
                #pragma unroll
                for (int j = 0; j < 8; j++)
                    mma16816(acc[i][j], af[i], &bfr[j >> 1][(j & 1) * 2]);
        }
    };

    // 3-stage pipeline, one sync per chunk. load(c+2) at iter c overwrites the
    // buffer computed at iter c-1; the sync at iter-c top orders that.
    load_chunk(0);
    load_chunk(1);
    for (int c = 0; c < NC; c++) {
        if (c < NC - 1) CP_WAIT(1); else CP_WAIT(0);
        __syncthreads();
        compute_chunk(c);
        if (c + 2 < NC) load_chunk(c + 2);
    }

    const int g = lane >> 2, t = lane & 3;
    if (MODE == 1) {
        #pragma unroll
        for (int i = 0; i < 2; i++) {
            int rl = wm * 32 + i * 16 + g;
            int rh = rl + 8;
            const float* hbl = hb_s + (((row0 + rl) / BFB) == b0 ? 0 : 128);
            const float* hbh = hb_s + (((row0 + rh) / BFB) == b0 ? 0 : 128);
            float pl = 0.f, ph = 0.f;
            #pragma unroll
            for (int j = 0; j < 8; j++) {
                int nl = wn * 64 + j * 8 + 2 * t;
                float w0 = was_s[nl], w1 = was_s[nl + 1];
                pl += w0 * tanha(acc[i][j][0] + hbl[nl])
                    + w1 * tanha(acc[i][j][1] + hbl[nl + 1]);
                ph += w0 * tanha(acc[i][j][2] + hbh[nl])
                    + w1 * tanha(acc[i][j][3] + hbh[nl + 1]);
            }
            pl += __shfl_xor_sync(0xffffffffu, pl, 1);
            pl += __shfl_xor_sync(0xffffffffu, pl, 2);
            ph += __shfl_xor_sync(0xffffffffu, ph, 1);
            ph += __shfl_xor_sync(0xffffffffu, ph, 2);
            if (t == 0) {
                atomicAdd(&g_e1[row0 + rl], pl);
                atomicAdd(&g_e1[row0 + rh], ph);
            }
        }
    } else {
        #pragma unroll
        for (int i = 0; i < 2; i++) {
            int rl = row0 + wm * 32 + i * 16 + g;
            #pragma unroll
            for (int j = 0; j < 8; j++) {
                int nc = n0c + wn * 64 + j * 8 + 2 * t;
                *reinterpret_cast<float2*>(&g_p[(long)rl * PM + nc])
                    = make_float2(acc[i][j][0], acc[i][j][1]);
                *reinterpret_cast<float2*>(&g_p[(long)(rl + 8) * PM + nc])
                    = make_float2(acc[i][j][2], acc[i][j][3]);
            }
        }
    }
}

// ============================================================================
// K3: softmax over NB + attention + concat + fp16 convert of feat
// ============================================================================
__global__ __launch_bounds__(256) void k3_soft(const float* __restrict__ obj,
                                               const float* __restrict__ i3d)
{
    __shared__ float e_s[NB_], alpha[NB_];
    int bf = blockIdx.x, tid = threadIdx.x;
    const float* fbase = obj + (long)bf * NB_ * R_;
    if (tid < NB_) e_s[tid] = g_e1[bf * NB_ + tid];
    __syncthreads();
    if (tid == 0) {
        float m = -1e30f;
        for (int l = 0; l < NB_; l++) m = fmaxf(m, e_s[l]);
        float s = 0.f, tmp[NB_];
        for (int l = 0; l < NB_; l++) { tmp[l] = expf(e_s[l] - m); s += tmp[l]; }
        float inv = 1.f / s;
        for (int l = 0; l < NB_; l++) alpha[l] = tmp[l] * inv;
    }
    __syncthreads();
    float* fout = g_feat + (long)bf * D_;
    __half* fh = g_Fh + (long)bf * D_;
    for (int d = tid; d < R_; d += 256) {
        float s = 0.f;
        #pragma unroll 4
        for (int l = 0; l < NB_; l++) s = fmaf(alpha[l], fbase[l * R_ + d], s);
        fout[d] = s;
        fh[d] = __float2half_rn(s);
    }
    for (int d = tid; d < 2 * H_; d += 256) {
        float v = i3d[(long)bf * (2 * H_) + d];
        fout[R_ + d] = v;
        fh[R_ + d] = __float2half_rn(v);
    }
}

// ============================================================================
// K5: e2[b,i,j] = war . tanh(p2[b,i] + p1[b,j] + hp2[b])
// ============================================================================
__global__ __launch_bounds__(256) void k5_e2(const float* __restrict__ war)
{
    __shared__ float base[H_];
    __shared__ float warr[H_];
    int bi = blockIdx.x;
    int b = bi / F_;
    int tid = threadIdx.x, warp = tid >> 5, lane = tid & 31;
    for (int h = tid; h < H_; h += 256) {
        base[h] = g_p[(long)bi * PM + H_ + h] + g_hp2[b * H_ + h];
        warr[h] = war[h];
    }
    __syncthreads();
    for (int jj = 0; jj < 5; jj++) {
        int j = warp + jj * 8;
        const float* p1 = g_p + (long)(b * F_ + j) * PM;
        float part = 0.f;
        #pragma unroll 4
        for (int kk = 0; kk < 16; kk++) {
            int h = lane + kk * 32;
            part += warr[h] * tanha(base[h] + p1[h]);
        }
        #pragma unroll
        for (int off = 16; off; off >>= 1)
            part += __shfl_xor_sync(0xffffffffu, part, off);
        if (lane == 0) g_e2[(long)b * (F_ * F_) + (bi % F_) * F_ + j] = part;
    }
}

// ============================================================================
// K6: per-batch softmax over F*F, marginals, final weighted sums. grid (32,3).
// ============================================================================
__global__ __launch_bounds__(256) void k6_final(float* __restrict__ out)
{
    __shared__ float ex[F_ * F_];
    __shared__ float red[256];
    __shared__ float rowsum[F_], colsum[F_];
    int b = blockIdx.x, tid = threadIdx.x;
    const float* e = g_e2 + b * (F_ * F_);

    float m = -1e30f;
    for (int t = tid; t < F_ * F_; t += 256) m = fmaxf(m, e[t]);
    red[tid] = m; __syncthreads();
    for (int s = 128; s > 0; s >>= 1) {
        if (tid < s) red[tid] = fmaxf(red[tid], red[tid + s]);
        __syncthreads();
    }
    m = red[0]; __syncthreads();

    float sum = 0.f;
    for (int t = tid; t < F_ * F_; t += 256) { float v = expf(e[t] - m); ex[t] = v; sum += v; }
    red[tid] = sum; __syncthreads();
    for (int s = 128; s > 0; s >>= 1) {
        if (tid < s) red[tid] += red[tid + s];
        __syncthreads();
    }
    float inv = 1.f / red[0];

    if (tid < F_) { rowsum[tid] = 0.f; colsum[tid] = 0.f; }
    __syncthreads();
    for (int t = tid; t < F_ * F_; t += 256) {
        float a = ex[t] * inv;
        atomicAdd(&rowsum[t / F_], a);
        atomicAdd(&colsum[t % F_], a);
    }
    __syncthreads();

    int c0 = blockIdx.y * 512;
    for (int d = c0 + tid; d < c0 + 512; d += 256) {
        float r1 = 0.f, r2 = 0.f;
        #pragma unroll 8
        for (int q = 0; q < F_; q++) {
            float fv = g_feat[(long)(b * F_ + q) * D_ + d];
            r1 = fmaf(colsum[q], fv, r1);
            r2 = fmaf(rowsum[q], fv, r2);
        }
        out[b * (2 * D_) + d]      = r1;
        out[b * (2 * D_) + D_ + d] = r2;
    }
}

// ============================================================================
extern "C" void kernel_launch(void* const* d_in, const int* in_sizes, int n_in,
                              void* d_out, int out_size)
{
    const float* i3d    = (const float*)d_in[0];
    const float* obj    = (const float*)d_in[1];
    const float* hidden = (const float*)d_in[2];
    const float* Wsf    = (const float*)d_in[3];
    const float* bsf    = (const float*)d_in[4];
    const float* Wsh    = (const float*)d_in[5];
    const float* bsh    = (const float*)d_in[6];
    const float* was    = (const float*)d_in[7];
    const float* Wrf    = (const float*)d_in[8];
    const float* brf    = (const float*)d_in[9];
    const float* Wrh    = (const float*)d_in[10];
    const float* brh    = (const float*)d_in[11];
    const float* war    = (const float*)d_in[12];
    float* out = (float*)d_out;

    cudaFuncSetAttribute(kmma<512, 8, 1>,   cudaFuncAttributeMaxDynamicSharedMemorySize, SMEM_TOT);
    cudaFuncSetAttribute(kmma<1536, 24, 2>, cudaFuncAttributeMaxDynamicSharedMemorySize, SMEM_TOT);

    k0_hproj  <<<dim3(B_, 16), 256>>>(hidden, Wsh, bsh, bsf, Wrh, brh, brf);
    k1_splitA <<<23040, 256>>>(obj);
    k1_splitB <<<1792,  256>>>(Wsf, Wrf);
    kmma<512, 8, 1>   <<<dim3(M1 / 128, 4),  256, SMEM_TOT>>>(was);     // 4th launch -> profiled
    k3_soft   <<<NBF, 256>>>(obj, i3d);
    kmma<1536, 24, 2> <<<dim3(NBF / 128, 8), 256, SMEM_TOT>>>(nullptr);
    k5_e2     <<<NBF, 256>>>(war);
    k6_final  <<<dim3(B_, 3), 256>>>(out);
}

// round 11
// speedup vs baseline: 5.4840x; 1.0267x over previous
#include <cuda_runtime.h>
#include <cuda_fp16.h>
#include <math.h>
#include <stdint.h>

#define B_   32
#define F_   40
#define NB_  36
#define R_   512
#define H_   512
#define D_   1536
#define NBF  1280
#define PM   1024
#define M1   46080
#define BFB  1440      // F_*NB_ rows per batch in stage-1

// ---------------- device scratch (static, no allocation) ----------------
__device__ __align__(16) float g_hb [B_*H_];
__device__ __align__(16) float g_hp2[B_*H_];
__device__ __align__(16) float g_e1 [M1];
__device__ __align__(16) float g_feat[(long)NBF*D_];
__device__ __align__(16) float g_p  [(long)NBF*PM];
__device__ __align__(16) float g_e2 [B_*F_*F_];
__device__ __align__(16) __half g_Ah [(long)M1*R_];
__device__ __align__(16) __half g_B1h[H_*R_];
__device__ __align__(16) __half g_Fh [(long)NBF*D_];
__device__ __align__(16) __half g_B2h[(long)PM*D_];

// ---------------- portable (non-'a') PTX helpers ----------------
__device__ __forceinline__ uint32_t smem_u32(const void* p){
    uint32_t a;
    asm("{ .reg .u64 t; cvta.to.shared.u64 t, %1; cvt.u32.u64 %0, t; }" : "=r"(a) : "l"(p));
    return a;
}
__device__ __forceinline__ float tanha(float x){
    float y;
    asm("tanh.approx.f32 %0, %1;" : "=f"(y) : "f"(x));
    return y;
}
#define CP_ASYNC16(dst, src) \
    asm volatile("cp.async.cg.shared.global [%0], [%1], 16;" :: "r"(dst), "l"(src) : "memory")
#define CP_COMMIT() asm volatile("cp.async.commit_group;" ::: "memory")
#define CP_WAIT(n)  asm volatile("cp.async.wait_group %0;" :: "n"(n) : "memory")

__device__ __forceinline__ void ldsm4(uint32_t* r, uint32_t addr){
    asm volatile("ldmatrix.sync.aligned.m8n8.x4.shared.b16 {%0,%1,%2,%3}, [%4];"
        : "=r"(r[0]), "=r"(r[1]), "=r"(r[2]), "=r"(r[3]) : "r"(addr));
}
__device__ __forceinline__ void mma16816(float* c, const uint32_t* a, const uint32_t* b){
    asm volatile("mma.sync.aligned.m16n8k16.row.col.f32.f16.f16.f32 "
        "{%0,%1,%2,%3}, {%4,%5,%6,%7}, {%8,%9}, {%0,%1,%2,%3};"
        : "+f"(c[0]), "+f"(c[1]), "+f"(c[2]), "+f"(c[3])
        : "r"(a[0]), "r"(a[1]), "r"(a[2]), "r"(a[3]), "r"(b[0]), "r"(b[1]));
}

__device__ __forceinline__ void hi4_store(float4 v, __half* hi, size_t qi){
    __half2 h01 = __floats2half2_rn(v.x, v.y);
    __half2 h23 = __floats2half2_rn(v.z, v.w);
    reinterpret_cast<uint2*>(hi)[qi] = make_uint2(*(uint32_t*)&h01, *(uint32_t*)&h23);
}

// ============================================================================
// KPREP: one launch doing (a) hidden projections, (b) obj->fp16, (c) weight
// fp16 conversions + e1 zeroing. Branch is block-uniform.
// blocks [0,512): k0;  [512,23552): splitA;  [23552,25344): splitB+zero.
// ============================================================================
__global__ __launch_bounds__(256) void kprep(
    const float* __restrict__ hidden, const float* __restrict__ Wsh,
    const float* __restrict__ bsh,    const float* __restrict__ bsf,
    const float* __restrict__ Wrh,    const float* __restrict__ brh,
    const float* __restrict__ brf,    const float* __restrict__ obj,
    const float* __restrict__ Wsf,    const float* __restrict__ Wrf)
{
    int blk = blockIdx.x, tid = threadIdx.x;
    if (blk < 512) {
        __shared__ float hs[H_];
        int b = blk >> 4;
        int h = (blk & 15) * 32 + (tid >> 3);
        int ks = tid & 7;
        for (int i = tid; i < H_; i += 256) hs[i] = hidden[b * H_ + i];
        __syncthreads();
        const float4* w1 = reinterpret_cast<const float4*>(Wsh + (long)h * H_) + ks * 16;
        const float4* w2 = reinterpret_cast<const float4*>(Wrh + (long)h * H_) + ks * 16;
        const float*  hk = hs + ks * 64;
        float a1 = 0.f, a2 = 0.f;
        #pragma unroll
        for (int k4 = 0; k4 < 16; k4++) {
            float4 v1 = w1[k4], v2 = w2[k4];
            float h0 = hk[k4*4+0], h1 = hk[k4*4+1], h2 = hk[k4*4+2], h3 = hk[k4*4+3];
            a1 = fmaf(h0, v1.x, a1); a1 = fmaf(h1, v1.y, a1);
            a1 = fmaf(h2, v1.z, a1); a1 = fmaf(h3, v1.w, a1);
            a2 = fmaf(h0, v2.x, a2); a2 = fmaf(h1, v2.y, a2);
            a2 = fmaf(h2, v2.z, a2); a2 = fmaf(h3, v2.w, a2);
        }
        #pragma unroll
        for (int off = 4; off; off >>= 1) {
            a1 += __shfl_xor_sync(0xffffffffu, a1, off);
            a2 += __shfl_xor_sync(0xffffffffu, a2, off);
        }
        if (ks == 0) {
            g_hb [b * H_ + h] = a1 + bsh[h] + bsf[h];
            g_hp2[b * H_ + h] = a2 + brh[h] + brf[h];
        }
    } else if (blk < 23552) {
        size_t i = (size_t)(blk - 512) * 256 + tid;
        float4 v = reinterpret_cast<const float4*>(obj)[i];
        hi4_store(v, g_Ah, i);
    } else {
        size_t q = (size_t)(blk - 23552) * 256 + tid;
        if (q < M1) g_e1[q] = 0.f;
        if (q < 65536) {                                 // B1: Wsf 512x512
            float4 v = reinterpret_cast<const float4*>(Wsf)[q];
            hi4_store(v, g_B1h, q);
        } else {                                         // B2: rearranged Wrf -> 1024x1536
            size_t j = q - 65536;
            int m = (int)(j / 384), c4 = (int)(j % 384);
            const float* row = Wrf + (long)(m & 511) * (2 * D_) + (m >> 9) * D_;
            float4 v = reinterpret_cast<const float4*>(row)[c4];
            hi4_store(v, g_B2h, (size_t)m * (D_ / 4) + c4);
        }
    }
}

// ============================================================================
// KMMA: 3-stage cp.async + ldmatrix + mma.sync fp16 GEMM, single pass, one
// __syncthreads per K-chunk. CTA tile 128 x NT, 8 warps of 32 x NT/2, Kc=64,
// SW128 swizzle. MODE 1 (NT=256): tanh.approx reduce -> atomicAdd g_e1.
// MODE 2 (NT=128): stores into g_p.
// ============================================================================
template<int NT> struct KCfg {
    static constexpr int STAGE = 16384 + NT * 128;
    static constexpr int SBUF  = 3 * STAGE;
    static constexpr int TOT   = SBUF + NT * 4 + 2 * NT * 4;
};

template<int KD, int NC, int MODE, int NT>
__global__ __launch_bounds__(256, (MODE == 1) ? 1 : 2)
void kmma(const float* __restrict__ wasp)
{
    constexpr int STAGE = KCfg<NT>::STAGE;
    constexpr int SBUF  = KCfg<NT>::SBUF;
    constexpr int NW    = NT / 2;        // cols per warp
    extern __shared__ char smem[];
    const uint32_t sb = smem_u32(smem);
    const int tid  = threadIdx.x, lane = tid & 31, wid = tid >> 5;
    const int wm   = wid & 3, wn = wid >> 2;
    const int row0 = blockIdx.x * 128;
    const int n0c  = blockIdx.y * NT;

    const __half *Ah, *Bh;
    if (MODE == 1) { Ah = g_Ah; Bh = g_B1h; }
    else           { Ah = g_Fh; Bh = g_B2h; }

    float* was_s = (float*)(smem + SBUF);
    float* hb_s  = (float*)(smem + SBUF + NT * 4);
    int b0 = 0;
    if (MODE == 1) {
        b0 = row0 / BFB;
        int b1 = (row0 + 127) / BFB;
        for (int i = tid; i < NT; i += 256) {
            was_s[i]      = wasp[n0c + i];
            hb_s[i]       = g_hb[b0 * H_ + n0c + i];
            hb_s[NT + i]  = g_hb[b1 * H_ + n0c + i];
        }
    }

    const int ldr = tid >> 3;            // base row (+32 per iter)
    const int ldq = tid & 7;             // 16B chunk within 128B row

    const int sub = lane >> 3, lr = lane & 7;
    const int a_row = wm * 32 + ((sub & 1) << 3) + lr;
    const int a_cb  = (sub >> 1) << 4;
    const int b_row = wn * NW + ((sub >> 1) << 3) + lr;
    const int b_cb  = (sub & 1) << 4;
    const uint32_t amask = (uint32_t)((a_row & 7) << 4);
    const uint32_t bmask = (uint32_t)((b_row & 7) << 4);

    float acc[2][NW / 8][4];
    #pragma unroll
    for (int i = 0; i < 2; i++)
        #pragma unroll
        for (int j = 0; j < NW / 8; j++)
            #pragma unroll
            for (int v = 0; v < 4; v++) acc[i][j][v] = 0.f;

    auto load_chunk = [&](int c) {
        const long kin = (long)c * 64;
        uint32_t abase = sb + (uint32_t)(c % 3) * STAGE;
        uint32_t bbase = abase + 16384;
        #pragma unroll
        for (int it = 0; it < 4; it++) {
            int r = ldr + it * 32;
            uint32_t off = (uint32_t)(r * 128 + ldq * 16) ^ ((uint32_t)(r & 7) << 4);
            CP_ASYNC16(abase + off, Ah + (long)(row0 + r) * KD + kin + ldq * 8);
        }
        #pragma unroll
        for (int it = 0; it < NT / 32; it++) {
            int r = ldr + it * 32;
            uint32_t off = (uint32_t)(r * 128 + ldq * 16) ^ ((uint32_t)(r & 7) << 4);
            CP_ASYNC16(bbase + off, Bh + (long)(n0c + r) * KD + kin + ldq * 8);
        }
        CP_COMMIT();
    };

    auto compute_chunk = [&](int c) {
        uint32_t abase = sb + (uint32_t)(c % 3) * STAGE;
        uint32_t bbase = abase + 16384;
        #pragma unroll
        for (int ks = 0; ks < 4; ks++) {
            const uint32_t kb = (uint32_t)(ks * 32);
            uint32_t af[2][4], bfr[NW / 16][4];
            #pragma unroll
            for (int i = 0; i < 2; i++)
                ldsm4(af[i], abase + (uint32_t)((a_row + i * 16) * 128)
                                   + (((uint32_t)a_cb + kb) ^ amask));
            #pragma unroll
            for (int j2 = 0; j2 < NW / 16; j2++)
                ldsm4(bfr[j2], bbase + (uint32_t)((b_row + j2 * 16) * 128)
                                     + (((uint32_t)b_cb + kb) ^ bmask));
            #pragma unroll
            for (int i = 0; i < 2; i++)
                #pragma unroll
                for (int j = 0; j < NW / 8; j++)
                    mma16816(acc[i][j], af[i], &bfr[j >> 1][(j & 1) * 2]);
        }
    };

    load_chunk(0);
    load_chunk(1);
    for (int c = 0; c < NC; c++) {
        if (c < NC - 1) CP_WAIT(1); else CP_WAIT(0);
        __syncthreads();
        compute_chunk(c);
        if (c + 2 < NC) load_chunk(c + 2);
    }

    const int g = lane >> 2, t = lane & 3;
    if (MODE == 1) {
        #pragma unroll
        for (int i = 0; i < 2; i++) {
            int rl = wm * 32 + i * 16 + g;
            int rh = rl + 8;
            const float* hbl = hb_s + (((row0 + rl) / BFB) == b0 ? 0 : NT);
            const float* hbh = hb_s + (((row0 + rh) / BFB) == b0 ? 0 : NT);
            float pl = 0.f, ph = 0.f;
            #pragma unroll
            for (int j = 0; j < NW / 8; j++) {
                int nl = wn * NW + j * 8 + 2 * t;
                float w0 = was_s[nl], w1 = was_s[nl + 1];
                pl += w0 * tanha(acc[i][j][0] + hbl[nl])
                    + w1 * tanha(acc[i][j][1] + hbl[nl + 1]);
                ph += w0 * tanha(acc[i][j][2] + hbh[nl])
                    + w1 * tanha(acc[i][j][3] + hbh[nl + 1]);
            }
            pl += __shfl_xor_sync(0xffffffffu, pl, 1);
            pl += __shfl_xor_sync(0xffffffffu, pl, 2);
            ph += __shfl_xor_sync(0xffffffffu, ph, 1);
            ph += __shfl_xor_sync(0xffffffffu, ph, 2);
            if (t == 0) {
                atomicAdd(&g_e1[row0 + rl], pl);
                atomicAdd(&g_e1[row0 + rh], ph);
            }
        }
    } else {
        #pragma unroll
        for (int i = 0; i < 2; i++) {
            int rl = row0 + wm * 32 + i * 16 + g;
            #pragma unroll
            for (int j = 0; j < NW / 8; j++) {
                int nc = n0c + wn * NW + j * 8 + 2 * t;
                *reinterpret_cast<float2*>(&g_p[(long)rl * PM + nc])
                    = make_float2(acc[i][j][0], acc[i][j][1]);
                *reinterpret_cast<float2*>(&g_p[(long)(rl + 8) * PM + nc])
                    = make_float2(acc[i][j][2], acc[i][j][3]);
            }
        }
    }
}

// ============================================================================
// K3: softmax over NB + attention (from fp16 A) + concat + fp16 feat
// ============================================================================
__global__ __launch_bounds__(256) void k3_soft(const float* __restrict__ i3d)
{
    __shared__ float e_s[NB_], alpha[NB_];
    int bf = blockIdx.x, tid = threadIdx.x;
    const __half* fb = g_Ah + (long)bf * NB_ * R_;
    if (tid < NB_) e_s[tid] = g_e1[bf * NB_ + tid];
    __syncthreads();
    if (tid == 0) {
        float m = -1e30f;
        for (int l = 0; l < NB_; l++) m = fmaxf(m, e_s[l]);
        float s = 0.f, tmp[NB_];
        for (int l = 0; l < NB_; l++) { tmp[l] = expf(e_s[l] - m); s += tmp[l]; }
        float inv = 1.f / s;
        for (int l = 0; l < NB_; l++) alpha[l] = tmp[l] * inv;
    }
    __syncthreads();
    float* fout = g_feat + (long)bf * D_;
    __half* fh = g_Fh + (long)bf * D_;
    for (int d = tid; d < R_; d += 256) {
        float s = 0.f;
        #pragma unroll 4
        for (int l = 0; l < NB_; l++)
            s = fmaf(alpha[l], __half2float(fb[l * R_ + d]), s);
        fout[d] = s;
        fh[d] = __float2half_rn(s);
    }
    for (int d = tid; d < 2 * H_; d += 256) {
        float v = i3d[(long)bf * (2 * H_) + d];
        fout[R_ + d] = v;
        fh[R_ + d] = __float2half_rn(v);
    }
}

// ============================================================================
// K5: e2[b,i,j] = war . tanh(p2[b,i] + p1[b,j] + hp2[b]). grid (32,5): block
// caches 8 base rows in smem; each warp reuses one p1 row across all 8 i's.
// ============================================================================
__global__ __launch_bounds__(256) void k5_e2(const float* __restrict__ war)
{
    __shared__ float base[8][H_];
    __shared__ float warr[H_];
    int b = blockIdx.x, i0 = blockIdx.y * 8;
    int tid = threadIdx.x, warp = tid >> 5, lane = tid & 31;
    for (int h = tid; h < H_; h += 256) warr[h] = war[h];
    for (int idx = tid; idx < 8 * H_; idx += 256) {
        int ii = idx >> 9, h = idx & (H_ - 1);
        base[ii][h] = g_p[(long)(b * F_ + i0 + ii) * PM + H_ + h] + g_hp2[b * H_ + h];
    }
    __syncthreads();
    for (int jj = 0; jj < 5; jj++) {
        int j = jj * 8 + warp;
        const float* p1 = g_p + (long)(b * F_ + j) * PM;
        float p1v[16];
        #pragma unroll
        for (int kk = 0; kk < 16; kk++) p1v[kk] = p1[lane + kk * 32];
        #pragma unroll
        for (int ii = 0; ii < 8; ii++) {
            float part = 0.f;
            #pragma unroll
            for (int kk = 0; kk < 16; kk++) {
                int h = lane + kk * 32;
                part += warr[h] * tanha(base[ii][h] + p1v[kk]);
            }
            #pragma unroll
            for (int off = 16; off; off >>= 1)
                part += __shfl_xor_sync(0xffffffffu, part, off);
            if (lane == 0) g_e2[(long)b * (F_ * F_) + (i0 + ii) * F_ + j] = part;
        }
    }
}

// ============================================================================
// K6: per-batch softmax over F*F, marginals, final weighted sums. grid (32,3).
// ============================================================================
__global__ __launch_bounds__(256) void k6_final(float* __restrict__ out)
{
    __shared__ float ex[F_ * F_];
    __shared__ float red[256];
    __shared__ float rowsum[F_], colsum[F_];
    int b = blockIdx.x, tid = threadIdx.x;
    const float* e = g_e2 + b * (F_ * F_);

    float m = -1e30f;
    for (int t = tid; t < F_ * F_; t += 256) m = fmaxf(m, e[t]);
    red[tid] = m; __syncthreads();
    for (int s = 128; s > 0; s >>= 1) {
        if (tid < s) red[tid] = fmaxf(red[tid], red[tid + s]);
        __syncthreads();
    }
    m = red[0]; __syncthreads();

    float sum = 0.f;
    for (int t = tid; t < F_ * F_; t += 256) { float v = expf(e[t] - m); ex[t] = v; sum += v; }
    red[tid] = sum; __syncthreads();
    for (int s = 128; s > 0; s >>= 1) {
        if (tid < s) red[tid] += red[tid + s];
        __syncthreads();
    }
    float inv = 1.f / red[0];

    if (tid < F_) { rowsum[tid] = 0.f; colsum[tid] = 0.f; }
    __syncthreads();
    for (int t = tid; t < F_ * F_; t += 256) {
        float a = ex[t] * inv;
        atomicAdd(&rowsum[t / F_], a);
        atomicAdd(&colsum[t % F_], a);
    }
    __syncthreads();

    int c0 = blockIdx.y * 512;
    for (int d = c0 + tid; d < c0 + 512; d += 256) {
        float r1 = 0.f, r2 = 0.f;
        #pragma unroll 8
        for (int q = 0; q < F_; q++) {
            float fv = g_feat[(long)(b * F_ + q) * D_ + d];
            r1 = fmaf(colsum[q], fv, r1);
            r2 = fmaf(rowsum[q], fv, r2);
        }
        out[b * (2 * D_) + d]      = r1;
        out[b * (2 * D_) + D_ + d] = r2;
    }
}

// ============================================================================
extern "C" void kernel_launch(void* const* d_in, const int* in_sizes, int n_in,
                              void* d_out, int out_size)
{
    const float* i3d    = (const float*)d_in[0];
    const float* obj    = (const float*)d_in[1];
    const float* hidden = (const float*)d_in[2];
    const float* Wsf    = (const float*)d_in[3];
    const float* bsf    = (const float*)d_in[4];
    const float* Wsh    = (const float*)d_in[5];
    const float* bsh    = (const float*)d_in[6];
    const float* was    = (const float*)d_in[7];
    const float* Wrf    = (const float*)d_in[8];
    const float* brf    = (const float*)d_in[9];
    const float* Wrh    = (const float*)d_in[10];
    const float* brh    = (const float*)d_in[11];
    const float* war    = (const float*)d_in[12];
    float* out = (float*)d_out;

    cudaFuncSetAttribute(kmma<512, 8, 1, 256>,
        cudaFuncAttributeMaxDynamicSharedMemorySize, KCfg<256>::TOT);
    cudaFuncSetAttribute(kmma<1536, 24, 2, 128>,
        cudaFuncAttributeMaxDynamicSharedMemorySize, KCfg<128>::TOT);

    kprep <<<25344, 256>>>(hidden, Wsh, bsh, bsf, Wrh, brh, brf, obj, Wsf, Wrf);
    kmma<512, 8, 1, 256>  <<<dim3(M1 / 128, 2), 256, KCfg<256>::TOT>>>(was);
    k3_soft <<<NBF, 256>>>(i3d);
    kmma<1536, 24, 2, 128><<<dim3(NBF / 128, 8), 256, KCfg<128>::TOT>>>(nullptr); // 4th -> profiled
    k5_e2   <<<dim3(B_, 5), 256>>>(war);
    k6_final<<<dim3(B_, 3), 256>>>(out);
}

// round 12
// speedup vs baseline: 5.5074x; 1.0043x over previous
#include <cuda_runtime.h>
#include <cuda_fp16.h>
#include <math.h>
#include <stdint.h>

#define B_   32
#define F_   40
#define NB_  36
#define R_   512
#define H_   512
#define D_   1536
#define NBF  1280
#define PM   1024
#define M1   46080
#define BFB  1440      // F_*NB_ rows per batch in stage-1

// ---------------- device scratch (static, no allocation) ----------------
__device__ __align__(16) float g_hb [B_*H_];
__device__ __align__(16) float g_hp2[B_*H_];
__device__ __align__(16) float g_e1 [M1];
__device__ __align__(16) float g_feat[(long)NBF*D_];
__device__ __align__(16) float g_p  [(long)NBF*PM];
__device__ __align__(16) float g_e2 [B_*F_*F_];
__device__ __align__(16) __half g_Ah [(long)M1*R_];
__device__ __align__(16) __half g_B1h[H_*R_];
__device__ __align__(16) __half g_Fh [(long)NBF*D_];
__device__ __align__(16) __half g_B2h[(long)PM*D_];

// ---------------- portable (non-'a') PTX helpers ----------------
__device__ __forceinline__ uint32_t smem_u32(const void* p){
    uint32_t a;
    asm("{ .reg .u64 t; cvta.to.shared.u64 t, %1; cvt.u32.u64 %0, t; }" : "=r"(a) : "l"(p));
    return a;
}
__device__ __forceinline__ float tanha(float x){
    float y;
    asm("tanh.approx.f32 %0, %1;" : "=f"(y) : "f"(x));
    return y;
}
#define CP_ASYNC16(dst, src) \
    asm volatile("cp.async.cg.shared.global [%0], [%1], 16;" :: "r"(dst), "l"(src) : "memory")
#define CP_COMMIT() asm volatile("cp.async.commit_group;" ::: "memory")
#define CP_WAIT(n)  asm volatile("cp.async.wait_group %0;" :: "n"(n) : "memory")

__device__ __forceinline__ void ldsm4(uint32_t* r, uint32_t addr){
    asm volatile("ldmatrix.sync.aligned.m8n8.x4.shared.b16 {%0,%1,%2,%3}, [%4];"
        : "=r"(r[0]), "=r"(r[1]), "=r"(r[2]), "=r"(r[3]) : "r"(addr));
}
__device__ __forceinline__ void mma16816(float* c, const uint32_t* a, const uint32_t* b){
    asm volatile("mma.sync.aligned.m16n8k16.row.col.f32.f16.f16.f32 "
        "{%0,%1,%2,%3}, {%4,%5,%6,%7}, {%8,%9}, {%0,%1,%2,%3};"
        : "+f"(c[0]), "+f"(c[1]), "+f"(c[2]), "+f"(c[3])
        : "r"(a[0]), "r"(a[1]), "r"(a[2]), "r"(a[3]), "r"(b[0]), "r"(b[1]));
}

__device__ __forceinline__ void hi4_store(float4 v, __half* hi, size_t qi){
    __half2 h01 = __floats2half2_rn(v.x, v.y);
    __half2 h23 = __floats2half2_rn(v.z, v.w);
    reinterpret_cast<uint2*>(hi)[qi] = make_uint2(*(uint32_t*)&h01, *(uint32_t*)&h23);
}

// ============================================================================
// KPREP: one launch: (a) hidden projections, (b) obj->fp16, (c) weights->fp16
// + e1 zeroing. Branch is block-uniform.
// ============================================================================
__global__ __launch_bounds__(256) void kprep(
    const float* __restrict__ hidden, const float* __restrict__ Wsh,
    const float* __restrict__ bsh,    const float* __restrict__ bsf,
    const float* __restrict__ Wrh,    const float* __restrict__ brh,
    const float* __restrict__ brf,    const float* __restrict__ obj,
    const float* __restrict__ Wsf,    const float* __restrict__ Wrf)
{
    int blk = blockIdx.x, tid = threadIdx.x;
    if (blk < 512) {
        __shared__ float hs[H_];
        int b = blk >> 4;
        int h = (blk & 15) * 32 + (tid >> 3);
        int ks = tid & 7;
        for (int i = tid; i < H_; i += 256) hs[i] = hidden[b * H_ + i];
        __syncthreads();
        const float4* w1 = reinterpret_cast<const float4*>(Wsh + (long)h * H_) + ks * 16;
        const float4* w2 = reinterpret_cast<const float4*>(Wrh + (long)h * H_) + ks * 16;
        const float*  hk = hs + ks * 64;
        float a1 = 0.f, a2 = 0.f;
        #pragma unroll
        for (int k4 = 0; k4 < 16; k4++) {
            float4 v1 = w1[k4], v2 = w2[k4];
            float h0 = hk[k4*4+0], h1 = hk[k4*4+1], h2 = hk[k4*4+2], h3 = hk[k4*4+3];
            a1 = fmaf(h0, v1.x, a1); a1 = fmaf(h1, v1.y, a1);
            a1 = fmaf(h2, v1.z, a1); a1 = fmaf(h3, v1.w, a1);
            a2 = fmaf(h0, v2.x, a2); a2 = fmaf(h1, v2.y, a2);
            a2 = fmaf(h2, v2.z, a2); a2 = fmaf(h3, v2.w, a2);
        }
        #pragma unroll
        for (int off = 4; off; off >>= 1) {
            a1 += __shfl_xor_sync(0xffffffffu, a1, off);
            a2 += __shfl_xor_sync(0xffffffffu, a2, off);
        }
        if (ks == 0) {
            g_hb [b * H_ + h] = a1 + bsh[h] + bsf[h];
            g_hp2[b * H_ + h] = a2 + brh[h] + brf[h];
        }
    } else if (blk < 23552) {
        size_t i = (size_t)(blk - 512) * 256 + tid;
        float4 v = reinterpret_cast<const float4*>(obj)[i];
        hi4_store(v, g_Ah, i);
    } else {
        size_t q = (size_t)(blk - 23552) * 256 + tid;
        if (q < M1) g_e1[q] = 0.f;
        if (q < 65536) {                                 // B1: Wsf 512x512
            float4 v = reinterpret_cast<const float4*>(Wsf)[q];
            hi4_store(v, g_B1h, q);
        } else {                                         // B2: rearranged Wrf -> 1024x1536
            size_t j = q - 65536;
            int m = (int)(j / 384), c4 = (int)(j % 384);
            const float* row = Wrf + (long)(m & 511) * (2 * D_) + (m >> 9) * D_;
            float4 v = reinterpret_cast<const float4*>(row)[c4];
            hi4_store(v, g_B2h, (size_t)m * (D_ / 4) + c4);
        }
    }
}

// ============================================================================
// KMMA: NST-stage cp.async + ldmatrix + mma.sync fp16 GEMM, single pass, one
// __syncthreads per K-chunk (Kc=64, SW128 swizzle). CTA tile MT x NT, 8 warps:
// wm in 0..3 covers MT rows (MI=MT/64 16-row sub-tiles each), wn in 0..1
// covers NT/2 cols each. MODE 1: tanh.approx reduce -> atomicAdd g_e1.
// MODE 2: stores into g_p.
// ============================================================================
template<int MT, int NT, int NST> struct KCfg {
    static constexpr int STAGE = (MT + NT) * 128;
    static constexpr int SBUF  = NST * STAGE;
    static constexpr int TOT   = SBUF + 3 * NT * 4;
};

template<int KD, int NC, int MODE, int MT, int NT, int NST>
__global__ __launch_bounds__(256, (MODE == 1) ? 1 : 2)
void kmma(const float* __restrict__ wasp)
{
    constexpr int STAGE = KCfg<MT, NT, NST>::STAGE;
    constexpr int SBUF  = KCfg<MT, NT, NST>::SBUF;
    constexpr int NW    = NT / 2;        // cols per warp
    constexpr int MI    = MT / 64;       // 16-row sub-tiles per warp
    extern __shared__ char smem[];
    const uint32_t sb = smem_u32(smem);
    const int tid  = threadIdx.x, lane = tid & 31, wid = tid >> 5;
    const int wm   = wid & 3, wn = wid >> 2;
    const int row0 = blockIdx.x * MT;
    const int n0c  = blockIdx.y * NT;

    const __half *Ah, *Bh;
    if (MODE == 1) { Ah = g_Ah; Bh = g_B1h; }
    else           { Ah = g_Fh; Bh = g_B2h; }

    float* was_s = (float*)(smem + SBUF);
    float* hb_s  = (float*)(smem + SBUF + NT * 4);
    int b0 = 0;
    if (MODE == 1) {
        b0 = row0 / BFB;
        int b1 = (row0 + MT - 1) / BFB;
        for (int i = tid; i < NT; i += 256) {
            was_s[i]      = wasp[n0c + i];
            hb_s[i]       = g_hb[b0 * H_ + n0c + i];
            hb_s[NT + i]  = g_hb[b1 * H_ + n0c + i];
        }
    }

    const int ldr = tid >> 3;            // base row (+32 per iter)
    const int ldq = tid & 7;             // 16B chunk within 128B row

    const int sub = lane >> 3, lr = lane & 7;
    const int a_row = wm * (16 * MI) + ((sub & 1) << 3) + lr;
    const int a_cb  = (sub >> 1) << 4;
    const int b_row = wn * NW + ((sub >> 1) << 3) + lr;
    const int b_cb  = (sub & 1) << 4;
    const uint32_t amask = (uint32_t)((a_row & 7) << 4);
    const uint32_t bmask = (uint32_t)((b_row & 7) << 4);

    float acc[MI][NW / 8][4];
    #pragma unroll
    for (int i = 0; i < MI; i++)
        #pragma unroll
        for (int j = 0; j < NW / 8; j++)
            #pragma unroll
            for (int v = 0; v < 4; v++) acc[i][j][v] = 0.f;

    auto load_chunk = [&](int c) {
        const long kin = (long)c * 64;
        uint32_t abase = sb + (uint32_t)(c % NST) * STAGE;
        uint32_t bbase = abase + MT * 128;
        #pragma unroll
        for (int it = 0; it < MT / 32; it++) {
            int r = ldr + it * 32;
            uint32_t off = (uint32_t)(r * 128 + ldq * 16) ^ ((uint32_t)(r & 7) << 4);
            CP_ASYNC16(abase + off, Ah + (long)(row0 + r) * KD + kin + ldq * 8);
        }
        #pragma unroll
        for (int it = 0; it < NT / 32; it++) {
            int r = ldr + it * 32;
            uint32_t off = (uint32_t)(r * 128 + ldq * 16) ^ ((uint32_t)(r & 7) << 4);
            CP_ASYNC16(bbase + off, Bh + (long)(n0c + r) * KD + kin + ldq * 8);
        }
        CP_COMMIT();
    };

    auto compute_chunk = [&](int c) {
        uint32_t abase = sb + (uint32_t)(c % NST) * STAGE;
        uint32_t bbase = abase + MT * 128;
        #pragma unroll
        for (int ks = 0; ks < 4; ks++) {
            const uint32_t kb = (uint32_t)(ks * 32);
            uint32_t af[MI][4], bfr[NW / 16][4];
            #pragma unroll
            for (int i = 0; i < MI; i++)
                ldsm4(af[i], abase + (uint32_t)((a_row + i * 16) * 128)
                                   + (((uint32_t)a_cb + kb) ^ amask));
            #pragma unroll
            for (int j2 = 0; j2 < NW / 16; j2++)
                ldsm4(bfr[j2], bbase + (uint32_t)((b_row + j2 * 16) * 128)
                                     + (((uint32_t)b_cb + kb) ^ bmask));
            #pragma unroll
            for (int i = 0; i < MI; i++)
                #pragma unroll
                for (int j = 0; j < NW / 8; j++)
                    mma16816(acc[i][j], af[i], &bfr[j >> 1][(j & 1) * 2]);
        }
    };

    // NST-stage pipeline, one commit per iteration (empty in tail) keeps
    // CP_WAIT(NST-2) exact: at iter c, chunks 0..c are complete.
    #pragma unroll
    for (int c = 0; c < NST - 1; c++) load_chunk(c);
    for (int c = 0; c < NC; c++) {
        CP_WAIT(NST - 2);
        __syncthreads();
        compute_chunk(c);
        if (c + NST - 1 < NC) load_chunk(c + NST - 1); else CP_COMMIT();
    }

    const int g = lane >> 2, t = lane & 3;
    if (MODE == 1) {
        #pragma unroll
        for (int i = 0; i < MI; i++) {
            int rl = wm * (16 * MI) + i * 16 + g;
            int rh = rl + 8;
            const float* hbl = hb_s + (((row0 + rl) / BFB) == b0 ? 0 : NT);
            const float* hbh = hb_s + (((row0 + rh) / BFB) == b0 ? 0 : NT);
            float pl = 0.f, ph = 0.f;
            #pragma unroll
            for (int j = 0; j < NW / 8; j++) {
                int nl = wn * NW + j * 8 + 2 * t;
                float w0 = was_s[nl], w1 = was_s[nl + 1];
                pl += w0 * tanha(acc[i][j][0] + hbl[nl])
                    + w1 * tanha(acc[i][j][1] + hbl[nl + 1]);
                ph += w0 * tanha(acc[i][j][2] + hbh[nl])
                    + w1 * tanha(acc[i][j][3] + hbh[nl + 1]);
            }
            pl += __shfl_xor_sync(0xffffffffu, pl, 1);
            pl += __shfl_xor_sync(0xffffffffu, pl, 2);
            ph += __shfl_xor_sync(0xffffffffu, ph, 1);
            ph += __shfl_xor_sync(0xffffffffu, ph, 2);
            if (t == 0) {
                atomicAdd(&g_e1[row0 + rl], pl);
                atomicAdd(&g_e1[row0 + rh], ph);
            }
        }
    } else {
        #pragma unroll
        for (int i = 0; i < MI; i++) {
            int rl = row0 + wm * (16 * MI) + i * 16 + g;
            #pragma unroll
            for (int j = 0; j < NW / 8; j++) {
                int nc = n0c + wn * NW + j * 8 + 2 * t;
                *reinterpret_cast<float2*>(&g_p[(long)rl * PM + nc])
                    = make_float2(acc[i][j][0], acc[i][j][1]);
                *reinterpret_cast<float2*>(&g_p[(long)(rl + 8) * PM + nc])
                    = make_float2(acc[i][j][2], acc[i][j][3]);
            }
        }
    }
}

// ============================================================================
// K3: softmax over NB + attention (from fp16 A) + concat + fp16 feat
// ============================================================================
__global__ __launch_bounds__(256) void k3_soft(const float* __restrict__ i3d)
{
    __shared__ float e_s[NB_], alpha[NB_];
    int bf = blockIdx.x, tid = threadIdx.x;
    const __half* fb = g_Ah + (long)bf * NB_ * R_;
    if (tid < NB_) e_s[tid] = g_e1[bf * NB_ + tid];
    __syncthreads();
    if (tid == 0) {
        float m = -1e30f;
        for (int l = 0; l < NB_; l++) m = fmaxf(m, e_s[l]);
        float s = 0.f, tmp[NB_];
        for (int l = 0; l < NB_; l++) { tmp[l] = expf(e_s[l] - m); s += tmp[l]; }
        float inv = 1.f / s;
        for (int l = 0; l < NB_; l++) alpha[l] = tmp[l] * inv;
    }
    __syncthreads();
    float* fout = g_feat + (long)bf * D_;
    __half* fh = g_Fh + (long)bf * D_;
    for (int d = tid; d < R_; d += 256) {
        float s = 0.f;
        #pragma unroll 4
        for (int l = 0; l < NB_; l++)
            s = fmaf(alpha[l], __half2float(fb[l * R_ + d]), s);
        fout[d] = s;
        fh[d] = __float2half_rn(s);
    }
    for (int d = tid; d < 2 * H_; d += 256) {
        float v = i3d[(long)bf * (2 * H_) + d];
        fout[R_ + d] = v;
        fh[R_ + d] = __float2half_rn(v);
    }
}

// ============================================================================
// K5: e2[b,i,j] = war . tanh(p2[b,i] + p1[b,j] + hp2[b]). grid (32,5)
// ============================================================================
__global__ __launch_bounds__(256) void k5_e2(const float* __restrict__ war)
{
    __shared__ float base[8][H_];
    __shared__ float warr[H_];
    int b = blockIdx.x, i0 = blockIdx.y * 8;
    int tid = threadIdx.x, warp = tid >> 5, lane = tid & 31;
    for (int h = tid; h < H_; h += 256) warr[h] = war[h];
    for (int idx = tid; idx < 8 * H_; idx += 256) {
        int ii = idx >> 9, h = idx & (H_ - 1);
        base[ii][h] = g_p[(long)(b * F_ + i0 + ii) * PM + H_ + h] + g_hp2[b * H_ + h];
    }
    __syncthreads();
    for (int jj = 0; jj < 5; jj++) {
        int j = jj * 8 + warp;
        const float* p1 = g_p + (long)(b * F_ + j) * PM;
        float p1v[16];
        #pragma unroll
        for (int kk = 0; kk < 16; kk++) p1v[kk] = p1[lane + kk * 32];
        #pragma unroll
        for (int ii = 0; ii < 8; ii++) {
            float part = 0.f;
            #pragma unroll
            for (int kk = 0; kk < 16; kk++) {
                int h = lane + kk * 32;
                part += warr[h] * tanha(base[ii][h] + p1v[kk]);
            }
            #pragma unroll
            for (int off = 16; off; off >>= 1)
                part += __shfl_xor_sync(0xffffffffu, part, off);
            if (lane == 0) g_e2[(long)b * (F_ * F_) + (i0 + ii) * F_ + j] = part;
        }
    }
}

// ============================================================================
// K6: per-batch softmax over F*F, marginals, final weighted sums. grid (32,3).
// ============================================================================
__global__ __launch_bounds__(256) void k6_final(float* __restrict__ out)
{
    __shared__ float ex[F_ * F_];
    __shared__ float red[256];
    __shared__ float rowsum[F_], colsum[F_];
    int b = blockIdx.x, tid = threadIdx.x;
    const float* e = g_e2 + b * (F_ * F_);

    float m = -1e30f;
    for (int t = tid; t < F_ * F_; t += 256) m = fmaxf(m, e[t]);
    red[tid] = m; __syncthreads();
    for (int s = 128; s > 0; s >>= 1) {
        if (tid < s) red[tid] = fmaxf(red[tid], red[tid + s]);
        __syncthreads();
    }
    m = red[0]; __syncthreads();

    float sum = 0.f;
    for (int t = tid; t < F_ * F_; t += 256) { float v = expf(e[t] - m); ex[t] = v; sum += v; }
    red[tid] = sum; __syncthreads();
    for (int s = 128; s > 0; s >>= 1) {
        if (tid < s) red[tid] += red[tid + s];
        __syncthreads();
    }
    float inv = 1.f / red[0];

    if (tid < F_) { rowsum[tid] = 0.f; colsum[tid] = 0.f; }
    __syncthreads();
    for (int t = tid; t < F_ * F_; t += 256) {
        float a = ex[t] * inv;
        atomicAdd(&rowsum[t / F_], a);
        atomicAdd(&colsum[t % F_], a);
    }
    __syncthreads();

    int c0 = blockIdx.y * 512;
    for (int d = c0 + tid; d < c0 + 512; d += 256) {
        float r1 = 0.f, r2 = 0.f;
        #pragma unroll 8
        for (int q = 0; q < F_; q++) {
            float fv = g_feat[(long)(b * F_ + q) * D_ + d];
            r1 = fmaf(colsum[q], fv, r1);
            r2 = fmaf(rowsum[q], fv, r2);
        }
        out[b * (2 * D_) + d]      = r1;
        out[b * (2 * D_) + D_ + d] = r2;
    }
}

// ============================================================================
extern "C" void kernel_launch(void* const* d_in, const int* in_sizes, int n_in,
                              void* d_out, int out_size)
{
    const float* i3d    = (const float*)d_in[0];
    const float* obj    = (const float*)d_in[1];
    const float* hidden = (const float*)d_in[2];
    const float* Wsf    = (const float*)d_in[3];
    const float* bsf    = (const float*)d_in[4];
    const float* Wsh    = (const float*)d_in[5];
    const float* bsh    = (const float*)d_in[6];
    const float* was    = (const float*)d_in[7];
    const float* Wrf    = (const float*)d_in[8];
    const float* brf    = (const float*)d_in[9];
    const float* Wrh    = (const float*)d_in[10];
    const float* brh    = (const float*)d_in[11];
    const float* war    = (const float*)d_in[12];
    float* out = (float*)d_out;

    cudaFuncSetAttribute((const void*)kmma<512, 8, 1, 128, 256, 4>,
        cudaFuncAttributeMaxDynamicSharedMemorySize, KCfg<128, 256, 4>::TOT);
    cudaFuncSetAttribute((const void*)kmma<1536, 24, 2, 64, 128, 4>,
        cudaFuncAttributeMaxDynamicSharedMemorySize, KCfg<64, 128, 4>::TOT);

    kprep <<<25344, 256>>>(hidden, Wsh, bsh, bsf, Wrh, brh, brf, obj, Wsf, Wrf);
    kmma<512, 8, 1, 128, 256, 4>
        <<<dim3(M1 / 128, 2), 256, KCfg<128, 256, 4>::TOT>>>(was);
    k3_soft <<<NBF, 256>>>(i3d);
    kmma<1536, 24, 2, 64, 128, 4>
        <<<dim3(NBF / 64, 8), 256, KCfg<64, 128, 4>::TOT>>>(nullptr); // 4th -> profiled
    k5_e2   <<<dim3(B_, 5), 256>>>(war);
    k6_final<<<dim3(B_, 3), 256>>>(out);
}

// round 13
// speedup vs baseline: 5.6547x; 1.0267x over previous
#include <cuda_runtime.h>
#include <cuda_fp16.h>
#include <math.h>
#include <stdint.h>

#define B_   32
#define F_   40
#define NB_  36
#define R_   512
#define H_   512
#define D_   1536
#define NBF  1280
#define PM   1024
#define M1   46080
#define BFB  1440      // F_*NB_ rows per batch in stage-1

// ---------------- device scratch (static, no allocation) ----------------
__device__ __align__(16) float g_hb [B_*H_];
__device__ __align__(16) float g_hp2[B_*H_];
__device__ __align__(16) float g_e1 [M1];
__device__ __align__(16) float g_p  [(long)NBF*PM];   // K-split z=0 partial
__device__ __align__(16) float g_p2 [(long)NBF*PM];   // K-split z=1 partial
__device__ __align__(16) float g_e2 [B_*F_*F_];
__device__ __align__(16) __half g_Ah [(long)M1*R_];
__device__ __align__(16) __half g_B1h[H_*R_];
__device__ __align__(16) __half g_Fh [(long)NBF*D_];
__device__ __align__(16) __half g_B2h[(long)PM*D_];

// ---------------- portable (non-'a') PTX helpers ----------------
__device__ __forceinline__ uint32_t smem_u32(const void* p){
    uint32_t a;
    asm("{ .reg .u64 t; cvta.to.shared.u64 t, %1; cvt.u32.u64 %0, t; }" : "=r"(a) : "l"(p));
    return a;
}
__device__ __forceinline__ float tanha(float x){
    float y;
    asm("tanh.approx.f32 %0, %1;" : "=f"(y) : "f"(x));
    return y;
}
#define CP_ASYNC16(dst, src) \
    asm volatile("cp.async.cg.shared.global [%0], [%1], 16;" :: "r"(dst), "l"(src) : "memory")
#define CP_COMMIT() asm volatile("cp.async.commit_group;" ::: "memory")
#define CP_WAIT(n)  asm volatile("cp.async.wait_group %0;" :: "n"(n) : "memory")

__device__ __forceinline__ void ldsm4(uint32_t* r, uint32_t addr){
    asm volatile("ldmatrix.sync.aligned.m8n8.x4.shared.b16 {%0,%1,%2,%3}, [%4];"
        : "=r"(r[0]), "=r"(r[1]), "=r"(r[2]), "=r"(r[3]) : "r"(addr));
}
__device__ __forceinline__ void mma16816(float* c, const uint32_t* a, const uint32_t* b){
    asm volatile("mma.sync.aligned.m16n8k16.row.col.f32.f16.f16.f32 "
        "{%0,%1,%2,%3}, {%4,%5,%6,%7}, {%8,%9}, {%0,%1,%2,%3};"
        : "+f"(c[0]), "+f"(c[1]), "+f"(c[2]), "+f"(c[3])
        : "r"(a[0]), "r"(a[1]), "r"(a[2]), "r"(a[3]), "r"(b[0]), "r"(b[1]));
}

__device__ __forceinline__ void hi4_store(float4 v, __half* hi, size_t qi){
    __half2 h01 = __floats2half2_rn(v.x, v.y);
    __half2 h23 = __floats2half2_rn(v.z, v.w);
    reinterpret_cast<uint2*>(hi)[qi] = make_uint2(*(uint32_t*)&h01, *(uint32_t*)&h23);
}

// ============================================================================
// KPREP: one launch: (a) hidden projections, (b) obj->fp16, (c) weights->fp16
// + e1 zeroing. Branch is block-uniform.
// ============================================================================
__global__ __launch_bounds__(256) void kprep(
    const float* __restrict__ hidden, const float* __restrict__ Wsh,
    const float* __restrict__ bsh,    const float* __restrict__ bsf,
    const float* __restrict__ Wrh,    const float* __restrict__ brh,
    const float* __restrict__ brf,    const float* __restrict__ obj,
    const float* __restrict__ Wsf,    const float* __restrict__ Wrf)
{
    int blk = blockIdx.x, tid = threadIdx.x;
    if (blk < 512) {
        __shared__ float hs[H_];
        int b = blk >> 4;
        int h = (blk & 15) * 32 + (tid >> 3);
        int ks = tid & 7;
        for (int i = tid; i < H_; i += 256) hs[i] = hidden[b * H_ + i];
        __syncthreads();
        const float4* w1 = reinterpret_cast<const float4*>(Wsh + (long)h * H_) + ks * 16;
        const float4* w2 = reinterpret_cast<const float4*>(Wrh + (long)h * H_) + ks * 16;
        const float*  hk = hs + ks * 64;
        float a1 = 0.f, a2 = 0.f;
        #pragma unroll
        for (int k4 = 0; k4 < 16; k4++) {
            float4 v1 = w1[k4], v2 = w2[k4];
            float h0 = hk[k4*4+0], h1 = hk[k4*4+1], h2 = hk[k4*4+2], h3 = hk[k4*4+3];
            a1 = fmaf(h0, v1.x, a1); a1 = fmaf(h1, v1.y, a1);
            a1 = fmaf(h2, v1.z, a1); a1 = fmaf(h3, v1.w, a1);
            a2 = fmaf(h0, v2.x, a2); a2 = fmaf(h1, v2.y, a2);
            a2 = fmaf(h2, v2.z, a2); a2 = fmaf(h3, v2.w, a2);
        }
        #pragma unroll
        for (int off = 4; off; off >>= 1) {
            a1 += __shfl_xor_sync(0xffffffffu, a1, off);
            a2 += __shfl_xor_sync(0xffffffffu, a2, off);
        }
        if (ks == 0) {
            g_hb [b * H_ + h] = a1 + bsh[h] + bsf[h];
            g_hp2[b * H_ + h] = a2 + brh[h] + brf[h];
        }
    } else if (blk < 23552) {
        size_t i = (size_t)(blk - 512) * 256 + tid;
        float4 v = reinterpret_cast<const float4*>(obj)[i];
        hi4_store(v, g_Ah, i);
    } else {
        size_t q = (size_t)(blk - 23552) * 256 + tid;
        if (q < M1) g_e1[q] = 0.f;
        if (q < 65536) {                                 // B1: Wsf 512x512
            float4 v = reinterpret_cast<const float4*>(Wsf)[q];
            hi4_store(v, g_B1h, q);
        } else {                                         // B2: rearranged Wrf -> 1024x1536
            size_t j = q - 65536;
            int m = (int)(j / 384), c4 = (int)(j % 384);
            const float* row = Wrf + (long)(m & 511) * (2 * D_) + (m >> 9) * D_;
            float4 v = reinterpret_cast<const float4*>(row)[c4];
            hi4_store(v, g_B2h, (size_t)m * (D_ / 4) + c4);
        }
    }
}

// ============================================================================
// KMMA: NST-stage cp.async + ldmatrix + mma.sync fp16 GEMM, one __syncthreads
// per K-chunk (Kc=64, SW128 swizzle). CTA tile MT x NT, 8 warps.
// MODE 1: tanh.approx reduce -> atomicAdd g_e1.
// MODE 2: K-split via blockIdx.z (NC chunks each); z=0 -> g_p, z=1 -> g_p2.
// ============================================================================
template<int MT, int NT, int NST> struct KCfg {
    static constexpr int STAGE = (MT + NT) * 128;
    static constexpr int SBUF  = NST * STAGE;
    static constexpr int TOT   = SBUF + 3 * NT * 4;
};

template<int KD, int NC, int MODE, int MT, int NT, int NST>
__global__ __launch_bounds__(256, (MODE == 1) ? 1 : 2)
void kmma(const float* __restrict__ wasp)
{
    constexpr int STAGE = KCfg<MT, NT, NST>::STAGE;
    constexpr int SBUF  = KCfg<MT, NT, NST>::SBUF;
    constexpr int NW    = NT / 2;        // cols per warp
    constexpr int MI    = MT / 64;       // 16-row sub-tiles per warp
    extern __shared__ char smem[];
    const uint32_t sb = smem_u32(smem);
    const int tid  = threadIdx.x, lane = tid & 31, wid = tid >> 5;
    const int wm   = wid & 3, wn = wid >> 2;
    const int row0 = blockIdx.x * MT;
    const int n0c  = blockIdx.y * NT;
    const int koff = blockIdx.z * NC;    // K-split chunk offset (MODE 2)

    const __half *Ah, *Bh;
    if (MODE == 1) { Ah = g_Ah; Bh = g_B1h; }
    else           { Ah = g_Fh; Bh = g_B2h; }

    float* was_s = (float*)(smem + SBUF);
    float* hb_s  = (float*)(smem + SBUF + NT * 4);
    int b0 = 0;
    if (MODE == 1) {
        b0 = row0 / BFB;
        int b1 = (row0 + MT - 1) / BFB;
        for (int i = tid; i < NT; i += 256) {
            was_s[i]      = wasp[n0c + i];
            hb_s[i]       = g_hb[b0 * H_ + n0c + i];
            hb_s[NT + i]  = g_hb[b1 * H_ + n0c + i];
        }
    }

    const int ldr = tid >> 3;            // base row (+32 per iter)
    const int ldq = tid & 7;             // 16B chunk within 128B row

    const int sub = lane >> 3, lr = lane & 7;
    const int a_row = wm * (16 * MI) + ((sub & 1) << 3) + lr;
    const int a_cb  = (sub >> 1) << 4;
    const int b_row = wn * NW + ((sub >> 1) << 3) + lr;
    const int b_cb  = (sub & 1) << 4;
    const uint32_t amask = (uint32_t)((a_row & 7) << 4);
    const uint32_t bmask = (uint32_t)((b_row & 7) << 4);

    float acc[MI][NW / 8][4];
    #pragma unroll
    for (int i = 0; i < MI; i++)
        #pragma unroll
        for (int j = 0; j < NW / 8; j++)
            #pragma unroll
            for (int v = 0; v < 4; v++) acc[i][j][v] = 0.f;

    auto load_chunk = [&](int c) {
        const long kin = (long)(c + koff) * 64;
        uint32_t abase = sb + (uint32_t)(c % NST) * STAGE;
        uint32_t bbase = abase + MT * 128;
        #pragma unroll
        for (int it = 0; it < MT / 32; it++) {
            int r = ldr + it * 32;
            uint32_t off = (uint32_t)(r * 128 + ldq * 16) ^ ((uint32_t)(r & 7) << 4);
            CP_ASYNC16(abase + off, Ah + (long)(row0 + r) * KD + kin + ldq * 8);
        }
        #pragma unroll
        for (int it = 0; it < NT / 32; it++) {
            int r = ldr + it * 32;
            uint32_t off = (uint32_t)(r * 128 + ldq * 16) ^ ((uint32_t)(r & 7) << 4);
            CP_ASYNC16(bbase + off, Bh + (long)(n0c + r) * KD + kin + ldq * 8);
        }
        CP_COMMIT();
    };

    auto compute_chunk = [&](int c) {
        uint32_t abase = sb + (uint32_t)(c % NST) * STAGE;
        uint32_t bbase = abase + MT * 128;
        #pragma unroll
        for (int ks = 0; ks < 4; ks++) {
            const uint32_t kb = (uint32_t)(ks * 32);
            uint32_t af[MI][4], bfr[NW / 16][4];
            #pragma unroll
            for (int i = 0; i < MI; i++)
                ldsm4(af[i], abase + (uint32_t)((a_row + i * 16) * 128)
                                   + (((uint32_t)a_cb + kb) ^ amask));
            #pragma unroll
            for (int j2 = 0; j2 < NW / 16; j2++)
                ldsm4(bfr[j2], bbase + (uint32_t)((b_row + j2 * 16) * 128)
                                     + (((uint32_t)b_cb + kb) ^ bmask));
            #pragma unroll
            for (int i = 0; i < MI; i++)
                #pragma unroll
                for (int j = 0; j < NW / 8; j++)
                    mma16816(acc[i][j], af[i], &bfr[j >> 1][(j & 1) * 2]);
        }
    };

    #pragma unroll
    for (int c = 0; c < NST - 1; c++) load_chunk(c);
    for (int c = 0; c < NC; c++) {
        CP_WAIT(NST - 2);
        __syncthreads();
        compute_chunk(c);
        if (c + NST - 1 < NC) load_chunk(c + NST - 1); else CP_COMMIT();
    }

    const int g = lane >> 2, t = lane & 3;
    if (MODE == 1) {
        #pragma unroll
        for (int i = 0; i < MI; i++) {
            int rl = wm * (16 * MI) + i * 16 + g;
            int rh = rl + 8;
            const float* hbl = hb_s + (((row0 + rl) / BFB) == b0 ? 0 : NT);
            const float* hbh = hb_s + (((row0 + rh) / BFB) == b0 ? 0 : NT);
            float pl = 0.f, ph = 0.f;
            #pragma unroll
            for (int j = 0; j < NW / 8; j++) {
                int nl = wn * NW + j * 8 + 2 * t;
                float w0 = was_s[nl], w1 = was_s[nl + 1];
                pl += w0 * tanha(acc[i][j][0] + hbl[nl])
                    + w1 * tanha(acc[i][j][1] + hbl[nl + 1]);
                ph += w0 * tanha(acc[i][j][2] + hbh[nl])
                    + w1 * tanha(acc[i][j][3] + hbh[nl + 1]);
            }
            pl += __shfl_xor_sync(0xffffffffu, pl, 1);
            pl += __shfl_xor_sync(0xffffffffu, pl, 2);
            ph += __shfl_xor_sync(0xffffffffu, ph, 1);
            ph += __shfl_xor_sync(0xffffffffu, ph, 2);
            if (t == 0) {
                atomicAdd(&g_e1[row0 + rl], pl);
                atomicAdd(&g_e1[row0 + rh], ph);
            }
        }
    } else {
        float* outp = blockIdx.z ? g_p2 : g_p;
        #pragma unroll
        for (int i = 0; i < MI; i++) {
            int rl = row0 + wm * (16 * MI) + i * 16 + g;
            #pragma unroll
            for (int j = 0; j < NW / 8; j++) {
                int nc = n0c + wn * NW + j * 8 + 2 * t;
                *reinterpret_cast<float2*>(&outp[(long)rl * PM + nc])
                    = make_float2(acc[i][j][0], acc[i][j][1]);
                *reinterpret_cast<float2*>(&outp[(long)(rl + 8) * PM + nc])
                    = make_float2(acc[i][j][2], acc[i][j][3]);
            }
        }
    }
}

// ============================================================================
// K3: softmax over NB + attention (from fp16 A) + concat -> fp16 feat only
// ============================================================================
__global__ __launch_bounds__(256) void k3_soft(const float* __restrict__ i3d)
{
    __shared__ float e_s[NB_], alpha[NB_];
    int bf = blockIdx.x, tid = threadIdx.x;
    const __half* fb = g_Ah + (long)bf * NB_ * R_;
    if (tid < NB_) e_s[tid] = g_e1[bf * NB_ + tid];
    __syncthreads();
    if (tid == 0) {
        float m = -1e30f;
        for (int l = 0; l < NB_; l++) m = fmaxf(m, e_s[l]);
        float s = 0.f, tmp[NB_];
        for (int l = 0; l < NB_; l++) { tmp[l] = expf(e_s[l] - m); s += tmp[l]; }
        float inv = 1.f / s;
        for (int l = 0; l < NB_; l++) alpha[l] = tmp[l] * inv;
    }
    __syncthreads();
    __half* fh = g_Fh + (long)bf * D_;
    for (int d = tid; d < R_; d += 256) {
        float s = 0.f;
        #pragma unroll 4
        for (int l = 0; l < NB_; l++)
            s = fmaf(alpha[l], __half2float(fb[l * R_ + d]), s);
        fh[d] = __float2half_rn(s);
    }
    for (int d = tid; d < 2 * H_; d += 256)
        fh[R_ + d] = __float2half_rn(i3d[(long)bf * (2 * H_) + d]);
}

// ============================================================================
// K5: e2[b,i,j] = war . tanh(p2[b,i] + p1[b,j] + hp2[b]); p = g_p + g_p2.
// grid (32,5)
// ============================================================================
__global__ __launch_bounds__(256) void k5_e2(const float* __restrict__ war)
{
    __shared__ float base[8][H_];
    __shared__ float warr[H_];
    int b = blockIdx.x, i0 = blockIdx.y * 8;
    int tid = threadIdx.x, warp = tid >> 5, lane = tid & 31;
    for (int h = tid; h < H_; h += 256) warr[h] = war[h];
    for (int idx = tid; idx < 8 * H_; idx += 256) {
        int ii = idx >> 9, h = idx & (H_ - 1);
        long o = (long)(b * F_ + i0 + ii) * PM + H_ + h;
        base[ii][h] = g_p[o] + g_p2[o] + g_hp2[b * H_ + h];
    }
    __syncthreads();
    for (int jj = 0; jj < 5; jj++) {
        int j = jj * 8 + warp;
        long rowo = (long)(b * F_ + j) * PM;
        float p1v[16];
        #pragma unroll
        for (int kk = 0; kk < 16; kk++) {
            long o = rowo + lane + kk * 32;
            p1v[kk] = g_p[o] + g_p2[o];
        }
        #pragma unroll
        for (int ii = 0; ii < 8; ii++) {
            float part = 0.f;
            #pragma unroll
            for (int kk = 0; kk < 16; kk++) {
                int h = lane + kk * 32;
                part += warr[h] * tanha(base[ii][h] + p1v[kk]);
            }
            #pragma unroll
            for (int off = 16; off; off >>= 1)
                part += __shfl_xor_sync(0xffffffffu, part, off);
            if (lane == 0) g_e2[(long)b * (F_ * F_) + (i0 + ii) * F_ + j] = part;
        }
    }
}

// ============================================================================
// K6: per-batch softmax over F*F, marginals, weighted sums from fp16 feat.
// grid (32,3).
// ============================================================================
__global__ __launch_bounds__(256) void k6_final(float* __restrict__ out)
{
    __shared__ float ex[F_ * F_];
    __shared__ float red[256];
    __shared__ float rowsum[F_], colsum[F_];
    int b = blockIdx.x, tid = threadIdx.x;
    const float* e = g_e2 + b * (F_ * F_);

    float m = -1e30f;
    for (int t = tid; t < F_ * F_; t += 256) m = fmaxf(m, e[t]);
    red[tid] = m; __syncthreads();
    for (int s = 128; s > 0; s >>= 1) {
        if (tid < s) red[tid] = fmaxf(red[tid], red[tid + s]);
        __syncthreads();
    }
    m = red[0]; __syncthreads();

    float sum = 0.f;
    for (int t = tid; t < F_ * F_; t += 256) { float v = expf(e[t] - m); ex[t] = v; sum += v; }
    red[tid] = sum; __syncthreads();
    for (int s = 128; s > 0; s >>= 1) {
        if (tid < s) red[tid] += red[tid + s];
        __syncthreads();
    }
    float inv = 1.f / red[0];

    if (tid < F_) { rowsum[tid] = 0.f; colsum[tid] = 0.f; }
    __syncthreads();
    for (int t = tid; t < F_ * F_; t += 256) {
        float a = ex[t] * inv;
        atomicAdd(&rowsum[t / F_], a);
        atomicAdd(&colsum[t % F_], a);
    }
    __syncthreads();

    int c0 = blockIdx.y * 512;
    for (int d = c0 + tid; d < c0 + 512; d += 256) {
        float r1 = 0.f, r2 = 0.f;
        #pragma unroll 8
        for (int q = 0; q < F_; q++) {
            float fv = __half2float(g_Fh[(long)(b * F_ + q) * D_ + d]);
            r1 = fmaf(colsum[q], fv, r1);
            r2 = fmaf(rowsum[q], fv, r2);
        }
        out[b * (2 * D_) + d]      = r1;
        out[b * (2 * D_) + D_ + d] = r2;
    }
}

// ============================================================================
extern "C" void kernel_launch(void* const* d_in, const int* in_sizes, int n_in,
                              void* d_out, int out_size)
{
    const float* i3d    = (const float*)d_in[0];
    const float* obj    = (const float*)d_in[1];
    const float* hidden = (const float*)d_in[2];
    const float* Wsf    = (const float*)d_in[3];
    const float* bsf    = (const float*)d_in[4];
    const float* Wsh    = (const float*)d_in[5];
    const float* bsh    = (const float*)d_in[6];
    const float* was    = (const float*)d_in[7];
    const float* Wrf    = (const float*)d_in[8];
    const float* brf    = (const float*)d_in[9];
    const float* Wrh    = (const float*)d_in[10];
    const float* brh    = (const float*)d_in[11];
    const float* war    = (const float*)d_in[12];
    float* out = (float*)d_out;

    cudaFuncSetAttribute((const void*)kmma<512, 8, 1, 128, 256, 4>,
        cudaFuncAttributeMaxDynamicSharedMemorySize, KCfg<128, 256, 4>::TOT);
    cudaFuncSetAttribute((const void*)kmma<1536, 12, 2, 128, 128, 3>,
        cudaFuncAttributeMaxDynamicSharedMemorySize, KCfg<128, 128, 3>::TOT);

    kprep <<<25344, 256>>>(hidden, Wsh, bsh, bsf, Wrh, brh, brf, obj, Wsf, Wrf);
    kmma<512, 8, 1, 128, 256, 4>
        <<<dim3(M1 / 128, 2), 256, KCfg<128, 256, 4>::TOT>>>(was);
    k3_soft <<<NBF, 256>>>(i3d);
    kmma<1536, 12, 2, 128, 128, 3>
        <<<dim3(NBF / 128, 8, 2), 256, KCfg<128, 128, 3>::TOT>>>(nullptr); // 4th -> profiled
    k5_e2   <<<dim3(B_, 5), 256>>>(war);
    k6_final<<<dim3(B_, 3), 256>>>(out);
}

// round 14
// speedup vs baseline: 5.9015x; 1.0436x over previous
#include <cuda_runtime.h>
#include <cuda_fp16.h>
#include <math.h>
#include <stdint.h>

#define B_   32
#define F_   40
#define NB_  36
#define R_   512
#define H_   512
#define D_   1536
#define NBF  1280
#define PM   1024
#define M1   46080
#define BFB  1440      // F_*NB_ rows per batch in stage-1

// ---------------- device scratch (static, no allocation) ----------------
__device__ __align__(16) float g_hb [B_*H_];
__device__ __align__(16) float g_hp2[B_*H_];
__device__ __align__(16) float g_e1 [M1];
__device__ __align__(16) float g_p0 [(long)NBF*PM];   // K-split partials
__device__ __align__(16) float g_p1b[(long)NBF*PM];
__device__ __align__(16) float g_p2b[(long)NBF*PM];
__device__ __align__(16) float g_p3b[(long)NBF*PM];
__device__ __align__(16) float g_e2 [B_*F_*F_];
__device__ __align__(16) __half g_Ah [(long)M1*R_];
__device__ __align__(16) __half g_B1h[H_*R_];
__device__ __align__(16) __half g_Fh [(long)NBF*D_];
__device__ __align__(16) __half g_B2h[(long)PM*D_];

// ---------------- portable (non-'a') PTX helpers ----------------
__device__ __forceinline__ uint32_t smem_u32(const void* p){
    uint32_t a;
    asm("{ .reg .u64 t; cvta.to.shared.u64 t, %1; cvt.u32.u64 %0, t; }" : "=r"(a) : "l"(p));
    return a;
}
__device__ __forceinline__ float tanha(float x){
    float y;
    asm("tanh.approx.f32 %0, %1;" : "=f"(y) : "f"(x));
    return y;
}
#define CP_ASYNC16(dst, src) \
    asm volatile("cp.async.cg.shared.global [%0], [%1], 16;" :: "r"(dst), "l"(src) : "memory")
#define CP_COMMIT() asm volatile("cp.async.commit_group;" ::: "memory")
#define CP_WAIT(n)  asm volatile("cp.async.wait_group %0;" :: "n"(n) : "memory")

__device__ __forceinline__ void ldsm4(uint32_t* r, uint32_t addr){
    asm volatile("ldmatrix.sync.aligned.m8n8.x4.shared.b16 {%0,%1,%2,%3}, [%4];"
        : "=r"(r[0]), "=r"(r[1]), "=r"(r[2]), "=r"(r[3]) : "r"(addr));
}
__device__ __forceinline__ void mma16816(float* c, const uint32_t* a, const uint32_t* b){
    asm volatile("mma.sync.aligned.m16n8k16.row.col.f32.f16.f16.f32 "
        "{%0,%1,%2,%3}, {%4,%5,%6,%7}, {%8,%9}, {%0,%1,%2,%3};"
        : "+f"(c[0]), "+f"(c[1]), "+f"(c[2]), "+f"(c[3])
        : "r"(a[0]), "r"(a[1]), "r"(a[2]), "r"(a[3]), "r"(b[0]), "r"(b[1]));
}

__device__ __forceinline__ void hi4_store(float4 v, __half* hi, size_t qi){
    __half2 h01 = __floats2half2_rn(v.x, v.y);
    __half2 h23 = __floats2half2_rn(v.z, v.w);
    reinterpret_cast<uint2*>(hi)[qi] = make_uint2(*(uint32_t*)&h01, *(uint32_t*)&h23);
}

// ============================================================================
// KPREP: one launch: (a) hidden projections, (b) obj->fp16, (c) weights->fp16
// + e1 zeroing. Branch is block-uniform.
// ============================================================================
__global__ __launch_bounds__(256) void kprep(
    const float* __restrict__ hidden, const float* __restrict__ Wsh,
    const float* __restrict__ bsh,    const float* __restrict__ bsf,
    const float* __restrict__ Wrh,    const float* __restrict__ brh,
    const float* __restrict__ brf,    const float* __restrict__ obj,
    const float* __restrict__ Wsf,    const float* __restrict__ Wrf)
{
    int blk = blockIdx.x, tid = threadIdx.x;
    if (blk < 512) {
        __shared__ float hs[H_];
        int b = blk >> 4;
        int h = (blk & 15) * 32 + (tid >> 3);
        int ks = tid & 7;
        for (int i = tid; i < H_; i += 256) hs[i] = hidden[b * H_ + i];
        __syncthreads();
        const float4* w1 = reinterpret_cast<const float4*>(Wsh + (long)h * H_) + ks * 16;
        const float4* w2 = reinterpret_cast<const float4*>(Wrh + (long)h * H_) + ks * 16;
        const float*  hk = hs + ks * 64;
        float a1 = 0.f, a2 = 0.f;
        #pragma unroll
        for (int k4 = 0; k4 < 16; k4++) {
            float4 v1 = w1[k4], v2 = w2[k4];
            float h0 = hk[k4*4+0], h1 = hk[k4*4+1], h2 = hk[k4*4+2], h3 = hk[k4*4+3];
            a1 = fmaf(h0, v1.x, a1); a1 = fmaf(h1, v1.y, a1);
            a1 = fmaf(h2, v1.z, a1); a1 = fmaf(h3, v1.w, a1);
            a2 = fmaf(h0, v2.x, a2); a2 = fmaf(h1, v2.y, a2);
            a2 = fmaf(h2, v2.z, a2); a2 = fmaf(h3, v2.w, a2);
        }
        #pragma unroll
        for (int off = 4; off; off >>= 1) {
            a1 += __shfl_xor_sync(0xffffffffu, a1, off);
            a2 += __shfl_xor_sync(0xffffffffu, a2, off);
        }
        if (ks == 0) {
            g_hb [b * H_ + h] = a1 + bsh[h] + bsf[h];
            g_hp2[b * H_ + h] = a2 + brh[h] + brf[h];
        }
    } else if (blk < 23552) {
        size_t i = (size_t)(blk - 512) * 256 + tid;
        float4 v = reinterpret_cast<const float4*>(obj)[i];
        hi4_store(v, g_Ah, i);
    } else {
        size_t q = (size_t)(blk - 23552) * 256 + tid;
        if (q < M1) g_e1[q] = 0.f;
        if (q < 65536) {                                 // B1: Wsf 512x512
            float4 v = reinterpret_cast<const float4*>(Wsf)[q];
            hi4_store(v, g_B1h, q);
        } else {                                         // B2: rearranged Wrf -> 1024x1536
            size_t j = q - 65536;
            int m = (int)(j / 384), c4 = (int)(j % 384);
            const float* row = Wrf + (long)(m & 511) * (2 * D_) + (m >> 9) * D_;
            float4 v = reinterpret_cast<const float4*>(row)[c4];
            hi4_store(v, g_B2h, (size_t)m * (D_ / 4) + c4);
        }
    }
}

// ============================================================================
// KMMA: NST-stage cp.async + ldmatrix + mma.sync fp16 GEMM, one __syncthreads
// per K-chunk (Kc=64, SW128 swizzle). CTA tile MT x NT, 8 warps.
// MODE 1: tanh.approx reduce -> atomicAdd g_e1 (N-split via blockIdx.y).
// MODE 2: K-split via blockIdx.z (NC chunks each); z -> per-z partial buffer.
// Both configured for 2 CTAs/SM (latency hiding).
// ============================================================================
template<int MT, int NT, int NST> struct KCfg {
    static constexpr int STAGE = (MT + NT) * 128;
    static constexpr int SBUF  = NST * STAGE;
    static constexpr int TOT   = SBUF + 3 * NT * 4;
};

template<int KD, int NC, int MODE, int MT, int NT, int NST>
__global__ __launch_bounds__(256, 2)
void kmma(const float* __restrict__ wasp)
{
    constexpr int STAGE = KCfg<MT, NT, NST>::STAGE;
    constexpr int SBUF  = KCfg<MT, NT, NST>::SBUF;
    constexpr int NW    = NT / 2;        // cols per warp
    constexpr int MI    = MT / 64;       // 16-row sub-tiles per warp
    extern __shared__ char smem[];
    const uint32_t sb = smem_u32(smem);
    const int tid  = threadIdx.x, lane = tid & 31, wid = tid >> 5;
    const int wm   = wid & 3, wn = wid >> 2;
    const int row0 = blockIdx.x * MT;
    const int n0c  = blockIdx.y * NT;
    const int koff = blockIdx.z * NC;    // K-split chunk offset (MODE 2)

    const __half *Ah, *Bh;
    if (MODE == 1) { Ah = g_Ah; Bh = g_B1h; }
    else           { Ah = g_Fh; Bh = g_B2h; }

    float* was_s = (float*)(smem + SBUF);
    float* hb_s  = (float*)(smem + SBUF + NT * 4);
    int b0 = 0;
    if (MODE == 1) {
        b0 = row0 / BFB;
        int b1 = (row0 + MT - 1) / BFB;
        for (int i = tid; i < NT; i += 256) {
            was_s[i]      = wasp[n0c + i];
            hb_s[i]       = g_hb[b0 * H_ + n0c + i];
            hb_s[NT + i]  = g_hb[b1 * H_ + n0c + i];
        }
    }

    const int ldr = tid >> 3;            // base row (+32 per iter)
    const int ldq = tid & 7;             // 16B chunk within 128B row

    const int sub = lane >> 3, lr = lane & 7;
    const int a_row = wm * (16 * MI) + ((sub & 1) << 3) + lr;
    const int a_cb  = (sub >> 1) << 4;
    const int b_row = wn * NW + ((sub >> 1) << 3) + lr;
    const int b_cb  = (sub & 1) << 4;
    const uint32_t amask = (uint32_t)((a_row & 7) << 4);
    const uint32_t bmask = (uint32_t)((b_row & 7) << 4);

    float acc[MI][NW / 8][4];
    #pragma unroll
    for (int i = 0; i < MI; i++)
        #pragma unroll
        for (int j = 0; j < NW / 8; j++)
            #pragma unroll
            for (int v = 0; v < 4; v++) acc[i][j][v] = 0.f;

    auto load_chunk = [&](int c) {
        const long kin = (long)(c + koff) * 64;
        uint32_t abase = sb + (uint32_t)(c % NST) * STAGE;
        uint32_t bbase = abase + MT * 128;
        #pragma unroll
        for (int it = 0; it < MT / 32; it++) {
            int r = ldr + it * 32;
            uint32_t off = (uint32_t)(r * 128 + ldq * 16) ^ ((uint32_t)(r & 7) << 4);
            CP_ASYNC16(abase + off, Ah + (long)(row0 + r) * KD + kin + ldq * 8);
        }
        #pragma unroll
        for (int it = 0; it < NT / 32; it++) {
            int r = ldr + it * 32;
            uint32_t off = (uint32_t)(r * 128 + ldq * 16) ^ ((uint32_t)(r & 7) << 4);
            CP_ASYNC16(bbase + off, Bh + (long)(n0c + r) * KD + kin + ldq * 8);
        }
        CP_COMMIT();
    };

    auto compute_chunk = [&](int c) {
        uint32_t abase = sb + (uint32_t)(c % NST) * STAGE;
        uint32_t bbase = abase + MT * 128;
        #pragma unroll
        for (int ks = 0; ks < 4; ks++) {
            const uint32_t kb = (uint32_t)(ks * 32);
            uint32_t af[MI][4], bfr[NW / 16][4];
            #pragma unroll
            for (int i = 0; i < MI; i++)
                ldsm4(af[i], abase + (uint32_t)((a_row + i * 16) * 128)
                                   + (((uint32_t)a_cb + kb) ^ amask));
            #pragma unroll
            for (int j2 = 0; j2 < NW / 16; j2++)
                ldsm4(bfr[j2], bbase + (uint32_t)((b_row + j2 * 16) * 128)
                                     + (((uint32_t)b_cb + kb) ^ bmask));
            #pragma unroll
            for (int i = 0; i < MI; i++)
                #pragma unroll
                for (int j = 0; j < NW / 8; j++)
                    mma16816(acc[i][j], af[i], &bfr[j >> 1][(j & 1) * 2]);
        }
    };

    #pragma unroll
    for (int c = 0; c < NST - 1; c++) load_chunk(c);
    for (int c = 0; c < NC; c++) {
        CP_WAIT(NST - 2);
        __syncthreads();
        compute_chunk(c);
        if (c + NST - 1 < NC) load_chunk(c + NST - 1); else CP_COMMIT();
    }

    const int g = lane >> 2, t = lane & 3;
    if (MODE == 1) {
        #pragma unroll
        for (int i = 0; i < MI; i++) {
            int rl = wm * (16 * MI) + i * 16 + g;
            int rh = rl + 8;
            const float* hbl = hb_s + (((row0 + rl) / BFB) == b0 ? 0 : NT);
            const float* hbh = hb_s + (((row0 + rh) / BFB) == b0 ? 0 : NT);
            float pl = 0.f, ph = 0.f;
            #pragma unroll
            for (int j = 0; j < NW / 8; j++) {
                int nl = wn * NW + j * 8 + 2 * t;
                float w0 = was_s[nl], w1 = was_s[nl + 1];
                pl += w0 * tanha(acc[i][j][0] + hbl[nl])
                    + w1 * tanha(acc[i][j][1] + hbl[nl + 1]);
                ph += w0 * tanha(acc[i][j][2] + hbh[nl])
                    + w1 * tanha(acc[i][j][3] + hbh[nl + 1]);
            }
            pl += __shfl_xor_sync(0xffffffffu, pl, 1);
            pl += __shfl_xor_sync(0xffffffffu, pl, 2);
            ph += __shfl_xor_sync(0xffffffffu, ph, 1);
            ph += __shfl_xor_sync(0xffffffffu, ph, 2);
            if (t == 0) {
                atomicAdd(&g_e1[row0 + rl], pl);
                atomicAdd(&g_e1[row0 + rh], ph);
            }
        }
    } else {
        float* outp = (blockIdx.z == 0) ? g_p0 : (blockIdx.z == 1) ? g_p1b
                    : (blockIdx.z == 2) ? g_p2b : g_p3b;
        #pragma unroll
        for (int i = 0; i < MI; i++) {
            int rl = row0 + wm * (16 * MI) + i * 16 + g;
            #pragma unroll
            for (int j = 0; j < NW / 8; j++) {
                int nc = n0c + wn * NW + j * 8 + 2 * t;
                *reinterpret_cast<float2*>(&outp[(long)rl * PM + nc])
                    = make_float2(acc[i][j][0], acc[i][j][1]);
                *reinterpret_cast<float2*>(&outp[(long)(rl + 8) * PM + nc])
                    = make_float2(acc[i][j][2], acc[i][j][3]);
            }
        }
    }
}

// ============================================================================
// K3: softmax over NB + attention (from fp16 A) + concat -> fp16 feat only
// ============================================================================
__global__ __launch_bounds__(256) void k3_soft(const float* __restrict__ i3d)
{
    __shared__ float e_s[NB_], alpha[NB_];
    int bf = blockIdx.x, tid = threadIdx.x;
    const __half* fb = g_Ah + (long)bf * NB_ * R_;
    if (tid < NB_) e_s[tid] = g_e1[bf * NB_ + tid];
    __syncthreads();
    if (tid == 0) {
        float m = -1e30f;
        for (int l = 0; l < NB_; l++) m = fmaxf(m, e_s[l]);
        float s = 0.f, tmp[NB_];
        for (int l = 0; l < NB_; l++) { tmp[l] = expf(e_s[l] - m); s += tmp[l]; }
        float inv = 1.f / s;
        for (int l = 0; l < NB_; l++) alpha[l] = tmp[l] * inv;
    }
    __syncthreads();
    __half* fh = g_Fh + (long)bf * D_;
    for (int d = tid; d < R_; d += 256) {
        float s = 0.f;
        #pragma unroll 4
        for (int l = 0; l < NB_; l++)
            s = fmaf(alpha[l], __half2float(fb[l * R_ + d]), s);
        fh[d] = __float2half_rn(s);
    }
    for (int d = tid; d < 2 * H_; d += 256)
        fh[R_ + d] = __float2half_rn(i3d[(long)bf * (2 * H_) + d]);
}

// ============================================================================
// K5: e2[b,i,j] = war . tanh(p2[b,i] + p1[b,j] + hp2[b]); p = sum of 4
// K-split partials. grid (32,5)
// ============================================================================
__global__ __launch_bounds__(256) void k5_e2(const float* __restrict__ war)
{
    __shared__ float base[8][H_];
    __shared__ float warr[H_];
    int b = blockIdx.x, i0 = blockIdx.y * 8;
    int tid = threadIdx.x, warp = tid >> 5, lane = tid & 31;
    for (int h = tid; h < H_; h += 256) warr[h] = war[h];
    for (int idx = tid; idx < 8 * H_; idx += 256) {
        int ii = idx >> 9, h = idx & (H_ - 1);
        long o = (long)(b * F_ + i0 + ii) * PM + H_ + h;
        base[ii][h] = (g_p0[o] + g_p1b[o]) + (g_p2b[o] + g_p3b[o])
                    + g_hp2[b * H_ + h];
    }
    __syncthreads();
    for (int jj = 0; jj < 5; jj++) {
        int j = jj * 8 + warp;
        long rowo = (long)(b * F_ + j) * PM;
        float p1v[16];
        #pragma unroll
        for (int kk = 0; kk < 16; kk++) {
            long o = rowo + lane + kk * 32;
            p1v[kk] = (g_p0[o] + g_p1b[o]) + (g_p2b[o] + g_p3b[o]);
        }
        #pragma unroll
        for (int ii = 0; ii < 8; ii++) {
            float part = 0.f;
            #pragma unroll
            for (int kk = 0; kk < 16; kk++) {
                int h = lane + kk * 32;
                part += warr[h] * tanha(base[ii][h] + p1v[kk]);
            }
            #pragma unroll
            for (int off = 16; off; off >>= 1)
                part += __shfl_xor_sync(0xffffffffu, part, off);
            if (lane == 0) g_e2[(long)b * (F_ * F_) + (i0 + ii) * F_ + j] = part;
        }
    }
}

// ============================================================================
// K6: per-batch softmax over F*F, marginals, weighted sums from fp16 feat.
// grid (32,3).
// ============================================================================
__global__ __launch_bounds__(256) void k6_final(float* __restrict__ out)
{
    __shared__ float ex[F_ * F_];
    __shared__ float red[256];
    __shared__ float rowsum[F_], colsum[F_];
    int b = blockIdx.x, tid = threadIdx.x;
    const float* e = g_e2 + b * (F_ * F_);

    float m = -1e30f;
    for (int t = tid; t < F_ * F_; t += 256) m = fmaxf(m, e[t]);
    red[tid] = m; __syncthreads();
    for (int s = 128; s > 0; s >>= 1) {
        if (tid < s) red[tid] = fmaxf(red[tid], red[tid + s]);
        __syncthreads();
    }
    m = red[0]; __syncthreads();

    float sum = 0.f;
    for (int t = tid; t < F_ * F_; t += 256) { float v = expf(e[t] - m); ex[t] = v; sum += v; }
    red[tid] = sum; __syncthreads();
    for (int s = 128; s > 0; s >>= 1) {
        if (tid < s) red[tid] += red[tid + s];
        __syncthreads();
    }
    float inv = 1.f / red[0];

    if (tid < F_) { rowsum[tid] = 0.f; colsum[tid] = 0.f; }
    __syncthreads();
    for (int t = tid; t < F_ * F_; t += 256) {
        float a = ex[t] * inv;
        atomicAdd(&rowsum[t / F_], a);
        atomicAdd(&colsum[t % F_], a);
    }
    __syncthreads();

    int c0 = blockIdx.y * 512;
    for (int d = c0 + tid; d < c0 + 512; d += 256) {
        float r1 = 0.f, r2 = 0.f;
        #pragma unroll 8
        for (int q = 0; q < F_; q++) {
            float fv = __half2float(g_Fh[(long)(b * F_ + q) * D_ + d]);
            r1 = fmaf(colsum[q], fv, r1);
            r2 = fmaf(rowsum[q], fv, r2);
        }
        out[b * (2 * D_) + d]      = r1;
        out[b * (2 * D_) + D_ + d] = r2;
    }
}

// ============================================================================
extern "C" void kernel_launch(void* const* d_in, const int* in_sizes, int n_in,
                              void* d_out, int out_size)
{
    const float* i3d    = (const float*)d_in[0];
    const float* obj    = (const float*)d_in[1];
    const float* hidden = (const float*)d_in[2];
    const float* Wsf    = (const float*)d_in[3];
    const float* bsf    = (const float*)d_in[4];
    const float* Wsh    = (const float*)d_in[5];
    const float* bsh    = (const float*)d_in[6];
    const float* was    = (const float*)d_in[7];
    const float* Wrf    = (const float*)d_in[8];
    const float* brf    = (const float*)d_in[9];
    const float* Wrh    = (const float*)d_in[10];
    const float* brh    = (const float*)d_in[11];
    const float* war    = (const float*)d_in[12];
    float* out = (float*)d_out;

    cudaFuncSetAttribute((const void*)kmma<512, 8, 1, 128, 128, 3>,
        cudaFuncAttributeMaxDynamicSharedMemorySize, KCfg<128, 128, 3>::TOT);
    cudaFuncSetAttribute((const void*)kmma<1536, 6, 2, 128, 128, 3>,
        cudaFuncAttributeMaxDynamicSharedMemorySize, KCfg<128, 128, 3>::TOT);

    kprep <<<25344, 256>>>(hidden, Wsh, bsh, bsf, Wrh, brh, brf, obj, Wsf, Wrf);
    kmma<512, 8, 1, 128, 128, 3>
        <<<dim3(M1 / 128, 4), 256, KCfg<128, 128, 3>::TOT>>>(was);   // 2 CTA/SM
    k3_soft <<<NBF, 256>>>(i3d);
    kmma<1536, 6, 2, 128, 128, 3>
        <<<dim3(NBF / 128, 8, 4), 256, KCfg<128, 128, 3>::TOT>>>(nullptr); // 320 CTAs, 4th -> profiled
    k5_e2   <<<dim3(B_, 5), 256>>>(war);
    k6_final<<<dim3(B_, 3), 256>>>(out);
}

// round 15
// speedup vs baseline: 5.9085x; 1.0012x over previous
#include <cuda_runtime.h>
#include <cuda_fp16.h>
#include <math.h>
#include <stdint.h>

#define B_   32
#define F_   40
#define NB_  36
#define R_   512
#define H_   512
#define D_   1536
#define NBF  1280
#define PM   1024
#define M1   46080
#define BFB  1440      // F_*NB_ rows per batch in stage-1

// ---------------- device scratch (static, no allocation) ----------------
__device__ __align__(16) float g_hb [B_*H_];
__device__ __align__(16) float g_hp2[B_*H_];
__device__ __align__(16) float g_e1 [M1];
__device__ __align__(16) float g_p0 [(long)NBF*PM];   // K-split partials
__device__ __align__(16) float g_p1b[(long)NBF*PM];
__device__ __align__(16) float g_p2b[(long)NBF*PM];
__device__ __align__(16) float g_p3b[(long)NBF*PM];
__device__ __align__(16) float g_e2 [B_*F_*F_];
__device__ __align__(16) __half g_Ah [(long)M1*R_];
__device__ __align__(16) __half g_B1h[H_*R_];
__device__ __align__(16) __half g_Fh [(long)NBF*D_];
__device__ __align__(16) __half g_B2h[(long)PM*D_];

// ---------------- portable (non-'a') PTX helpers ----------------
__device__ __forceinline__ uint32_t smem_u32(const void* p){
    uint32_t a;
    asm("{ .reg .u64 t; cvta.to.shared.u64 t, %1; cvt.u32.u64 %0, t; }" : "=r"(a) : "l"(p));
    return a;
}
__device__ __forceinline__ float tanha(float x){
    float y;
    asm("tanh.approx.f32 %0, %1;" : "=f"(y) : "f"(x));
    return y;
}
#define CP_ASYNC16(dst, src) \
    asm volatile("cp.async.cg.shared.global [%0], [%1], 16;" :: "r"(dst), "l"(src) : "memory")
#define CP_COMMIT() asm volatile("cp.async.commit_group;" ::: "memory")
#define CP_WAIT(n)  asm volatile("cp.async.wait_group %0;" :: "n"(n) : "memory")

__device__ __forceinline__ void ldsm4(uint32_t* r, uint32_t addr){
    asm volatile("ldmatrix.sync.aligned.m8n8.x4.shared.b16 {%0,%1,%2,%3}, [%4];"
        : "=r"(r[0]), "=r"(r[1]), "=r"(r[2]), "=r"(r[3]) : "r"(addr));
}
__device__ __forceinline__ void mma16816(float* c, const uint32_t* a, const uint32_t* b){
    asm volatile("mma.sync.aligned.m16n8k16.row.col.f32.f16.f16.f32 "
        "{%0,%1,%2,%3}, {%4,%5,%6,%7}, {%8,%9}, {%0,%1,%2,%3};"
        : "+f"(c[0]), "+f"(c[1]), "+f"(c[2]), "+f"(c[3])
        : "r"(a[0]), "r"(a[1]), "r"(a[2]), "r"(a[3]), "r"(b[0]), "r"(b[1]));
}

__device__ __forceinline__ void hi4_store(float4 v, __half* hi, size_t qi){
    __half2 h01 = __floats2half2_rn(v.x, v.y);
    __half2 h23 = __floats2half2_rn(v.z, v.w);
    reinterpret_cast<uint2*>(hi)[qi] = make_uint2(*(uint32_t*)&h01, *(uint32_t*)&h23);
}

// ============================================================================
// KPREP: one launch: (a) hidden projections, (b) obj->fp16, (c) weights->fp16
// + e1 zeroing, (d) i3d->fp16 straight into g_Fh[:, 512:]. Block-uniform branch.
// ============================================================================
__global__ __launch_bounds__(256) void kprep(
    const float* __restrict__ hidden, const float* __restrict__ Wsh,
    const float* __restrict__ bsh,    const float* __restrict__ bsf,
    const float* __restrict__ Wrh,    const float* __restrict__ brh,
    const float* __restrict__ brf,    const float* __restrict__ obj,
    const float* __restrict__ Wsf,    const float* __restrict__ Wrf,
    const float* __restrict__ i3d)
{
    int blk = blockIdx.x, tid = threadIdx.x;
    if (blk < 512) {
        __shared__ float hs[H_];
        int b = blk >> 4;
        int h = (blk & 15) * 32 + (tid >> 3);
        int ks = tid & 7;
        for (int i = tid; i < H_; i += 256) hs[i] = hidden[b * H_ + i];
        __syncthreads();
        const float4* w1 = reinterpret_cast<const float4*>(Wsh + (long)h * H_) + ks * 16;
        const float4* w2 = reinterpret_cast<const float4*>(Wrh + (long)h * H_) + ks * 16;
        const float*  hk = hs + ks * 64;
        float a1 = 0.f, a2 = 0.f;
        #pragma unroll
        for (int k4 = 0; k4 < 16; k4++) {
            float4 v1 = w1[k4], v2 = w2[k4];
            float h0 = hk[k4*4+0], h1 = hk[k4*4+1], h2 = hk[k4*4+2], h3 = hk[k4*4+3];
            a1 = fmaf(h0, v1.x, a1); a1 = fmaf(h1, v1.y, a1);
            a1 = fmaf(h2, v1.z, a1); a1 = fmaf(h3, v1.w, a1);
            a2 = fmaf(h0, v2.x, a2); a2 = fmaf(h1, v2.y, a2);
            a2 = fmaf(h2, v2.z, a2); a2 = fmaf(h3, v2.w, a2);
        }
        #pragma unroll
        for (int off = 4; off; off >>= 1) {
            a1 += __shfl_xor_sync(0xffffffffu, a1, off);
            a2 += __shfl_xor_sync(0xffffffffu, a2, off);
        }
        if (ks == 0) {
            g_hb [b * H_ + h] = a1 + bsh[h] + bsf[h];
            g_hp2[b * H_ + h] = a2 + brh[h] + brf[h];
        }
    } else if (blk < 23552) {
        size_t i = (size_t)(blk - 512) * 256 + tid;
        float4 v = reinterpret_cast<const float4*>(obj)[i];
        hi4_store(v, g_Ah, i);
    } else if (blk < 25344) {
        size_t q = (size_t)(blk - 23552) * 256 + tid;
        if (q < M1) g_e1[q] = 0.f;
        if (q < 65536) {                                 // B1: Wsf 512x512
            float4 v = reinterpret_cast<const float4*>(Wsf)[q];
            hi4_store(v, g_B1h, q);
        } else {                                         // B2: rearranged Wrf -> 1024x1536
            size_t j = q - 65536;
            int m = (int)(j / 384), c4 = (int)(j % 384);
            const float* row = Wrf + (long)(m & 511) * (2 * D_) + (m >> 9) * D_;
            float4 v = reinterpret_cast<const float4*>(row)[c4];
            hi4_store(v, g_B2h, (size_t)m * (D_ / 4) + c4);
        }
    } else {                                             // i3d -> Fh[:, 512:]
        size_t q = (size_t)(blk - 25344) * 256 + tid;    // [0, 327680)
        int bf = (int)(q >> 8), w = (int)(q & 255);
        float4 v = reinterpret_cast<const float4*>(i3d)[q];
        hi4_store(v, g_Fh, (size_t)bf * (D_ / 4) + 128 + w);
    }
}

// ============================================================================
// KMMA: NST-stage cp.async + ldmatrix + mma.sync fp16 GEMM, one __syncthreads
// per K-chunk (Kc=64, SW128 swizzle). CTA tile MT x NT, 8 warps, 2 CTAs/SM.
// MODE 1: tanh.approx reduce -> atomicAdd g_e1 (N-split via blockIdx.y).
// MODE 2: K-chunks [KOFF0 + z*NC, +NC) -> partial buffer (PBASE + z).
// ============================================================================
template<int MT, int NT, int NST> struct KCfg {
    static constexpr int STAGE = (MT + NT) * 128;
    static constexpr int SBUF  = NST * STAGE;
    static constexpr int TOT   = SBUF + 3 * NT * 4;
};

template<int KD, int NC, int MODE, int MT, int NT, int NST, int KOFF0, int PBASE>
__global__ __launch_bounds__(256, 2)
void kmma(const float* __restrict__ wasp)
{
    constexpr int STAGE = KCfg<MT, NT, NST>::STAGE;
    constexpr int SBUF  = KCfg<MT, NT, NST>::SBUF;
    constexpr int NW    = NT / 2;        // cols per warp
    constexpr int MI    = MT / 64;       // 16-row sub-tiles per warp
    extern __shared__ char smem[];
    const uint32_t sb = smem_u32(smem);
    const int tid  = threadIdx.x, lane = tid & 31, wid = tid >> 5;
    const int wm   = wid & 3, wn = wid >> 2;
    const int row0 = blockIdx.x * MT;
    const int n0c  = blockIdx.y * NT;
    const int koff = KOFF0 + blockIdx.z * NC;

    const __half *Ah, *Bh;
    if (MODE == 1) { Ah = g_Ah; Bh = g_B1h; }
    else           { Ah = g_Fh; Bh = g_B2h; }

    float* was_s = (float*)(smem + SBUF);
    float* hb_s  = (float*)(smem + SBUF + NT * 4);
    int b0 = 0;
    if (MODE == 1) {
        b0 = row0 / BFB;
        int b1 = (row0 + MT - 1) / BFB;
        for (int i = tid; i < NT; i += 256) {
            was_s[i]      = wasp[n0c + i];
            hb_s[i]       = g_hb[b0 * H_ + n0c + i];
            hb_s[NT + i]  = g_hb[b1 * H_ + n0c + i];
        }
    }

    const int ldr = tid >> 3;            // base row (+32 per iter)
    const int ldq = tid & 7;             // 16B chunk within 128B row

    const int sub = lane >> 3, lr = lane & 7;
    const int a_row = wm * (16 * MI) + ((sub & 1) << 3) + lr;
    const int a_cb  = (sub >> 1) << 4;
    const int b_row = wn * NW + ((sub >> 1) << 3) + lr;
    const int b_cb  = (sub & 1) << 4;
    const uint32_t amask = (uint32_t)((a_row & 7) << 4);
    const uint32_t bmask = (uint32_t)((b_row & 7) << 4);

    float acc[MI][NW / 8][4];
    #pragma unroll
    for (int i = 0; i < MI; i++)
        #pragma unroll
        for (int j = 0; j < NW / 8; j++)
            #pragma unroll
            for (int v = 0; v < 4; v++) acc[i][j][v] = 0.f;

    auto load_chunk = [&](int c) {
        const long kin = (long)(c + koff) * 64;
        uint32_t abase = sb + (uint32_t)(c % NST) * STAGE;
        uint32_t bbase = abase + MT * 128;
        #pragma unroll
        for (int it = 0; it < MT / 32; it++) {
            int r = ldr + it * 32;
            uint32_t off = (uint32_t)(r * 128 + ldq * 16) ^ ((uint32_t)(r & 7) << 4);
            CP_ASYNC16(abase + off, Ah + (long)(row0 + r) * KD + kin + ldq * 8);
        }
        #pragma unroll
        for (int it = 0; it < NT / 32; it++) {
            int r = ldr + it * 32;
            uint32_t off = (uint32_t)(r * 128 + ldq * 16) ^ ((uint32_t)(r & 7) << 4);
            CP_ASYNC16(bbase + off, Bh + (long)(n0c + r) * KD + kin + ldq * 8);
        }
        CP_COMMIT();
    };

    auto compute_chunk = [&](int c) {
        uint32_t abase = sb + (uint32_t)(c % NST) * STAGE;
        uint32_t bbase = abase + MT * 128;
        #pragma unroll
        for (int ks = 0; ks < 4; ks++) {
            const uint32_t kb = (uint32_t)(ks * 32);
            uint32_t af[MI][4], bfr[NW / 16][4];
            #pragma unroll
            for (int i = 0; i < MI; i++)
                ldsm4(af[i], abase + (uint32_t)((a_row + i * 16) * 128)
                                   + (((uint32_t)a_cb + kb) ^ amask));
            #pragma unroll
            for (int j2 = 0; j2 < NW / 16; j2++)
                ldsm4(bfr[j2], bbase + (uint32_t)((b_row + j2 * 16) * 128)
                                     + (((uint32_t)b_cb + kb) ^ bmask));
            #pragma unroll
            for (int i = 0; i < MI; i++)
                #pragma unroll
                for (int j = 0; j < NW / 8; j++)
                    mma16816(acc[i][j], af[i], &bfr[j >> 1][(j & 1) * 2]);
        }
    };

    #pragma unroll
    for (int c = 0; c < NST - 1; c++) load_chunk(c);
    for (int c = 0; c < NC; c++) {
        CP_WAIT(NST - 2);
        __syncthreads();
        compute_chunk(c);
        if (c + NST - 1 < NC) load_chunk(c + NST - 1); else CP_COMMIT();
    }

    const int g = lane >> 2, t = lane & 3;
    if (MODE == 1) {
        #pragma unroll
        for (int i = 0; i < MI; i++) {
            int rl = wm * (16 * MI) + i * 16 + g;
            int rh = rl + 8;
            const float* hbl = hb_s + (((row0 + rl) / BFB) == b0 ? 0 : NT);
            const float* hbh = hb_s + (((row0 + rh) / BFB) == b0 ? 0 : NT);
            float pl = 0.f, ph = 0.f;
            #pragma unroll
            for (int j = 0; j < NW / 8; j++) {
                int nl = wn * NW + j * 8 + 2 * t;
                float w0 = was_s[nl], w1 = was_s[nl + 1];
                pl += w0 * tanha(acc[i][j][0] + hbl[nl])
                    + w1 * tanha(acc[i][j][1] + hbl[nl + 1]);
                ph += w0 * tanha(acc[i][j][2] + hbh[nl])
                    + w1 * tanha(acc[i][j][3] + hbh[nl + 1]);
            }
            pl += __shfl_xor_sync(0xffffffffu, pl, 1);
            pl += __shfl_xor_sync(0xffffffffu, pl, 2);
            ph += __shfl_xor_sync(0xffffffffu, ph, 1);
            ph += __shfl_xor_sync(0xffffffffu, ph, 2);
            if (t == 0) {
                atomicAdd(&g_e1[row0 + rl], pl);
                atomicAdd(&g_e1[row0 + rh], ph);
            }
        }
    } else {
        int pz = PBASE + blockIdx.z;
        float* outp = (pz == 0) ? g_p0 : (pz == 1) ? g_p1b
                    : (pz == 2) ? g_p2b : g_p3b;
        #pragma unroll
        for (int i = 0; i < MI; i++) {
            int rl = row0 + wm * (16 * MI) + i * 16 + g;
            #pragma unroll
            for (int j = 0; j < NW / 8; j++) {
                int nc = n0c + wn * NW + j * 8 + 2 * t;
                *reinterpret_cast<float2*>(&outp[(long)rl * PM + nc])
                    = make_float2(acc[i][j][0], acc[i][j][1]);
                *reinterpret_cast<float2*>(&outp[(long)(rl + 8) * PM + nc])
                    = make_float2(acc[i][j][2], acc[i][j][3]);
            }
        }
    }
}

// ============================================================================
// K3: softmax over NB + attention (from fp16 A) -> fp16 feat[:, :512] only
// (i3d half already written by kprep)
// ============================================================================
__global__ __launch_bounds__(256) void k3_soft()
{
    __shared__ float e_s[NB_], alpha[NB_];
    int bf = blockIdx.x, tid = threadIdx.x;
    const __half* fb = g_Ah + (long)bf * NB_ * R_;
    if (tid < NB_) e_s[tid] = g_e1[bf * NB_ + tid];
    __syncthreads();
    if (tid == 0) {
        float m = -1e30f;
        for (int l = 0; l < NB_; l++) m = fmaxf(m, e_s[l]);
        float s = 0.f, tmp[NB_];
        for (int l = 0; l < NB_; l++) { tmp[l] = expf(e_s[l] - m); s += tmp[l]; }
        float inv = 1.f / s;
        for (int l = 0; l < NB_; l++) alpha[l] = tmp[l] * inv;
    }
    __syncthreads();
    __half* fh = g_Fh + (long)bf * D_;
    for (int d = tid; d < R_; d += 256) {
        float s = 0.f;
        #pragma unroll 4
        for (int l = 0; l < NB_; l++)
            s = fmaf(alpha[l], __half2float(fb[l * R_ + d]), s);
        fh[d] = __float2half_rn(s);
    }
}

// ============================================================================
// K5: e2[b,i,j] = war . tanh(p2[b,i] + p1[b,j] + hp2[b]); p = sum of 4
// K-split partials. grid (32,5)
// ============================================================================
__global__ __launch_bounds__(256) void k5_e2(const float* __restrict__ war)
{
    __shared__ float base[8][H_];
    __shared__ float warr[H_];
    int b = blockIdx.x, i0 = blockIdx.y * 8;
    int tid = threadIdx.x, warp = tid >> 5, lane = tid & 31;
    for (int h = tid; h < H_; h += 256) warr[h] = war[h];
    for (int idx = tid; idx < 8 * H_; idx += 256) {
        int ii = idx >> 9, h = idx & (H_ - 1);
        long o = (long)(b * F_ + i0 + ii) * PM + H_ + h;
        base[ii][h] = (g_p0[o] + g_p1b[o]) + (g_p2b[o] + g_p3b[o])
                    + g_hp2[b * H_ + h];
    }
    __syncthreads();
    for (int jj = 0; jj < 5; jj++) {
        int j = jj * 8 + warp;
        long rowo = (long)(b * F_ + j) * PM;
        float p1v[16];
        #pragma unroll
        for (int kk = 0; kk < 16; kk++) {
            long o = rowo + lane + kk * 32;
            p1v[kk] = (g_p0[o] + g_p1b[o]) + (g_p2b[o] + g_p3b[o]);
        }
        #pragma unroll
        for (int ii = 0; ii < 8; ii++) {
            float part = 0.f;
            #pragma unroll
            for (int kk = 0; kk < 16; kk++) {
                int h = lane + kk * 32;
                part += warr[h] * tanha(base[ii][h] + p1v[kk]);
            }
            #pragma unroll
            for (int off = 16; off; off >>= 1)
                part += __shfl_xor_sync(0xffffffffu, part, off);
            if (lane == 0) g_e2[(long)b * (F_ * F_) + (i0 + ii) * F_ + j] = part;
        }
    }
}

// ============================================================================
// K6: per-batch softmax over F*F, marginals, weighted sums from fp16 feat.
// grid (32,3).
// ============================================================================
__global__ __launch_bounds__(256) void k6_final(float* __restrict__ out)
{
    __shared__ float ex[F_ * F_];
    __shared__ float red[256];
    __shared__ float rowsum[F_], colsum[F_];
    int b = blockIdx.x, tid = threadIdx.x;
    const float* e = g_e2 + b * (F_ * F_);

    float m = -1e30f;
    for (int t = tid; t < F_ * F_; t += 256) m = fmaxf(m, e[t]);
    red[tid] = m; __syncthreads();
    for (int s = 128; s > 0; s >>= 1) {
        if (tid < s) red[tid] = fmaxf(red[tid], red[tid + s]);
        __syncthreads();
    }
    m = red[0]; __syncthreads();

    float sum = 0.f;
    for (int t = tid; t < F_ * F_; t += 256) { float v = expf(e[t] - m); ex[t] = v; sum += v; }
    red[tid] = sum; __syncthreads();
    for (int s = 128; s > 0; s >>= 1) {
        if (tid < s) red[tid] += red[tid + s];
        __syncthreads();
    }
    float inv = 1.f / red[0];

    if (tid < F_) { rowsum[tid] = 0.f; colsum[tid] = 0.f; }
    __syncthreads();
    for (int t = tid; t < F_ * F_; t += 256) {
        float a = ex[t] * inv;
        atomicAdd(&rowsum[t / F_], a);
        atomicAdd(&colsum[t % F_], a);
    }
    __syncthreads();

    int c0 = blockIdx.y * 512;
    for (int d = c0 + tid; d < c0 + 512; d += 256) {
        float r1 = 0.f, r2 = 0.f;
        #pragma unroll 8
        for (int q = 0; q < F_; q++) {
            float fv = __half2float(g_Fh[(long)(b * F_ + q) * D_ + d]);
            r1 = fmaf(colsum[q], fv, r1);
            r2 = fmaf(rowsum[q], fv, r2);
        }
        out[b * (2 * D_) + d]      = r1;
        out[b * (2 * D_) + D_ + d] = r2;
    }
}

// ============================================================================
extern "C" void kernel_launch(void* const* d_in, const int* in_sizes, int n_in,
                              void* d_out, int out_size)
{
    const float* i3d    = (const float*)d_in[0];
    const float* obj    = (const float*)d_in[1];
    const float* hidden = (const float*)d_in[2];
    const float* Wsf    = (const float*)d_in[3];
    const float* bsf    = (const float*)d_in[4];
    const float* Wsh    = (const float*)d_in[5];
    const float* bsh    = (const float*)d_in[6];
    const float* was    = (const float*)d_in[7];
    const float* Wrf    = (const float*)d_in[8];
    const float* brf    = (const float*)d_in[9];
    const float* Wrh    = (const float*)d_in[10];
    const float* brh    = (const float*)d_in[11];
    const float* war    = (const float*)d_in[12];
    float* out = (float*)d_out;

    static cudaStream_t s2 = nullptr;
    static cudaEvent_t ev1 = nullptr, ev2 = nullptr;
    if (s2 == nullptr) {
        cudaStreamCreateWithFlags(&s2, cudaStreamNonBlocking);
        cudaEventCreateWithFlags(&ev1, cudaEventDisableTiming);
        cudaEventCreateWithFlags(&ev2, cudaEventDisableTiming);
    }

    // kmma1: stage-1. kmma2b: i3d part of p (K-chunks 8..23, partials 0/1).
    // kmma2a: obj_att part of p (K-chunks 0..7, partials 2/3).
    auto km1  = kmma<512, 8, 1, 128, 128, 3, 0, 0>;
    auto km2b = kmma<1536, 8, 2, 128, 128, 3, 8, 0>;
    auto km2a = kmma<1536, 4, 2, 128, 128, 3, 0, 2>;
    cudaFuncSetAttribute((const void*)km1,
        cudaFuncAttributeMaxDynamicSharedMemorySize, KCfg<128, 128, 3>::TOT);
    cudaFuncSetAttribute((const void*)km2b,
        cudaFuncAttributeMaxDynamicSharedMemorySize, KCfg<128, 128, 3>::TOT);
    cudaFuncSetAttribute((const void*)km2a,
        cudaFuncAttributeMaxDynamicSharedMemorySize, KCfg<128, 128, 3>::TOT);

    kprep <<<26624, 256>>>(hidden, Wsh, bsh, bsf, Wrh, brh, brf, obj, Wsf, Wrf, i3d);

    // Fork: i3d GEMM runs on s2 concurrently with stage-1 on the main stream.
    cudaEventRecord(ev1, 0);
    cudaStreamWaitEvent(s2, ev1, 0);
    km2b <<<dim3(NBF / 128, 8, 2), 256, KCfg<128, 128, 3>::TOT, s2>>>(nullptr);
    cudaEventRecord(ev2, s2);

    km1 <<<dim3(M1 / 128, 4), 256, KCfg<128, 128, 3>::TOT>>>(was);
    k3_soft <<<NBF, 256>>>();
    km2a <<<dim3(NBF / 128, 8, 2), 256, KCfg<128, 128, 3>::TOT>>>(nullptr);

    // Join: k5 needs all four partial buffers.
    cudaStreamWaitEvent(0, ev2, 0);
    k5_e2   <<<dim3(B_, 5), 256>>>(war);
    k6_final<<<dim3(B_, 3), 256>>>(out);
}